// round 2
// baseline (speedup 1.0000x reference)
#include <cuda_runtime.h>
#include <math.h>

#define NF 64
#define NBATCH 8
#define CELLS (12288 * NF)

// Static scratch (no runtime allocation).
__device__ float g_buf[15][CELLS];
__device__ float g_stats[128];      // [0:64) mean, [64:128) rstd
__device__ float g_part[64 * 128];  // BN partials per block: 64 sums + 64 sumsq
__device__ int   g_seg[64];         // segments: (qstart, qcount, kstart, kcount) x 9

// ---------------------------------------------------------------------------
// GEMM: C[N,64] = A[N,64] @ W[64,64]; 256 thr, 64 rows/block.
// ---------------------------------------------------------------------------
__global__ void __launch_bounds__(256) k_gemm64(
    const float* __restrict__ A, const float* __restrict__ W,
    float* __restrict__ C, int N)
{
    __shared__ float sW[64 * 64];
    __shared__ float sA[64 * 65];
    int t = threadIdx.x;
    int row0 = blockIdx.x * 64;
    for (int i = t; i < 4096; i += 256) {
        sW[i] = W[i];
        int r = i >> 6, c = i & 63;
        int gr = row0 + r;
        sA[r * 65 + c] = (gr < N) ? A[gr * 64 + c] : 0.f;
    }
    __syncthreads();
    int a = t >> 4, b = t & 15;
    float4 acc[4];
#pragma unroll
    for (int i = 0; i < 4; i++) acc[i] = make_float4(0.f, 0.f, 0.f, 0.f);
#pragma unroll 8
    for (int m = 0; m < 64; m++) {
        float4 w = *reinterpret_cast<const float4*>(&sW[m * 64 + 4 * b]);
#pragma unroll
        for (int i = 0; i < 4; i++) {
            float av = sA[(a + 16 * i) * 65 + m];
            acc[i].x += av * w.x; acc[i].y += av * w.y;
            acc[i].z += av * w.z; acc[i].w += av * w.w;
        }
    }
#pragma unroll
    for (int i = 0; i < 4; i++) {
        int gr = row0 + a + 16 * i;
        if (gr < N) *reinterpret_cast<float4*>(&C[gr * 64 + 4 * b]) = acc[i];
    }
}

// ---------------------------------------------------------------------------
// Rulebook sparse conv: out[n] = sum_k (idx[n,k]>=0) F[idx[n,k]] @ W[k]
// ---------------------------------------------------------------------------
__global__ void __launch_bounds__(256) k_gconv(
    const float* __restrict__ F, const int* __restrict__ idx, int K,
    const float* __restrict__ W, float* __restrict__ out, int N)
{
    __shared__ float sW[64 * 64];
    __shared__ float sF[64 * 68];
    __shared__ int   sIdx[64];
    int t = threadIdx.x;
    int row0 = blockIdx.x * 64;
    int a = t >> 4, b = t & 15;
    float4 acc[4];
#pragma unroll
    for (int i = 0; i < 4; i++) acc[i] = make_float4(0.f, 0.f, 0.f, 0.f);

    for (int k = 0; k < K; k++) {
        __syncthreads();
        if (t < 64) {
            int gr = row0 + t;
            sIdx[t] = (gr < N) ? idx[gr * K + k] : -1;
        }
        for (int i = t; i < 4096; i += 256) sW[i] = W[k * 4096 + i];
        __syncthreads();
        {
            int rr = t >> 2;
            int j = sIdx[rr];
            if (j >= 0) {
                int c0 = (t & 3) * 16;
#pragma unroll
                for (int q4 = 0; q4 < 4; q4++)
                    *reinterpret_cast<float4*>(&sF[rr * 68 + c0 + 4 * q4]) =
                        *reinterpret_cast<const float4*>(&F[j * 64 + c0 + 4 * q4]);
            }
        }
        __syncthreads();
#pragma unroll
        for (int i = 0; i < 4; i++) {
            int r = a + 16 * i;
            if (sIdx[r] >= 0) {
#pragma unroll 8
                for (int m = 0; m < 64; m++) {
                    float av = sF[r * 68 + m];
                    float4 w = *reinterpret_cast<const float4*>(&sW[m * 64 + 4 * b]);
                    acc[i].x += av * w.x; acc[i].y += av * w.y;
                    acc[i].z += av * w.z; acc[i].w += av * w.w;
                }
            }
        }
    }
#pragma unroll
    for (int i = 0; i < 4; i++) {
        int gr = row0 + a + 16 * i;
        if (gr < N) *reinterpret_cast<float4*>(&out[gr * 64 + 4 * b]) = acc[i];
    }
}

// ---------------------------------------------------------------------------
// Segment prep: seg 0 = global stage-1; segs 1..8 = per-batch ragged ranges.
// ---------------------------------------------------------------------------
__global__ void k_prep(const int* __restrict__ pad_idx, int nd, int ne, int lq)
{
    int t = threadIdx.x;
    int w = t >> 5, lane = t & 31;
    if (w < NBATCH) {
        int cnt = 0;
        for (int l = lane; l < lq; l += 32)
            cnt += (pad_idx[w * lq + l] >= 0) ? 1 : 0;
#pragma unroll
        for (int o = 16; o > 0; o >>= 1) cnt += __shfl_xor_sync(0xffffffffu, cnt, o);
        if (lane == 0) {
            int s = pad_idx[w * lq];  // counts >= 1 by construction
            g_seg[(1 + w) * 4 + 0] = s;
            g_seg[(1 + w) * 4 + 1] = cnt;
            g_seg[(1 + w) * 4 + 2] = s;
            g_seg[(1 + w) * 4 + 3] = cnt;
        }
    }
    if (t == 0) { g_seg[0] = 0; g_seg[1] = nd; g_seg[2] = 0; g_seg[3] = ne; }
}

// ---------------------------------------------------------------------------
// Flash attention over segments. 64-query tile per block, 64-key inner tiles.
// No 1/sqrt(d) scale (matches reference). thread (a,b): rows a+16i, cols 4b..4b+3.
// ---------------------------------------------------------------------------
#define PQ 64
#define PK 68
#define PV 64
#define FLASH_SMEM ((64 * PQ + 64 * PK + 64 * PV) * 4)

__global__ void __launch_bounds__(256) k_flash(
    const float* __restrict__ Q, const float* __restrict__ K,
    const float* __restrict__ V, float* __restrict__ O,
    int seg_off, int tiles_per_seg)
{
    extern __shared__ float sm[];
    float* sQ = sm;                       // 64*PQ
    float* sK = sm + 64 * PQ;             // 64*PK (reused for P after scores)
    float* sV = sm + 64 * PQ + 64 * PK;   // 64*PV

    int bx = blockIdx.x;
    int segi = bx / tiles_per_seg;
    int tile = bx - segi * tiles_per_seg;
    int seg = seg_off + segi;
    int q0 = g_seg[seg * 4 + 0], nq = g_seg[seg * 4 + 1];
    int k0 = g_seg[seg * 4 + 2], nk = g_seg[seg * 4 + 3];
    if (tile * 64 >= nq) return;
    int qbase = q0 + tile * 64;
    int nqv = min(64, nq - tile * 64);

    int t = threadIdx.x;
    for (int i = t; i < 4096; i += 256) {
        int r = i >> 6, c = i & 63;
        int gr = qbase + ((r < nqv) ? r : 0);
        sQ[r * PQ + c] = Q[gr * 64 + c];
    }
    int a = t >> 4, b = t & 15;
    float4 acc[4];
    float rmax[4], rsum[4];
#pragma unroll
    for (int i = 0; i < 4; i++) {
        acc[i] = make_float4(0.f, 0.f, 0.f, 0.f);
        rmax[i] = -1e30f; rsum[i] = 0.f;
    }

    int nkt = (nk + 63) >> 6;
    for (int kt = 0; kt < nkt; kt++) {
        int kb = k0 + kt * 64;
        int nkv = min(64, nk - kt * 64);
        __syncthreads();
        for (int i = t; i < 4096; i += 256) {
            int r = i >> 6, c = i & 63;
            int gr = kb + ((r < nkv) ? r : 0);
            sK[r * PK + c] = K[gr * 64 + c];
            sV[r * PV + c] = V[gr * 64 + c];
        }
        __syncthreads();

        float s[4][4];
#pragma unroll
        for (int i = 0; i < 4; i++)
#pragma unroll
            for (int j = 0; j < 4; j++) s[i][j] = 0.f;
#pragma unroll 4
        for (int m4 = 0; m4 < 16; m4++) {
            float4 qv[4], kv[4];
#pragma unroll
            for (int i = 0; i < 4; i++)
                qv[i] = *reinterpret_cast<const float4*>(&sQ[(a + 16 * i) * PQ + 4 * m4]);
#pragma unroll
            for (int j = 0; j < 4; j++)
                kv[j] = *reinterpret_cast<const float4*>(&sK[(b + 16 * j) * PK + 4 * m4]);
#pragma unroll
            for (int i = 0; i < 4; i++)
#pragma unroll
                for (int j = 0; j < 4; j++)
                    s[i][j] += qv[i].x * kv[j].x + qv[i].y * kv[j].y +
                               qv[i].z * kv[j].z + qv[i].w * kv[j].w;
        }
        if (nkv < 64) {
#pragma unroll
            for (int j = 0; j < 4; j++)
                if (b + 16 * j >= nkv) {
#pragma unroll
                    for (int i = 0; i < 4; i++) s[i][j] = -1e30f;
                }
        }
        __syncthreads();  // all sK reads done before overwriting with P

#pragma unroll
        for (int i = 0; i < 4; i++) {
            float mx = fmaxf(fmaxf(s[i][0], s[i][1]), fmaxf(s[i][2], s[i][3]));
            mx = fmaxf(mx, __shfl_xor_sync(0xffffffffu, mx, 1));
            mx = fmaxf(mx, __shfl_xor_sync(0xffffffffu, mx, 2));
            mx = fmaxf(mx, __shfl_xor_sync(0xffffffffu, mx, 4));
            mx = fmaxf(mx, __shfl_xor_sync(0xffffffffu, mx, 8));
            float mnew = fmaxf(rmax[i], mx);
            float corr = __expf(rmax[i] - mnew);
            rmax[i] = mnew;
            float ps = 0.f;
#pragma unroll
            for (int j = 0; j < 4; j++) {
                float p = __expf(s[i][j] - mnew);
                sK[(a + 16 * i) * PK + (b + 16 * j)] = p;
                ps += p;
            }
            ps += __shfl_xor_sync(0xffffffffu, ps, 1);
            ps += __shfl_xor_sync(0xffffffffu, ps, 2);
            ps += __shfl_xor_sync(0xffffffffu, ps, 4);
            ps += __shfl_xor_sync(0xffffffffu, ps, 8);
            rsum[i] = rsum[i] * corr + ps;
            acc[i].x *= corr; acc[i].y *= corr; acc[i].z *= corr; acc[i].w *= corr;
        }
        __syncwarp();  // P rows are written+read within the same half-warp

#pragma unroll 4
        for (int k4 = 0; k4 < 16; k4++) {
            float4 vv[4];
#pragma unroll
            for (int j = 0; j < 4; j++)
                vv[j] = *reinterpret_cast<const float4*>(&sV[(4 * k4 + j) * PV + 4 * b]);
#pragma unroll
            for (int i = 0; i < 4; i++) {
                float4 pv = *reinterpret_cast<const float4*>(&sK[(a + 16 * i) * PK + 4 * k4]);
                acc[i].x += pv.x * vv[0].x + pv.y * vv[1].x + pv.z * vv[2].x + pv.w * vv[3].x;
                acc[i].y += pv.x * vv[0].y + pv.y * vv[1].y + pv.z * vv[2].y + pv.w * vv[3].y;
                acc[i].z += pv.x * vv[0].z + pv.y * vv[1].z + pv.z * vv[2].z + pv.w * vv[3].z;
                acc[i].w += pv.x * vv[0].w + pv.y * vv[1].w + pv.z * vv[2].w + pv.w * vv[3].w;
            }
        }
    }
#pragma unroll
    for (int i = 0; i < 4; i++) {
        int r = a + 16 * i;
        if (r < nqv) {
            float inv = 1.f / rsum[i];
            float4 o = acc[i];
            o.x *= inv; o.y *= inv; o.z *= inv; o.w *= inv;
            *reinterpret_cast<float4*>(&O[(qbase + r) * 64 + 4 * b]) = o;
        }
    }
}

// ---------------------------------------------------------------------------
// BatchNorm: two-stage deterministic stats + fused apply.
// ---------------------------------------------------------------------------
__global__ void k_bnstats(const float* __restrict__ X, int N)
{
    __shared__ float sh[2][4][64];
    int c = threadIdx.x & 63, rg = threadIdx.x >> 6;
    float s = 0.f, s2 = 0.f;
    for (int r = blockIdx.x * 4 + rg; r < N; r += 256) {
        float v = X[r * 64 + c];
        s += v; s2 += v * v;
    }
    sh[0][rg][c] = s; sh[1][rg][c] = s2;
    __syncthreads();
    if (threadIdx.x < 64) {
        float ts = sh[0][0][c] + sh[0][1][c] + sh[0][2][c] + sh[0][3][c];
        float t2 = sh[1][0][c] + sh[1][1][c] + sh[1][2][c] + sh[1][3][c];
        g_part[blockIdx.x * 128 + c] = ts;
        g_part[blockIdx.x * 128 + 64 + c] = t2;
    }
}

__global__ void k_bnfin(int N)
{
    int c = threadIdx.x;
    float s = 0.f, s2 = 0.f;
    for (int b = 0; b < 64; b++) { s += g_part[b * 128 + c]; s2 += g_part[b * 128 + 64 + c]; }
    float m = s / (float)N;
    float v = s2 / (float)N - m * m;
    g_stats[c] = m;
    g_stats[64 + c] = rsqrtf(v + 1e-4f);
}

// mode 0: bn(x); 1: res + bn(x); 2: relu(bn(x))
__global__ void k_bnapply(const float* __restrict__ X, const float* __restrict__ Res,
                          const float* __restrict__ gamma, const float* __restrict__ beta,
                          float* __restrict__ Out, int N, int mode)
{
    int i = blockIdx.x * blockDim.x + threadIdx.x;
    if (i < N * 64) {
        int c = i & 63;
        float y = (X[i] - g_stats[c]) * g_stats[64 + c] * gamma[c] + beta[c];
        if (mode == 1) y += Res[i];
        if (mode == 2) y = fmaxf(y, 0.f);
        Out[i] = y;
    }
}

__global__ void k_add(const float* __restrict__ X, const float* __restrict__ Y,
                      float* __restrict__ Out, int N)
{
    int i = blockIdx.x * blockDim.x + threadIdx.x;
    if (i < N * 64) Out[i] = X[i] + Y[i];
}

// ---------------------------------------------------------------------------
extern "C" void kernel_launch(void* const* d_in, const int* in_sizes, int n_in,
                              void* d_out, int out_size)
{
    const float* xdec  = (const float*)d_in[0];
    const float* xenc  = (const float*)d_in[1];
    const float* Wp1   = (const float*)d_in[2];
    const float* Wq    = (const float*)d_in[3];
    const float* Wk    = (const float*)d_in[4];
    const float* Wv    = (const float*)d_in[5];
    const float* Wt    = (const float*)d_in[6];
    const float* Wq1   = (const float*)d_in[7];
    const float* Wk1   = (const float*)d_in[8];
    const float* Wv1   = (const float*)d_in[9];
    const float* Wdown = (const float*)d_in[10];
    const float* W3t   = (const float*)d_in[11];
    const float* W3a   = (const float*)d_in[12];
    const float* W3b   = (const float*)d_in[13];
    const float* gam   = (const float*)d_in[14];
    const float* bet   = (const float*)d_in[15];
    const int* nbr     = (const int*)d_in[16];
    const int* kv_nbr  = (const int*)d_in[17];
    const int* pad_idx = (const int*)d_in[18];

    int nd = in_sizes[0] / 64;
    int ne = in_sizes[1] / 64;
    int lq = in_sizes[18] / NBATCH;
    float* out = (float*)d_out;

    float* base = nullptr;
    cudaGetSymbolAddress((void**)&base, g_buf);
    float* B[15];
    for (int i = 0; i < 15; i++) B[i] = base + (size_t)i * CELLS;

    cudaFuncSetAttribute(k_flash, cudaFuncAttributeMaxDynamicSharedMemorySize, FLASH_SMEM);

    dim3 thr(256);
    int gbd = (nd + 63) / 64;
    int gbe = (ne + 63) / 64;
    int gel = (nd * 64 + 255) / 256;

    // Stage 1
    k_gemm64<<<gbd, thr>>>(xdec, Wp1, B[0], nd);          // xd0
    k_gemm64<<<gbd, thr>>>(B[0], Wq, B[1], nd);           // q
    k_gemm64<<<gbe, thr>>>(xenc, Wk, B[2], ne);           // ke
    k_gemm64<<<gbe, thr>>>(xenc, Wv, B[3], ne);           // ve
    k_prep<<<1, thr>>>(pad_idx, nd, ne, lq);
    k_flash<<<gbd, thr, FLASH_SMEM>>>(B[1], B[2], B[3], B[4], 0, gbd);
    k_gemm64<<<gbd, thr>>>(B[4], Wt, B[5], nd);           // xr
    k_bnstats<<<64, thr>>>(B[5], nd);
    k_bnfin<<<1, 64>>>(nd);
    k_bnapply<<<gel, thr>>>(B[5], B[0], gam + 0, bet + 0, B[6], nd, 1);   // xd

    // Stage 2
    k_gemm64<<<gbd, thr>>>(B[6], Wq1, B[7], nd);          // q1
    k_gconv<<<gbd, thr>>>(B[7], kv_nbr, 8, Wdown, B[8], nd);
    k_bnstats<<<64, thr>>>(B[8], nd);
    k_bnfin<<<1, 64>>>(nd);
    k_bnapply<<<gel, thr>>>(B[8], B[8], gam + 64, bet + 64, B[9], nd, 0); // kv
    k_gemm64<<<gbd, thr>>>(B[9], Wk1, B[10], nd);         // k1
    k_gemm64<<<gbd, thr>>>(B[9], Wv1, B[11], nd);         // v1
    int tps = (lq + 63) / 64;
    k_flash<<<NBATCH * tps, thr, FLASH_SMEM>>>(B[7], B[10], B[11], B[12], 1, tps);
    k_gconv<<<gbd, thr>>>(B[12], nbr, 27, W3t, B[13], nd);
    k_bnstats<<<64, thr>>>(B[13], nd);
    k_bnfin<<<1, 64>>>(nd);
    k_bnapply<<<gel, thr>>>(B[13], B[6], gam + 128, bet + 128, B[14], nd, 1); // xd2

    // Res block
    k_bnstats<<<64, thr>>>(B[14], nd);
    k_bnfin<<<1, 64>>>(nd);
    k_bnapply<<<gel, thr>>>(B[14], B[14], gam + 192, bet + 192, B[0], nd, 2);
    k_gconv<<<gbd, thr>>>(B[0], nbr, 27, W3a, B[1], nd);
    k_bnstats<<<64, thr>>>(B[1], nd);
    k_bnfin<<<1, 64>>>(nd);
    k_bnapply<<<gel, thr>>>(B[1], B[1], gam + 256, bet + 256, B[2], nd, 2);
    k_gconv<<<gbd, thr>>>(B[2], nbr, 27, W3b, B[3], nd);
    k_add<<<gel, thr>>>(B[14], B[3], B[4], nd);
    k_bnstats<<<64, thr>>>(B[4], nd);
    k_bnfin<<<1, 64>>>(nd);
    k_bnapply<<<gel, thr>>>(B[4], B[4], gam + 320, bet + 320, out, nd, 2);
}

// round 3
// speedup vs baseline: 1.0595x; 1.0595x over previous
#include <cuda_runtime.h>
#include <math.h>

#define NF 64
#define NBATCH 8
#define CELLS (12288 * NF)

// Static scratch (no runtime allocation).
__device__ float g_buf[15][CELLS];
__device__ float g_stats[128];      // [0:64) mean, [64:128) rstd
__device__ float g_part[64 * 128];  // BN partials per block
__device__ int   g_seg[64];         // segments: (qstart,qcount,kstart,kcount) x 9

// ---------------------------------------------------------------------------
// tf32 helpers
// ---------------------------------------------------------------------------
__device__ __forceinline__ unsigned f2tf32(float x) {
    unsigned r;
    asm("cvt.rna.tf32.f32 %0, %1;" : "=r"(r) : "f"(x));
    return r;
}

__device__ __forceinline__ void mma_tf32(float c[4], const unsigned a[4], const unsigned b[2]) {
    asm volatile(
        "mma.sync.aligned.m16n8k8.row.col.f32.tf32.tf32.f32 "
        "{%0,%1,%2,%3}, {%4,%5,%6,%7}, {%8,%9}, {%0,%1,%2,%3};"
        : "+f"(c[0]), "+f"(c[1]), "+f"(c[2]), "+f"(c[3])
        : "r"(a[0]), "r"(a[1]), "r"(a[2]), "r"(a[3]), "r"(b[0]), "r"(b[1]));
}

// ---------------------------------------------------------------------------
// GEMM: C[N,64] = A[N,64] @ W[64,64]; 256 thr, 64 rows/block.
// ---------------------------------------------------------------------------
__global__ void __launch_bounds__(256) k_gemm64(
    const float* __restrict__ A, const float* __restrict__ W,
    float* __restrict__ C, int N)
{
    __shared__ float sW[64 * 64];
    __shared__ float sA[64 * 65];
    int t = threadIdx.x;
    int row0 = blockIdx.x * 64;
    for (int i = t; i < 4096; i += 256) {
        sW[i] = W[i];
        int r = i >> 6, c = i & 63;
        int gr = row0 + r;
        sA[r * 65 + c] = (gr < N) ? A[gr * 64 + c] : 0.f;
    }
    __syncthreads();
    int a = t >> 4, b = t & 15;
    float4 acc[4];
#pragma unroll
    for (int i = 0; i < 4; i++) acc[i] = make_float4(0.f, 0.f, 0.f, 0.f);
#pragma unroll 8
    for (int m = 0; m < 64; m++) {
        float4 w = *reinterpret_cast<const float4*>(&sW[m * 64 + 4 * b]);
#pragma unroll
        for (int i = 0; i < 4; i++) {
            float av = sA[(a + 16 * i) * 65 + m];
            acc[i].x += av * w.x; acc[i].y += av * w.y;
            acc[i].z += av * w.z; acc[i].w += av * w.w;
        }
    }
#pragma unroll
    for (int i = 0; i < 4; i++) {
        int gr = row0 + a + 16 * i;
        if (gr < N) *reinterpret_cast<float4*>(&C[gr * 64 + 4 * b]) = acc[i];
    }
}

// ---------------------------------------------------------------------------
// Rulebook sparse conv: out[n] = sum_k (idx[n,k]>=0) F[idx[n,k]] @ W[k]
// ---------------------------------------------------------------------------
__global__ void __launch_bounds__(256) k_gconv(
    const float* __restrict__ F, const int* __restrict__ idx, int K,
    const float* __restrict__ W, float* __restrict__ out, int N)
{
    __shared__ float sW[64 * 64];
    __shared__ float sF[64 * 68];
    __shared__ int   sIdx[64];
    int t = threadIdx.x;
    int row0 = blockIdx.x * 64;
    int a = t >> 4, b = t & 15;
    float4 acc[4];
#pragma unroll
    for (int i = 0; i < 4; i++) acc[i] = make_float4(0.f, 0.f, 0.f, 0.f);

    for (int k = 0; k < K; k++) {
        __syncthreads();
        if (t < 64) {
            int gr = row0 + t;
            sIdx[t] = (gr < N) ? idx[gr * K + k] : -1;
        }
        for (int i = t; i < 4096; i += 256) sW[i] = W[k * 4096 + i];
        __syncthreads();
        {
            int rr = t >> 2;
            int j = sIdx[rr];
            if (j >= 0) {
                int c0 = (t & 3) * 16;
#pragma unroll
                for (int q4 = 0; q4 < 4; q4++)
                    *reinterpret_cast<float4*>(&sF[rr * 68 + c0 + 4 * q4]) =
                        *reinterpret_cast<const float4*>(&F[j * 64 + c0 + 4 * q4]);
            }
        }
        __syncthreads();
#pragma unroll
        for (int i = 0; i < 4; i++) {
            int r = a + 16 * i;
            if (sIdx[r] >= 0) {
#pragma unroll 8
                for (int m = 0; m < 64; m++) {
                    float av = sF[r * 68 + m];
                    float4 w = *reinterpret_cast<const float4*>(&sW[m * 64 + 4 * b]);
                    acc[i].x += av * w.x; acc[i].y += av * w.y;
                    acc[i].z += av * w.z; acc[i].w += av * w.w;
                }
            }
        }
    }
#pragma unroll
    for (int i = 0; i < 4; i++) {
        int gr = row0 + a + 16 * i;
        if (gr < N) *reinterpret_cast<float4*>(&out[gr * 64 + 4 * b]) = acc[i];
    }
}

// ---------------------------------------------------------------------------
// Segment prep: seg 0 = global stage-1; segs 1..8 = per-batch ragged ranges.
// ---------------------------------------------------------------------------
__global__ void k_prep(const int* __restrict__ pad_idx, int nd, int ne, int lq)
{
    int t = threadIdx.x;
    int w = t >> 5, lane = t & 31;
    if (w < NBATCH) {
        int cnt = 0;
        for (int l = lane; l < lq; l += 32)
            cnt += (pad_idx[w * lq + l] >= 0) ? 1 : 0;
#pragma unroll
        for (int o = 16; o > 0; o >>= 1) cnt += __shfl_xor_sync(0xffffffffu, cnt, o);
        if (lane == 0) {
            int s = pad_idx[w * lq];
            g_seg[(1 + w) * 4 + 0] = s;
            g_seg[(1 + w) * 4 + 1] = cnt;
            g_seg[(1 + w) * 4 + 2] = s;
            g_seg[(1 + w) * 4 + 3] = cnt;
        }
    }
    if (t == 0) { g_seg[0] = 0; g_seg[1] = nd; g_seg[2] = 0; g_seg[3] = ne; }
}

// ---------------------------------------------------------------------------
// Tensor-core flash attention (3xTF32). 64-query tile, 64-key inner tiles.
// 8 warps: warp w -> q-rows 16*(w&3).. , key-half 32*(w>>2)..
// smem layout (floats, pitch 68):
//   sKhi sKlo sVhi sVlo sPhi sPlo : 6 * 64*68
//   redm[2][64], reds[2][64]
// ---------------------------------------------------------------------------
#define PKT 68
#define FL_TILE (64 * PKT)
#define FLASH_SMEM ((6 * FL_TILE + 256) * 4)

__global__ void __launch_bounds__(256) k_flash_tc(
    const float* __restrict__ Q, const float* __restrict__ K,
    const float* __restrict__ V, float* __restrict__ O,
    int seg_off, int tiles_per_seg)
{
    extern __shared__ float sm[];
    float* sKhi = sm;
    float* sKlo = sm + FL_TILE;
    float* sVhi = sm + 2 * FL_TILE;
    float* sVlo = sm + 3 * FL_TILE;
    float* sPhi = sm + 4 * FL_TILE;
    float* sPlo = sm + 5 * FL_TILE;
    float* redm = sm + 6 * FL_TILE;        // [2][64]
    float* reds = sm + 6 * FL_TILE + 128;  // [2][64]

    int bx = blockIdx.x;
    int segi = bx / tiles_per_seg;
    int tile = bx - segi * tiles_per_seg;
    int seg = seg_off + segi;
    int q0 = g_seg[seg * 4 + 0], nq = g_seg[seg * 4 + 1];
    int k0 = g_seg[seg * 4 + 2], nk = g_seg[seg * 4 + 3];
    if (tile * 64 >= nq) return;
    int qbase = q0 + tile * 64;
    int nqv = min(64, nq - tile * 64);

    int t = threadIdx.x;
    int w = t >> 5, lane = t & 31;
    int g = w & 3, h = w >> 2;
    int quad = lane >> 2, qi = lane & 3;
    int r0 = g * 16 + quad, r1 = r0 + 8;

    // Q fragments (hi/lo) in registers for the whole kernel.
    unsigned ah[32], al[32];
#pragma unroll
    for (int kk = 0; kk < 8; kk++) {
        int rows[2] = { r0, r1 };
        int cols[2] = { kk * 8 + qi, kk * 8 + qi + 4 };
#pragma unroll
        for (int jj = 0; jj < 4; jj++) {
            int rr = rows[jj & 1];      // a0:(r0,c0) a1:(r1,c0) a2:(r0,c1) a3:(r1,c1)
            int cc = cols[jj >> 1];
            int gr = qbase + ((rr < nqv) ? rr : 0);
            float q = Q[gr * 64 + cc];
            unsigned hi = f2tf32(q);
            ah[kk * 4 + jj] = hi;
            al[kk * 4 + jj] = f2tf32(q - __uint_as_float(hi));
        }
    }

    float oc[32];   // O accum: 8 n-tiles x 4
#pragma unroll
    for (int i = 0; i < 32; i++) oc[i] = 0.f;
    float rmax0 = -1e30f, rmax1 = -1e30f, rsum0 = 0.f, rsum1 = 0.f;

    int nkt = (nk + 63) >> 6;
    for (int kt = 0; kt < nkt; kt++) {
        int kb = k0 + kt * 64;
        int nkv = min(64, nk - kt * 64);
        __syncthreads();
        for (int i = t; i < 4096; i += 256) {
            int r = i >> 6, c = i & 63;
            int gr = kb + ((r < nkv) ? r : 0);
            float kvv = K[gr * 64 + c];
            unsigned khi = f2tf32(kvv);
            sKhi[r * PKT + c] = __uint_as_float(khi);
            sKlo[r * PKT + c] = __uint_as_float(f2tf32(kvv - __uint_as_float(khi)));
            float vv = (r < nkv) ? V[gr * 64 + c] : 0.f;
            unsigned vhi = f2tf32(vv);
            sVhi[r * PKT + c] = __uint_as_float(vhi);
            sVlo[r * PKT + c] = __uint_as_float(f2tf32(vv - __uint_as_float(vhi)));
        }
        __syncthreads();

        // ---- S = Q @ K^T  (warp covers 16 rows x 32 keys) ----
        float c4[4][4];
#pragma unroll
        for (int nt = 0; nt < 4; nt++)
#pragma unroll
            for (int k = 0; k < 4; k++) c4[nt][k] = 0.f;

#pragma unroll
        for (int kk = 0; kk < 8; kk++) {
#pragma unroll
            for (int nt = 0; nt < 4; nt++) {
                int key = 32 * h + 8 * nt + quad;
                int d0 = kk * 8 + qi;
                unsigned bh[2], bl[2];
                bh[0] = __float_as_uint(sKhi[key * PKT + d0]);
                bh[1] = __float_as_uint(sKhi[key * PKT + d0 + 4]);
                bl[0] = __float_as_uint(sKlo[key * PKT + d0]);
                bl[1] = __float_as_uint(sKlo[key * PKT + d0 + 4]);
                mma_tf32(c4[nt], &ah[kk * 4], bh);
                mma_tf32(c4[nt], &ah[kk * 4], bl);
                mma_tf32(c4[nt], &al[kk * 4], bh);
            }
        }

        // ---- masking ----
        if (nkv < 64) {
#pragma unroll
            for (int nt = 0; nt < 4; nt++) {
                int colb = 32 * h + 8 * nt + 2 * qi;
#pragma unroll
                for (int k = 0; k < 4; k++)
                    if (colb + (k & 1) >= nkv) c4[nt][k] = -1e30f;
            }
        }

        // ---- softmax (cross-half via smem) ----
        float mx0 = -1e30f, mx1 = -1e30f;
#pragma unroll
        for (int nt = 0; nt < 4; nt++) {
            mx0 = fmaxf(mx0, fmaxf(c4[nt][0], c4[nt][1]));
            mx1 = fmaxf(mx1, fmaxf(c4[nt][2], c4[nt][3]));
        }
        mx0 = fmaxf(mx0, __shfl_xor_sync(0xffffffffu, mx0, 1));
        mx0 = fmaxf(mx0, __shfl_xor_sync(0xffffffffu, mx0, 2));
        mx1 = fmaxf(mx1, __shfl_xor_sync(0xffffffffu, mx1, 1));
        mx1 = fmaxf(mx1, __shfl_xor_sync(0xffffffffu, mx1, 2));
        if (qi == 0) { redm[h * 64 + r0] = mx0; redm[h * 64 + r1] = mx1; }
        __syncthreads();
        float mnew0 = fmaxf(rmax0, fmaxf(redm[r0], redm[64 + r0]));
        float mnew1 = fmaxf(rmax1, fmaxf(redm[r1], redm[64 + r1]));
        float corr0 = __expf(rmax0 - mnew0);
        float corr1 = __expf(rmax1 - mnew1);
        rmax0 = mnew0; rmax1 = mnew1;

        float ps0 = 0.f, ps1 = 0.f;
#pragma unroll
        for (int nt = 0; nt < 4; nt++) {
            int colb = 32 * h + 8 * nt + 2 * qi;
#pragma unroll
            for (int k = 0; k < 4; k++) {
                float mr = (k < 2) ? mnew0 : mnew1;
                float p = __expf(c4[nt][k] - mr);
                if (k < 2) ps0 += p; else ps1 += p;
                int row = (k < 2) ? r0 : r1;
                int col = colb + (k & 1);
                unsigned phi = f2tf32(p);
                sPhi[row * PKT + col] = __uint_as_float(phi);
                sPlo[row * PKT + col] = __uint_as_float(f2tf32(p - __uint_as_float(phi)));
            }
        }
        ps0 += __shfl_xor_sync(0xffffffffu, ps0, 1);
        ps0 += __shfl_xor_sync(0xffffffffu, ps0, 2);
        ps1 += __shfl_xor_sync(0xffffffffu, ps1, 1);
        ps1 += __shfl_xor_sync(0xffffffffu, ps1, 2);
        if (qi == 0) { reds[h * 64 + r0] = ps0; reds[h * 64 + r1] = ps1; }
        __syncthreads();
        rsum0 = rsum0 * corr0 + reds[r0] + reds[64 + r0];
        rsum1 = rsum1 * corr1 + reds[r1] + reds[64 + r1];
#pragma unroll
        for (int nt = 0; nt < 8; nt++) {
            oc[nt * 4 + 0] *= corr0; oc[nt * 4 + 1] *= corr0;
            oc[nt * 4 + 2] *= corr1; oc[nt * 4 + 3] *= corr1;
        }

        // ---- O += P @ V  (warp: 16 rows x all 64 cols over its 32-key slice) ----
#pragma unroll
        for (int kk = 0; kk < 4; kk++) {
            int key0 = 32 * h + 8 * kk + qi;
            unsigned ph[4], pl[4];
            ph[0] = __float_as_uint(sPhi[r0 * PKT + key0]);
            ph[1] = __float_as_uint(sPhi[r1 * PKT + key0]);
            ph[2] = __float_as_uint(sPhi[r0 * PKT + key0 + 4]);
            ph[3] = __float_as_uint(sPhi[r1 * PKT + key0 + 4]);
            pl[0] = __float_as_uint(sPlo[r0 * PKT + key0]);
            pl[1] = __float_as_uint(sPlo[r1 * PKT + key0]);
            pl[2] = __float_as_uint(sPlo[r0 * PKT + key0 + 4]);
            pl[3] = __float_as_uint(sPlo[r1 * PKT + key0 + 4]);
#pragma unroll
            for (int nt = 0; nt < 8; nt++) {
                int col = 8 * nt + quad;
                unsigned bh[2], bl[2];
                bh[0] = __float_as_uint(sVhi[key0 * PKT + col]);
                bh[1] = __float_as_uint(sVhi[(key0 + 4) * PKT + col]);
                bl[0] = __float_as_uint(sVlo[key0 * PKT + col]);
                bl[1] = __float_as_uint(sVlo[(key0 + 4) * PKT + col]);
                mma_tf32(&oc[nt * 4], ph, bh);
                mma_tf32(&oc[nt * 4], ph, bl);
                mma_tf32(&oc[nt * 4], pl, bh);
            }
        }
    }

    // ---- combine key-halves and write ----
    __syncthreads();
    float* sO = sPhi;  // reuse
    if (h == 1) {
#pragma unroll
        for (int nt = 0; nt < 8; nt++) {
            int colb = 8 * nt + 2 * qi;
            sO[r0 * PKT + colb]     = oc[nt * 4 + 0];
            sO[r0 * PKT + colb + 1] = oc[nt * 4 + 1];
            sO[r1 * PKT + colb]     = oc[nt * 4 + 2];
            sO[r1 * PKT + colb + 1] = oc[nt * 4 + 3];
        }
    }
    __syncthreads();
    if (h == 0) {
        float inv0 = 1.f / rsum0, inv1 = 1.f / rsum1;
#pragma unroll
        for (int nt = 0; nt < 8; nt++) {
            int colb = 8 * nt + 2 * qi;
            if (r0 < nqv) {
                O[(qbase + r0) * 64 + colb]     = (oc[nt * 4 + 0] + sO[r0 * PKT + colb]) * inv0;
                O[(qbase + r0) * 64 + colb + 1] = (oc[nt * 4 + 1] + sO[r0 * PKT + colb + 1]) * inv0;
            }
            if (r1 < nqv) {
                O[(qbase + r1) * 64 + colb]     = (oc[nt * 4 + 2] + sO[r1 * PKT + colb]) * inv1;
                O[(qbase + r1) * 64 + colb + 1] = (oc[nt * 4 + 3] + sO[r1 * PKT + colb + 1]) * inv1;
            }
        }
    }
}

// ---------------------------------------------------------------------------
// BatchNorm: two-stage deterministic stats + fused apply.
// ---------------------------------------------------------------------------
__global__ void k_bnstats(const float* __restrict__ X, int N)
{
    __shared__ float sh[2][4][64];
    int c = threadIdx.x & 63, rg = threadIdx.x >> 6;
    float s = 0.f, s2 = 0.f;
    for (int r = blockIdx.x * 4 + rg; r < N; r += 256) {
        float v = X[r * 64 + c];
        s += v; s2 += v * v;
    }
    sh[0][rg][c] = s; sh[1][rg][c] = s2;
    __syncthreads();
    if (threadIdx.x < 64) {
        float ts = sh[0][0][c] + sh[0][1][c] + sh[0][2][c] + sh[0][3][c];
        float t2 = sh[1][0][c] + sh[1][1][c] + sh[1][2][c] + sh[1][3][c];
        g_part[blockIdx.x * 128 + c] = ts;
        g_part[blockIdx.x * 128 + 64 + c] = t2;
    }
}

__global__ void k_bnfin(int N)
{
    int c = threadIdx.x;
    float s = 0.f, s2 = 0.f;
    for (int b = 0; b < 64; b++) { s += g_part[b * 128 + c]; s2 += g_part[b * 128 + 64 + c]; }
    float m = s / (float)N;
    float v = s2 / (float)N - m * m;
    g_stats[c] = m;
    g_stats[64 + c] = rsqrtf(v + 1e-4f);
}

// mode 0: bn(x); 1: res + bn(x); 2: relu(bn(x))
__global__ void k_bnapply(const float* __restrict__ X, const float* __restrict__ Res,
                          const float* __restrict__ gamma, const float* __restrict__ beta,
                          float* __restrict__ Out, int N, int mode)
{
    int i = blockIdx.x * blockDim.x + threadIdx.x;
    if (i < N * 64) {
        int c = i & 63;
        float y = (X[i] - g_stats[c]) * g_stats[64 + c] * gamma[c] + beta[c];
        if (mode == 1) y += Res[i];
        if (mode == 2) y = fmaxf(y, 0.f);
        Out[i] = y;
    }
}

__global__ void k_add(const float* __restrict__ X, const float* __restrict__ Y,
                      float* __restrict__ Out, int N)
{
    int i = blockIdx.x * blockDim.x + threadIdx.x;
    if (i < N * 64) Out[i] = X[i] + Y[i];
}

// ---------------------------------------------------------------------------
extern "C" void kernel_launch(void* const* d_in, const int* in_sizes, int n_in,
                              void* d_out, int out_size)
{
    const float* xdec  = (const float*)d_in[0];
    const float* xenc  = (const float*)d_in[1];
    const float* Wp1   = (const float*)d_in[2];
    const float* Wq    = (const float*)d_in[3];
    const float* Wk    = (const float*)d_in[4];
    const float* Wv    = (const float*)d_in[5];
    const float* Wt    = (const float*)d_in[6];
    const float* Wq1   = (const float*)d_in[7];
    const float* Wk1   = (const float*)d_in[8];
    const float* Wv1   = (const float*)d_in[9];
    const float* Wdown = (const float*)d_in[10];
    const float* W3t   = (const float*)d_in[11];
    const float* W3a   = (const float*)d_in[12];
    const float* W3b   = (const float*)d_in[13];
    const float* gam   = (const float*)d_in[14];
    const float* bet   = (const float*)d_in[15];
    const int* nbr     = (const int*)d_in[16];
    const int* kv_nbr  = (const int*)d_in[17];
    const int* pad_idx = (const int*)d_in[18];

    int nd = in_sizes[0] / 64;
    int ne = in_sizes[1] / 64;
    int lq = in_sizes[18] / NBATCH;
    float* out = (float*)d_out;

    float* base = nullptr;
    cudaGetSymbolAddress((void**)&base, g_buf);
    float* B[15];
    for (int i = 0; i < 15; i++) B[i] = base + (size_t)i * CELLS;

    cudaFuncSetAttribute(k_flash_tc, cudaFuncAttributeMaxDynamicSharedMemorySize, FLASH_SMEM);

    dim3 thr(256);
    int gbd = (nd + 63) / 64;
    int gbe = (ne + 63) / 64;
    int gel = (nd * 64 + 255) / 256;

    // Stage 1
    k_gemm64<<<gbd, thr>>>(xdec, Wp1, B[0], nd);          // xd0
    k_gemm64<<<gbd, thr>>>(B[0], Wq, B[1], nd);           // q
    k_gemm64<<<gbe, thr>>>(xenc, Wk, B[2], ne);           // ke
    k_gemm64<<<gbe, thr>>>(xenc, Wv, B[3], ne);           // ve
    k_prep<<<1, thr>>>(pad_idx, nd, ne, lq);
    k_flash_tc<<<gbd, thr, FLASH_SMEM>>>(B[1], B[2], B[3], B[4], 0, gbd);
    k_gemm64<<<gbd, thr>>>(B[4], Wt, B[5], nd);           // xr
    k_bnstats<<<64, thr>>>(B[5], nd);
    k_bnfin<<<1, 64>>>(nd);
    k_bnapply<<<gel, thr>>>(B[5], B[0], gam + 0, bet + 0, B[6], nd, 1);   // xd

    // Stage 2
    k_gemm64<<<gbd, thr>>>(B[6], Wq1, B[7], nd);          // q1
    k_gconv<<<gbd, thr>>>(B[7], kv_nbr, 8, Wdown, B[8], nd);
    k_bnstats<<<64, thr>>>(B[8], nd);
    k_bnfin<<<1, 64>>>(nd);
    k_bnapply<<<gel, thr>>>(B[8], B[8], gam + 64, bet + 64, B[9], nd, 0); // kv
    k_gemm64<<<gbd, thr>>>(B[9], Wk1, B[10], nd);         // k1
    k_gemm64<<<gbd, thr>>>(B[9], Wv1, B[11], nd);         // v1
    int tps = (lq + 63) / 64;
    k_flash_tc<<<NBATCH * tps, thr, FLASH_SMEM>>>(B[7], B[10], B[11], B[12], 1, tps);
    k_gconv<<<gbd, thr>>>(B[12], nbr, 27, W3t, B[13], nd);
    k_bnstats<<<64, thr>>>(B[13], nd);
    k_bnfin<<<1, 64>>>(nd);
    k_bnapply<<<gel, thr>>>(B[13], B[6], gam + 128, bet + 128, B[14], nd, 1); // xd2

    // Res block
    k_bnstats<<<64, thr>>>(B[14], nd);
    k_bnfin<<<1, 64>>>(nd);
    k_bnapply<<<gel, thr>>>(B[14], B[14], gam + 192, bet + 192, B[0], nd, 2);
    k_gconv<<<gbd, thr>>>(B[0], nbr, 27, W3a, B[1], nd);
    k_bnstats<<<64, thr>>>(B[1], nd);
    k_bnfin<<<1, 64>>>(nd);
    k_bnapply<<<gel, thr>>>(B[1], B[1], gam + 256, bet + 256, B[2], nd, 2);
    k_gconv<<<gbd, thr>>>(B[2], nbr, 27, W3b, B[3], nd);
    k_add<<<gel, thr>>>(B[14], B[3], B[4], nd);
    k_bnstats<<<64, thr>>>(B[4], nd);
    k_bnfin<<<1, 64>>>(nd);
    k_bnapply<<<gel, thr>>>(B[4], B[4], gam + 320, bet + 320, out, nd, 2);
}

// round 4
// speedup vs baseline: 2.2681x; 2.1407x over previous
#include <cuda_runtime.h>
#include <cuda_bf16.h>
#include <math.h>

#define NF 64
#define NBATCH 8
#define CELLS (12288 * NF)
#define PADCELLS (CELLS + 64 * 64)

// Static scratch (no runtime allocation).
__device__ float g_buf[15][CELLS];
__device__ __nv_bfloat16 g_bf[6][PADCELLS];  // Qhi Qlo Khi Klo Vhi Vlo
__device__ float g_stats[128];
__device__ float g_part[64 * 128];
__device__ int   g_seg[64];

// ---------------------------------------------------------------------------
// Helpers
// ---------------------------------------------------------------------------
__device__ __forceinline__ int SW(int r, int cb) {          // swizzled byte offset, 128B pitch
    return r * 128 + (cb ^ ((r & 7) << 4));
}
__device__ __forceinline__ unsigned smu32(const void* p) {
    return (unsigned)__cvta_generic_to_shared(p);
}
__device__ __forceinline__ void cpa16(unsigned dst, const void* src) {
    asm volatile("cp.async.ca.shared.global [%0], [%1], 16;" :: "r"(dst), "l"(src) : "memory");
}
#define CP_COMMIT() asm volatile("cp.async.commit_group;" ::: "memory")
#define CP_WAIT1()  asm volatile("cp.async.wait_group 1;" ::: "memory")

__device__ __forceinline__ void ldsm4(unsigned r[4], unsigned a) {
    asm volatile("ldmatrix.sync.aligned.m8n8.x4.shared.b16 {%0,%1,%2,%3}, [%4];"
                 : "=r"(r[0]), "=r"(r[1]), "=r"(r[2]), "=r"(r[3]) : "r"(a));
}
__device__ __forceinline__ void ldsm4t(unsigned r[4], unsigned a) {
    asm volatile("ldmatrix.sync.aligned.m8n8.x4.trans.shared.b16 {%0,%1,%2,%3}, [%4];"
                 : "=r"(r[0]), "=r"(r[1]), "=r"(r[2]), "=r"(r[3]) : "r"(a));
}
__device__ __forceinline__ void mma_bf(float c[4], const unsigned a[4], const unsigned b[2]) {
    asm volatile(
        "mma.sync.aligned.m16n8k16.row.col.f32.bf16.bf16.f32 "
        "{%0,%1,%2,%3}, {%4,%5,%6,%7}, {%8,%9}, {%0,%1,%2,%3};"
        : "+f"(c[0]), "+f"(c[1]), "+f"(c[2]), "+f"(c[3])
        : "r"(a[0]), "r"(a[1]), "r"(a[2]), "r"(a[3]), "r"(b[0]), "r"(b[1]));
}

// ---------------------------------------------------------------------------
// Converter: fp32 -> bf16 hi/lo, zero-padded to npad elements.
// ---------------------------------------------------------------------------
__global__ void k_cvt(const float* __restrict__ X, __nv_bfloat16* __restrict__ hi,
                      __nv_bfloat16* __restrict__ lo, int n, int npad)
{
    int i = blockIdx.x * blockDim.x + threadIdx.x;
    if (i < npad) {
        float x = (i < n) ? X[i] : 0.f;
        __nv_bfloat16 h = __float2bfloat16(x);
        hi[i] = h;
        lo[i] = __float2bfloat16(x - __bfloat162float(h));
    }
}

// ---------------------------------------------------------------------------
// GEMM: C[N,64] = A[N,64] @ W[64,64]
// ---------------------------------------------------------------------------
__global__ void __launch_bounds__(256) k_gemm64(
    const float* __restrict__ A, const float* __restrict__ W,
    float* __restrict__ C, int N)
{
    __shared__ float sW[64 * 64];
    __shared__ float sA[64 * 65];
    int t = threadIdx.x;
    int row0 = blockIdx.x * 64;
    for (int i = t; i < 4096; i += 256) {
        sW[i] = W[i];
        int r = i >> 6, c = i & 63;
        int gr = row0 + r;
        sA[r * 65 + c] = (gr < N) ? A[gr * 64 + c] : 0.f;
    }
    __syncthreads();
    int a = t >> 4, b = t & 15;
    float4 acc[4];
#pragma unroll
    for (int i = 0; i < 4; i++) acc[i] = make_float4(0.f, 0.f, 0.f, 0.f);
#pragma unroll 8
    for (int m = 0; m < 64; m++) {
        float4 w = *reinterpret_cast<const float4*>(&sW[m * 64 + 4 * b]);
#pragma unroll
        for (int i = 0; i < 4; i++) {
            float av = sA[(a + 16 * i) * 65 + m];
            acc[i].x += av * w.x; acc[i].y += av * w.y;
            acc[i].z += av * w.z; acc[i].w += av * w.w;
        }
    }
#pragma unroll
    for (int i = 0; i < 4; i++) {
        int gr = row0 + a + 16 * i;
        if (gr < N) *reinterpret_cast<float4*>(&C[gr * 64 + 4 * b]) = acc[i];
    }
}

// ---------------------------------------------------------------------------
// Rulebook sparse conv
// ---------------------------------------------------------------------------
__global__ void __launch_bounds__(256) k_gconv(
    const float* __restrict__ F, const int* __restrict__ idx, int K,
    const float* __restrict__ W, float* __restrict__ out, int N)
{
    __shared__ float sW[64 * 64];
    __shared__ float sF[64 * 68];
    __shared__ int   sIdx[64];
    int t = threadIdx.x;
    int row0 = blockIdx.x * 64;
    int a = t >> 4, b = t & 15;
    float4 acc[4];
#pragma unroll
    for (int i = 0; i < 4; i++) acc[i] = make_float4(0.f, 0.f, 0.f, 0.f);

    for (int k = 0; k < K; k++) {
        __syncthreads();
        if (t < 64) {
            int gr = row0 + t;
            sIdx[t] = (gr < N) ? idx[gr * K + k] : -1;
        }
        for (int i = t; i < 4096; i += 256) sW[i] = W[k * 4096 + i];
        __syncthreads();
        {
            int rr = t >> 2;
            int j = sIdx[rr];
            if (j >= 0) {
                int c0 = (t & 3) * 16;
#pragma unroll
                for (int q4 = 0; q4 < 4; q4++)
                    *reinterpret_cast<float4*>(&sF[rr * 68 + c0 + 4 * q4]) =
                        *reinterpret_cast<const float4*>(&F[j * 64 + c0 + 4 * q4]);
            }
        }
        __syncthreads();
#pragma unroll
        for (int i = 0; i < 4; i++) {
            int r = a + 16 * i;
            if (sIdx[r] >= 0) {
#pragma unroll 8
                for (int m = 0; m < 64; m++) {
                    float av = sF[r * 68 + m];
                    float4 w = *reinterpret_cast<const float4*>(&sW[m * 64 + 4 * b]);
                    acc[i].x += av * w.x; acc[i].y += av * w.y;
                    acc[i].z += av * w.z; acc[i].w += av * w.w;
                }
            }
        }
    }
#pragma unroll
    for (int i = 0; i < 4; i++) {
        int gr = row0 + a + 16 * i;
        if (gr < N) *reinterpret_cast<float4*>(&out[gr * 64 + 4 * b]) = acc[i];
    }
}

// ---------------------------------------------------------------------------
// Segment prep
// ---------------------------------------------------------------------------
__global__ void k_prep(const int* __restrict__ pad_idx, int nd, int ne, int lq)
{
    int t = threadIdx.x;
    int w = t >> 5, lane = t & 31;
    if (w < NBATCH) {
        int cnt = 0;
        for (int l = lane; l < lq; l += 32)
            cnt += (pad_idx[w * lq + l] >= 0) ? 1 : 0;
#pragma unroll
        for (int o = 16; o > 0; o >>= 1) cnt += __shfl_xor_sync(0xffffffffu, cnt, o);
        if (lane == 0) {
            int s = pad_idx[w * lq];
            g_seg[(1 + w) * 4 + 0] = s;
            g_seg[(1 + w) * 4 + 1] = cnt;
            g_seg[(1 + w) * 4 + 2] = s;
            g_seg[(1 + w) * 4 + 3] = cnt;
        }
    }
    if (t == 0) { g_seg[0] = 0; g_seg[1] = nd; g_seg[2] = 0; g_seg[3] = ne; }
}

// ---------------------------------------------------------------------------
// bf16 3x tensor-core flash attention.
// 8 warps: warp = (qg = w&3 -> 16 q-rows, h = w>>2 -> 32-key half).
// smem: KV double buffer 2x32KB | Q hi/lo 16KB | P hi/lo 16KB (reused as fp32 O) | red 1KB
// ---------------------------------------------------------------------------
#define FLASH_SMEM_BF (65536 + 16384 + 16384 + 1024)

__global__ void __launch_bounds__(256, 2) k_flash_bf(
    const __nv_bfloat16* __restrict__ gQh, const __nv_bfloat16* __restrict__ gQl,
    const __nv_bfloat16* __restrict__ gKh, const __nv_bfloat16* __restrict__ gKl,
    const __nv_bfloat16* __restrict__ gVh, const __nv_bfloat16* __restrict__ gVl,
    float* __restrict__ O, int seg_off, int tiles_per_seg)
{
    extern __shared__ char smc[];
    char* sKV = smc;                  // 2 x [Khi|Klo|Vhi|Vlo] x 8KB
    char* sQ  = smc + 65536;          // Qhi 8KB, Qlo 8KB
    char* sP  = smc + 81920;          // Phi 8KB, Plo 8KB / fp32 O staging
    float* red = (float*)(smc + 98304); // redm[2][64], reds[2][64]

    int bx = blockIdx.x;
    int segi = bx / tiles_per_seg;
    int tile = bx - segi * tiles_per_seg;
    int seg = seg_off + segi;
    int q0 = g_seg[seg * 4 + 0], nq = g_seg[seg * 4 + 1];
    int k0 = g_seg[seg * 4 + 2], nk = g_seg[seg * 4 + 3];
    if (tile * 64 >= nq) return;
    int qbase = q0 + tile * 64;
    int nqv = min(64, nq - tile * 64);

    int t = threadIdx.x;
    int w = t >> 5, lane = t & 31;
    int qg = w & 3, h = w >> 2;
    int quad = lane >> 2, qi = lane & 3;
    int r0 = qg * 16 + quad, r1 = r0 + 8;

    // ---- prologue copies: Q tile + KV tile 0 (group 0) ----
    {
#pragma unroll
        for (int j = 0; j < 2; j++) {
            int chunk = t + 256 * j;         // 512 chunks per 8KB array
            int row = chunk >> 3, jj = chunk & 7;
            cpa16(smu32(sQ + SW(row, jj << 4)),         gQh + (size_t)(qbase + row) * 64 + jj * 8);
            cpa16(smu32(sQ + 8192 + SW(row, jj << 4)),  gQl + (size_t)(qbase + row) * 64 + jj * 8);
        }
        const __nv_bfloat16* gs[4] = { gKh, gKl, gVh, gVl };
#pragma unroll
        for (int a = 0; a < 4; a++)
#pragma unroll
            for (int j = 0; j < 2; j++) {
                int chunk = t + 256 * j;
                int row = chunk >> 3, jj = chunk & 7;
                cpa16(smu32(sKV + a * 8192 + SW(row, jj << 4)),
                      gs[a] + (size_t)(k0 + row) * 64 + jj * 8);
            }
    }
    CP_COMMIT();

    float oc[32];
#pragma unroll
    for (int i = 0; i < 32; i++) oc[i] = 0.f;
    float rmax0 = -1e30f, rmax1 = -1e30f, rsum0 = 0.f, rsum1 = 0.f;

    int nkt = (nk + 63) >> 6;
    for (int kt = 0; kt < nkt; kt++) {
        char* sb = sKV + (kt & 1) * 32768;
        __syncthreads();   // prior reads of the buffer we're about to fill are done
        if (kt + 1 < nkt) {
            char* nb = sKV + ((kt + 1) & 1) * 32768;
            int kb = k0 + (kt + 1) * 64;
            const __nv_bfloat16* gs[4] = { gKh, gKl, gVh, gVl };
#pragma unroll
            for (int a = 0; a < 4; a++)
#pragma unroll
                for (int j = 0; j < 2; j++) {
                    int chunk = t + 256 * j;
                    int row = chunk >> 3, jj = chunk & 7;
                    cpa16(smu32(nb + a * 8192 + SW(row, jj << 4)),
                          gs[a] + (size_t)(kb + row) * 64 + jj * 8);
                }
        }
        CP_COMMIT();
        CP_WAIT1();        // current tile's data resident
        __syncthreads();

        int nkv = min(64, nk - kt * 64);
        char* sKh = sb;
        char* sKl = sb + 8192;
        char* sVh = sb + 16384;
        char* sVl = sb + 24576;

        // ---- S = Q K^T : warp covers 16 rows x 32 keys ----
        float c4[4][4];
#pragma unroll
        for (int nt = 0; nt < 4; nt++)
#pragma unroll
            for (int k = 0; k < 4; k++) c4[nt][k] = 0.f;

#pragma unroll
        for (int ch = 0; ch < 4; ch++) {
            unsigned qh[4], ql[4];
            {
                int r = qg * 16 + (lane & 7) + ((lane & 8) ? 8 : 0);
                int cb = ch * 32 + ((lane & 16) ? 16 : 0);
                ldsm4(qh, smu32(sQ + SW(r, cb)));
                ldsm4(ql, smu32(sQ + 8192 + SW(r, cb)));
            }
            unsigned kh[8], kl[8];
            {
                int r = 32 * h + (lane & 7) + ((lane & 16) ? 8 : 0);
                int cb = ch * 32 + ((lane & 8) ? 16 : 0);
                ldsm4(kh,     smu32(sKh + SW(r, cb)));
                ldsm4(kh + 4, smu32(sKh + SW(r + 16, cb)));
                ldsm4(kl,     smu32(sKl + SW(r, cb)));
                ldsm4(kl + 4, smu32(sKl + SW(r + 16, cb)));
            }
#pragma unroll
            for (int nt = 0; nt < 4; nt++) {
                mma_bf(c4[nt], qh, &kh[2 * nt]);
                mma_bf(c4[nt], qh, &kl[2 * nt]);
                mma_bf(c4[nt], ql, &kh[2 * nt]);
            }
        }

        if (nkv < 64) {
#pragma unroll
            for (int nt = 0; nt < 4; nt++) {
                int colb = 32 * h + 8 * nt + 2 * qi;
#pragma unroll
                for (int k = 0; k < 4; k++)
                    if (colb + (k & 1) >= nkv) c4[nt][k] = -1e30f;
            }
        }

        // ---- online softmax ----
        float mx0 = -1e30f, mx1 = -1e30f;
#pragma unroll
        for (int nt = 0; nt < 4; nt++) {
            mx0 = fmaxf(mx0, fmaxf(c4[nt][0], c4[nt][1]));
            mx1 = fmaxf(mx1, fmaxf(c4[nt][2], c4[nt][3]));
        }
        mx0 = fmaxf(mx0, __shfl_xor_sync(0xffffffffu, mx0, 1));
        mx0 = fmaxf(mx0, __shfl_xor_sync(0xffffffffu, mx0, 2));
        mx1 = fmaxf(mx1, __shfl_xor_sync(0xffffffffu, mx1, 1));
        mx1 = fmaxf(mx1, __shfl_xor_sync(0xffffffffu, mx1, 2));
        if (qi == 0) { red[h * 64 + r0] = mx0; red[h * 64 + r1] = mx1; }
        __syncthreads();
        float mnew0 = fmaxf(rmax0, fmaxf(red[r0], red[64 + r0]));
        float mnew1 = fmaxf(rmax1, fmaxf(red[r1], red[64 + r1]));
        float corr0 = __expf(rmax0 - mnew0);
        float corr1 = __expf(rmax1 - mnew1);
        rmax0 = mnew0; rmax1 = mnew1;

        float ps0 = 0.f, ps1 = 0.f;
#pragma unroll
        for (int nt = 0; nt < 4; nt++) {
            int colcb = (32 * h + 8 * nt + 2 * qi) * 2;
            float p00 = __expf(c4[nt][0] - mnew0);
            float p01 = __expf(c4[nt][1] - mnew0);
            float p10 = __expf(c4[nt][2] - mnew1);
            float p11 = __expf(c4[nt][3] - mnew1);
            ps0 += p00 + p01; ps1 += p10 + p11;
            __nv_bfloat16 h00 = __float2bfloat16(p00), h01 = __float2bfloat16(p01);
            __nv_bfloat16 h10 = __float2bfloat16(p10), h11 = __float2bfloat16(p11);
            unsigned uh0 = (unsigned)__bfloat16_as_ushort(h00) | ((unsigned)__bfloat16_as_ushort(h01) << 16);
            unsigned uh1 = (unsigned)__bfloat16_as_ushort(h10) | ((unsigned)__bfloat16_as_ushort(h11) << 16);
            __nv_bfloat16 l00 = __float2bfloat16(p00 - __bfloat162float(h00));
            __nv_bfloat16 l01 = __float2bfloat16(p01 - __bfloat162float(h01));
            __nv_bfloat16 l10 = __float2bfloat16(p10 - __bfloat162float(h10));
            __nv_bfloat16 l11 = __float2bfloat16(p11 - __bfloat162float(h11));
            unsigned ul0 = (unsigned)__bfloat16_as_ushort(l00) | ((unsigned)__bfloat16_as_ushort(l01) << 16);
            unsigned ul1 = (unsigned)__bfloat16_as_ushort(l10) | ((unsigned)__bfloat16_as_ushort(l11) << 16);
            *(unsigned*)(sP + SW(r0, colcb)) = uh0;
            *(unsigned*)(sP + SW(r1, colcb)) = uh1;
            *(unsigned*)(sP + 8192 + SW(r0, colcb)) = ul0;
            *(unsigned*)(sP + 8192 + SW(r1, colcb)) = ul1;
        }
        ps0 += __shfl_xor_sync(0xffffffffu, ps0, 1);
        ps0 += __shfl_xor_sync(0xffffffffu, ps0, 2);
        ps1 += __shfl_xor_sync(0xffffffffu, ps1, 1);
        ps1 += __shfl_xor_sync(0xffffffffu, ps1, 2);
        if (qi == 0) { red[128 + h * 64 + r0] = ps0; red[128 + h * 64 + r1] = ps1; }
        __syncthreads();
        rsum0 = rsum0 * corr0 + red[128 + r0] + red[192 + r0];
        rsum1 = rsum1 * corr1 + red[128 + r1] + red[192 + r1];
#pragma unroll
        for (int nt = 0; nt < 8; nt++) {
            oc[nt * 4 + 0] *= corr0; oc[nt * 4 + 1] *= corr0;
            oc[nt * 4 + 2] *= corr1; oc[nt * 4 + 3] *= corr1;
        }

        // ---- O += P V : warp covers 16 rows x 64 cols over its 32-key slice ----
#pragma unroll
        for (int ck = 0; ck < 2; ck++) {
            int key0 = 32 * h + 16 * ck;
            unsigned ph[4], pl[4];
            {
                int r = qg * 16 + (lane & 7) + ((lane & 8) ? 8 : 0);
                int cb = key0 * 2 + ((lane & 16) ? 16 : 0);
                ldsm4(ph, smu32(sP + SW(r, cb)));
                ldsm4(pl, smu32(sP + 8192 + SW(r, cb)));
            }
#pragma unroll
            for (int cc = 0; cc < 4; cc++) {
                unsigned vh[4], vl[4];
                {
                    int r = key0 + (lane & 7) + ((lane & 8) ? 8 : 0);
                    int cb = cc * 32 + ((lane & 16) ? 16 : 0);
                    ldsm4t(vh, smu32(sVh + SW(r, cb)));
                    ldsm4t(vl, smu32(sVl + SW(r, cb)));
                }
                mma_bf(&oc[(2 * cc) * 4], ph, &vh[0]);
                mma_bf(&oc[(2 * cc) * 4], ph, &vl[0]);
                mma_bf(&oc[(2 * cc) * 4], pl, &vh[0]);
                mma_bf(&oc[(2 * cc + 1) * 4], ph, &vh[2]);
                mma_bf(&oc[(2 * cc + 1) * 4], ph, &vl[2]);
                mma_bf(&oc[(2 * cc + 1) * 4], pl, &vh[2]);
            }
        }
    }

    // ---- combine key-halves, scale, write ----
    __syncthreads();
    float* sO = (float*)sP;
    if (h == 1) {
#pragma unroll
        for (int nt = 0; nt < 8; nt++) {
            int colb = 8 * nt + 2 * qi;
            sO[r0 * 64 + colb]     = oc[nt * 4 + 0];
            sO[r0 * 64 + colb + 1] = oc[nt * 4 + 1];
            sO[r1 * 64 + colb]     = oc[nt * 4 + 2];
            sO[r1 * 64 + colb + 1] = oc[nt * 4 + 3];
        }
    }
    __syncthreads();
    if (h == 0) {
        float inv0 = 1.f / rsum0, inv1 = 1.f / rsum1;
#pragma unroll
        for (int nt = 0; nt < 8; nt++) {
            int colb = 8 * nt + 2 * qi;
            if (r0 < nqv) {
                O[(size_t)(qbase + r0) * 64 + colb]     = (oc[nt * 4 + 0] + sO[r0 * 64 + colb]) * inv0;
                O[(size_t)(qbase + r0) * 64 + colb + 1] = (oc[nt * 4 + 1] + sO[r0 * 64 + colb + 1]) * inv0;
            }
            if (r1 < nqv) {
                O[(size_t)(qbase + r1) * 64 + colb]     = (oc[nt * 4 + 2] + sO[r1 * 64 + colb]) * inv1;
                O[(size_t)(qbase + r1) * 64 + colb + 1] = (oc[nt * 4 + 3] + sO[r1 * 64 + colb + 1]) * inv1;
            }
        }
    }
}

// ---------------------------------------------------------------------------
// BatchNorm pieces
// ---------------------------------------------------------------------------
__global__ void k_bnstats(const float* __restrict__ X, int N)
{
    __shared__ float sh[2][4][64];
    int c = threadIdx.x & 63, rg = threadIdx.x >> 6;
    float s = 0.f, s2 = 0.f;
    for (int r = blockIdx.x * 4 + rg; r < N; r += 256) {
        float v = X[r * 64 + c];
        s += v; s2 += v * v;
    }
    sh[0][rg][c] = s; sh[1][rg][c] = s2;
    __syncthreads();
    if (threadIdx.x < 64) {
        float ts = sh[0][0][c] + sh[0][1][c] + sh[0][2][c] + sh[0][3][c];
        float t2 = sh[1][0][c] + sh[1][1][c] + sh[1][2][c] + sh[1][3][c];
        g_part[blockIdx.x * 128 + c] = ts;
        g_part[blockIdx.x * 128 + 64 + c] = t2;
    }
}

__global__ void k_bnfin(int N)
{
    int c = threadIdx.x;
    float s = 0.f, s2 = 0.f;
    for (int b = 0; b < 64; b++) { s += g_part[b * 128 + c]; s2 += g_part[b * 128 + 64 + c]; }
    float m = s / (float)N;
    float v = s2 / (float)N - m * m;
    g_stats[c] = m;
    g_stats[64 + c] = rsqrtf(v + 1e-4f);
}

__global__ void k_bnapply(const float* __restrict__ X, const float* __restrict__ Res,
                          const float* __restrict__ gamma, const float* __restrict__ beta,
                          float* __restrict__ Out, int N, int mode)
{
    int i = blockIdx.x * blockDim.x + threadIdx.x;
    if (i < N * 64) {
        int c = i & 63;
        float y = (X[i] - g_stats[c]) * g_stats[64 + c] * gamma[c] + beta[c];
        if (mode == 1) y += Res[i];
        if (mode == 2) y = fmaxf(y, 0.f);
        Out[i] = y;
    }
}

__global__ void k_add(const float* __restrict__ X, const float* __restrict__ Y,
                      float* __restrict__ Out, int N)
{
    int i = blockIdx.x * blockDim.x + threadIdx.x;
    if (i < N * 64) Out[i] = X[i] + Y[i];
}

// ---------------------------------------------------------------------------
extern "C" void kernel_launch(void* const* d_in, const int* in_sizes, int n_in,
                              void* d_out, int out_size)
{
    const float* xdec  = (const float*)d_in[0];
    const float* xenc  = (const float*)d_in[1];
    const float* Wp1   = (const float*)d_in[2];
    const float* Wq    = (const float*)d_in[3];
    const float* Wk    = (const float*)d_in[4];
    const float* Wv    = (const float*)d_in[5];
    const float* Wt    = (const float*)d_in[6];
    const float* Wq1   = (const float*)d_in[7];
    const float* Wk1   = (const float*)d_in[8];
    const float* Wv1   = (const float*)d_in[9];
    const float* Wdown = (const float*)d_in[10];
    const float* W3t   = (const float*)d_in[11];
    const float* W3a   = (const float*)d_in[12];
    const float* W3b   = (const float*)d_in[13];
    const float* gam   = (const float*)d_in[14];
    const float* bet   = (const float*)d_in[15];
    const int* nbr     = (const int*)d_in[16];
    const int* kv_nbr  = (const int*)d_in[17];
    const int* pad_idx = (const int*)d_in[18];

    int nd = in_sizes[0] / 64;
    int ne = in_sizes[1] / 64;
    int lq = in_sizes[18] / NBATCH;
    float* out = (float*)d_out;

    float* base = nullptr;
    cudaGetSymbolAddress((void**)&base, g_buf);
    float* B[15];
    for (int i = 0; i < 15; i++) B[i] = base + (size_t)i * CELLS;

    __nv_bfloat16* bfb = nullptr;
    cudaGetSymbolAddress((void**)&bfb, g_bf);
    __nv_bfloat16* BF[6];
    for (int i = 0; i < 6; i++) BF[i] = bfb + (size_t)i * PADCELLS;

    cudaFuncSetAttribute(k_flash_bf, cudaFuncAttributeMaxDynamicSharedMemorySize, FLASH_SMEM_BF);

    dim3 thr(256);
    int gbd = (nd + 63) / 64;
    int gbe = (ne + 63) / 64;
    int gel = (nd * 64 + 255) / 256;
    int ndp = (nd + 64) * 64, nep = (ne + 64) * 64;
    int gcd = (ndp + 255) / 256, gce = (nep + 255) / 256;

    // Stage 1
    k_gemm64<<<gbd, thr>>>(xdec, Wp1, B[0], nd);          // xd0
    k_gemm64<<<gbd, thr>>>(B[0], Wq, B[1], nd);           // q
    k_gemm64<<<gbe, thr>>>(xenc, Wk, B[2], ne);           // ke
    k_gemm64<<<gbe, thr>>>(xenc, Wv, B[3], ne);           // ve
    k_prep<<<1, thr>>>(pad_idx, nd, ne, lq);
    k_cvt<<<gcd, thr>>>(B[1], BF[0], BF[1], nd * 64, ndp);
    k_cvt<<<gce, thr>>>(B[2], BF[2], BF[3], ne * 64, nep);
    k_cvt<<<gce, thr>>>(B[3], BF[4], BF[5], ne * 64, nep);
    k_flash_bf<<<gbd, thr, FLASH_SMEM_BF>>>(BF[0], BF[1], BF[2], BF[3], BF[4], BF[5], B[4], 0, gbd);
    k_gemm64<<<gbd, thr>>>(B[4], Wt, B[5], nd);           // xr
    k_bnstats<<<64, thr>>>(B[5], nd);
    k_bnfin<<<1, 64>>>(nd);
    k_bnapply<<<gel, thr>>>(B[5], B[0], gam + 0, bet + 0, B[6], nd, 1);   // xd

    // Stage 2
    k_gemm64<<<gbd, thr>>>(B[6], Wq1, B[7], nd);          // q1
    k_gconv<<<gbd, thr>>>(B[7], kv_nbr, 8, Wdown, B[8], nd);
    k_bnstats<<<64, thr>>>(B[8], nd);
    k_bnfin<<<1, 64>>>(nd);
    k_bnapply<<<gel, thr>>>(B[8], B[8], gam + 64, bet + 64, B[9], nd, 0); // kv
    k_gemm64<<<gbd, thr>>>(B[9], Wk1, B[10], nd);         // k1
    k_gemm64<<<gbd, thr>>>(B[9], Wv1, B[11], nd);         // v1
    k_cvt<<<gcd, thr>>>(B[7],  BF[0], BF[1], nd * 64, ndp);
    k_cvt<<<gcd, thr>>>(B[10], BF[2], BF[3], nd * 64, ndp);
    k_cvt<<<gcd, thr>>>(B[11], BF[4], BF[5], nd * 64, ndp);
    int tps = (lq + 63) / 64;
    k_flash_bf<<<NBATCH * tps, thr, FLASH_SMEM_BF>>>(BF[0], BF[1], BF[2], BF[3], BF[4], BF[5], B[12], 1, tps);
    k_gconv<<<gbd, thr>>>(B[12], nbr, 27, W3t, B[13], nd);
    k_bnstats<<<64, thr>>>(B[13], nd);
    k_bnfin<<<1, 64>>>(nd);
    k_bnapply<<<gel, thr>>>(B[13], B[6], gam + 128, bet + 128, B[14], nd, 1); // xd2

    // Res block
    k_bnstats<<<64, thr>>>(B[14], nd);
    k_bnfin<<<1, 64>>>(nd);
    k_bnapply<<<gel, thr>>>(B[14], B[14], gam + 192, bet + 192, B[0], nd, 2);
    k_gconv<<<gbd, thr>>>(B[0], nbr, 27, W3a, B[1], nd);
    k_bnstats<<<64, thr>>>(B[1], nd);
    k_bnfin<<<1, 64>>>(nd);
    k_bnapply<<<gel, thr>>>(B[1], B[1], gam + 256, bet + 256, B[2], nd, 2);
    k_gconv<<<gbd, thr>>>(B[2], nbr, 27, W3b, B[3], nd);
    k_add<<<gel, thr>>>(B[14], B[3], B[4], nd);
    k_bnstats<<<64, thr>>>(B[4], nd);
    k_bnfin<<<1, 64>>>(nd);
    k_bnapply<<<gel, thr>>>(B[4], B[4], gam + 320, bet + 320, out, nd, 2);
}

// round 5
// speedup vs baseline: 2.4503x; 1.0803x over previous
#include <cuda_runtime.h>
#include <cuda_bf16.h>
#include <math.h>

#define NF 64
#define NBATCH 8
#define CELLS (12288 * NF)
#define PADCELLS (CELLS + 64 * 64)

// Static scratch (no runtime allocation). Zero-initialized; bf16 pad rows are
// never written so they remain zero across calls.
__device__ float g_buf[15][CELLS];
__device__ __nv_bfloat16 g_bf[6][PADCELLS];  // Qhi Qlo Khi Klo Vhi Vlo
__device__ float g_stats[128];
__device__ float g_part[64 * 128];
__device__ int   g_seg[64];

// ---------------------------------------------------------------------------
// Helpers
// ---------------------------------------------------------------------------
__device__ __forceinline__ int SW(int r, int cb) {          // swizzled byte offset, 128B pitch
    return r * 128 + (cb ^ ((r & 7) << 4));
}
__device__ __forceinline__ unsigned smu32(const void* p) {
    return (unsigned)__cvta_generic_to_shared(p);
}
__device__ __forceinline__ void cpa16(unsigned dst, const void* src) {
    asm volatile("cp.async.ca.shared.global [%0], [%1], 16;" :: "r"(dst), "l"(src) : "memory");
}
#define CP_COMMIT() asm volatile("cp.async.commit_group;" ::: "memory")
#define CP_WAIT1()  asm volatile("cp.async.wait_group 1;" ::: "memory")

__device__ __forceinline__ void ldsm4(unsigned r[4], unsigned a) {
    asm volatile("ldmatrix.sync.aligned.m8n8.x4.shared.b16 {%0,%1,%2,%3}, [%4];"
                 : "=r"(r[0]), "=r"(r[1]), "=r"(r[2]), "=r"(r[3]) : "r"(a));
}
__device__ __forceinline__ void ldsm4t(unsigned r[4], unsigned a) {
    asm volatile("ldmatrix.sync.aligned.m8n8.x4.trans.shared.b16 {%0,%1,%2,%3}, [%4];"
                 : "=r"(r[0]), "=r"(r[1]), "=r"(r[2]), "=r"(r[3]) : "r"(a));
}
__device__ __forceinline__ void mma_bf(float c[4], const unsigned a[4], const unsigned b[2]) {
    asm volatile(
        "mma.sync.aligned.m16n8k16.row.col.f32.bf16.bf16.f32 "
        "{%0,%1,%2,%3}, {%4,%5,%6,%7}, {%8,%9}, {%0,%1,%2,%3};"
        : "+f"(c[0]), "+f"(c[1]), "+f"(c[2]), "+f"(c[3])
        : "r"(a[0]), "r"(a[1]), "r"(a[2]), "r"(a[3]), "r"(b[0]), "r"(b[1]));
}

// ---------------------------------------------------------------------------
// GEMM: C[N,64] = A[N,64] @ W[64,64]; optional fused fp32->bf16 hi/lo output.
// ---------------------------------------------------------------------------
__global__ void __launch_bounds__(256) k_gemm64(
    const float* __restrict__ A, const float* __restrict__ W,
    float* __restrict__ C, int N,
    __nv_bfloat16* __restrict__ hi, __nv_bfloat16* __restrict__ lo)
{
    __shared__ float sW[64 * 64];
    __shared__ float sA[64 * 65];
    int t = threadIdx.x;
    int row0 = blockIdx.x * 64;
    for (int i = t; i < 4096; i += 256) {
        sW[i] = W[i];
        int r = i >> 6, c = i & 63;
        int gr = row0 + r;
        sA[r * 65 + c] = (gr < N) ? A[gr * 64 + c] : 0.f;
    }
    __syncthreads();
    int a = t >> 4, b = t & 15;
    float4 acc[4];
#pragma unroll
    for (int i = 0; i < 4; i++) acc[i] = make_float4(0.f, 0.f, 0.f, 0.f);
#pragma unroll 8
    for (int m = 0; m < 64; m++) {
        float4 w = *reinterpret_cast<const float4*>(&sW[m * 64 + 4 * b]);
#pragma unroll
        for (int i = 0; i < 4; i++) {
            float av = sA[(a + 16 * i) * 65 + m];
            acc[i].x += av * w.x; acc[i].y += av * w.y;
            acc[i].z += av * w.z; acc[i].w += av * w.w;
        }
    }
#pragma unroll
    for (int i = 0; i < 4; i++) {
        int gr = row0 + a + 16 * i;
        if (gr < N) {
            *reinterpret_cast<float4*>(&C[gr * 64 + 4 * b]) = acc[i];
            if (hi) {
                float v[4] = { acc[i].x, acc[i].y, acc[i].z, acc[i].w };
                unsigned short hbits[4], lbits[4];
#pragma unroll
                for (int j = 0; j < 4; j++) {
                    __nv_bfloat16 h = __float2bfloat16(v[j]);
                    hbits[j] = __bfloat16_as_ushort(h);
                    lbits[j] = __bfloat16_as_ushort(__float2bfloat16(v[j] - __bfloat162float(h)));
                }
                uint2 hp, lp;
                hp.x = (unsigned)hbits[0] | ((unsigned)hbits[1] << 16);
                hp.y = (unsigned)hbits[2] | ((unsigned)hbits[3] << 16);
                lp.x = (unsigned)lbits[0] | ((unsigned)lbits[1] << 16);
                lp.y = (unsigned)lbits[2] | ((unsigned)lbits[3] << 16);
                *reinterpret_cast<uint2*>(&hi[(size_t)gr * 64 + 4 * b]) = hp;
                *reinterpret_cast<uint2*>(&lo[(size_t)gr * 64 + 4 * b]) = lp;
            }
        }
    }
}

// ---------------------------------------------------------------------------
// Rulebook sparse conv with block-wide empty-tap skipping.
// ---------------------------------------------------------------------------
__global__ void __launch_bounds__(256) k_gconv(
    const float* __restrict__ F, const int* __restrict__ idx, int K,
    const float* __restrict__ W, float* __restrict__ out, int N)
{
    __shared__ float sW[64 * 64];
    __shared__ float sF[64 * 68];
    __shared__ int   sIdx[64];
    int t = threadIdx.x;
    int row0 = blockIdx.x * 64;
    int a = t >> 4, b = t & 15;
    float4 acc[4];
#pragma unroll
    for (int i = 0; i < 4; i++) acc[i] = make_float4(0.f, 0.f, 0.f, 0.f);

    for (int k = 0; k < K; k++) {
        __syncthreads();   // prior compute done: safe to overwrite sIdx/sF/sW
        int myvalid = 0;
        if (t < 64) {
            int gr = row0 + t;
            int j = (gr < N) ? idx[gr * K + k] : -1;
            sIdx[t] = j;
            myvalid = (j >= 0);
        }
        if (!__syncthreads_or(myvalid)) continue;   // empty tap: skip everything
        for (int i = t; i < 4096; i += 256) sW[i] = W[k * 4096 + i];
        {
            int rr = t >> 2;
            int j = sIdx[rr];
            if (j >= 0) {
                int c0 = (t & 3) * 16;
#pragma unroll
                for (int q4 = 0; q4 < 4; q4++)
                    *reinterpret_cast<float4*>(&sF[rr * 68 + c0 + 4 * q4]) =
                        *reinterpret_cast<const float4*>(&F[j * 64 + c0 + 4 * q4]);
            }
        }
        __syncthreads();
#pragma unroll
        for (int i = 0; i < 4; i++) {
            int r = a + 16 * i;
            if (sIdx[r] >= 0) {
#pragma unroll 8
                for (int m = 0; m < 64; m++) {
                    float av = sF[r * 68 + m];
                    float4 w = *reinterpret_cast<const float4*>(&sW[m * 64 + 4 * b]);
                    acc[i].x += av * w.x; acc[i].y += av * w.y;
                    acc[i].z += av * w.z; acc[i].w += av * w.w;
                }
            }
        }
    }
#pragma unroll
    for (int i = 0; i < 4; i++) {
        int gr = row0 + a + 16 * i;
        if (gr < N) *reinterpret_cast<float4*>(&out[gr * 64 + 4 * b]) = acc[i];
    }
}

// ---------------------------------------------------------------------------
// Segment prep
// ---------------------------------------------------------------------------
__global__ void k_prep(const int* __restrict__ pad_idx, int nd, int ne, int lq)
{
    int t = threadIdx.x;
    int w = t >> 5, lane = t & 31;
    if (w < NBATCH) {
        int cnt = 0;
        for (int l = lane; l < lq; l += 32)
            cnt += (pad_idx[w * lq + l] >= 0) ? 1 : 0;
#pragma unroll
        for (int o = 16; o > 0; o >>= 1) cnt += __shfl_xor_sync(0xffffffffu, cnt, o);
        if (lane == 0) {
            int s = pad_idx[w * lq];
            g_seg[(1 + w) * 4 + 0] = s;
            g_seg[(1 + w) * 4 + 1] = cnt;
            g_seg[(1 + w) * 4 + 2] = s;
            g_seg[(1 + w) * 4 + 3] = cnt;
        }
    }
    if (t == 0) { g_seg[0] = 0; g_seg[1] = nd; g_seg[2] = 0; g_seg[3] = ne; }
}

// ---------------------------------------------------------------------------
// bf16 3x tensor-core flash attention; per-half INDEPENDENT online softmax
// (halves merged once in the epilogue) -> only 2 block barriers per key tile.
// ---------------------------------------------------------------------------
#define FLASH_SMEM_BF (65536 + 16384 + 16384 + 1024)

__global__ void __launch_bounds__(256, 2) k_flash_bf(
    const __nv_bfloat16* __restrict__ gQh, const __nv_bfloat16* __restrict__ gQl,
    const __nv_bfloat16* __restrict__ gKh, const __nv_bfloat16* __restrict__ gKl,
    const __nv_bfloat16* __restrict__ gVh, const __nv_bfloat16* __restrict__ gVl,
    float* __restrict__ O, int seg_off, int tiles_per_seg)
{
    extern __shared__ char smc[];
    char* sKV = smc;                    // 2 x [Khi|Klo|Vhi|Vlo] x 8KB
    char* sQ  = smc + 65536;            // Qhi 8KB, Qlo 8KB
    char* sP  = smc + 81920;            // Phi 8KB, Plo 8KB / fp32 O staging
    float* red = (float*)(smc + 98304); // m[2][64], s[2][64]

    int bx = blockIdx.x;
    int segi = bx / tiles_per_seg;
    int tile = bx - segi * tiles_per_seg;
    int seg = seg_off + segi;
    int q0 = g_seg[seg * 4 + 0], nq = g_seg[seg * 4 + 1];
    int k0 = g_seg[seg * 4 + 2], nk = g_seg[seg * 4 + 3];
    if (tile * 64 >= nq) return;
    int qbase = q0 + tile * 64;
    int nqv = min(64, nq - tile * 64);

    int t = threadIdx.x;
    int w = t >> 5, lane = t & 31;
    int qg = w & 3, h = w >> 2;
    int quad = lane >> 2, qi = lane & 3;
    int r0 = qg * 16 + quad, r1 = r0 + 8;

    // prologue: Q + KV tile 0
    {
#pragma unroll
        for (int j = 0; j < 2; j++) {
            int chunk = t + 256 * j;
            int row = chunk >> 3, jj = chunk & 7;
            cpa16(smu32(sQ + SW(row, jj << 4)),        gQh + (size_t)(qbase + row) * 64 + jj * 8);
            cpa16(smu32(sQ + 8192 + SW(row, jj << 4)), gQl + (size_t)(qbase + row) * 64 + jj * 8);
        }
        const __nv_bfloat16* gs[4] = { gKh, gKl, gVh, gVl };
#pragma unroll
        for (int a = 0; a < 4; a++)
#pragma unroll
            for (int j = 0; j < 2; j++) {
                int chunk = t + 256 * j;
                int row = chunk >> 3, jj = chunk & 7;
                cpa16(smu32(sKV + a * 8192 + SW(row, jj << 4)),
                      gs[a] + (size_t)(k0 + row) * 64 + jj * 8);
            }
    }
    CP_COMMIT();

    float oc[32];
#pragma unroll
    for (int i = 0; i < 32; i++) oc[i] = 0.f;
    float rmax0 = -1e30f, rmax1 = -1e30f, rsum0 = 0.f, rsum1 = 0.f;

    int nkt = (nk + 63) >> 6;
    for (int kt = 0; kt < nkt; kt++) {
        char* sb = sKV + (kt & 1) * 32768;
        __syncthreads();
        if (kt + 1 < nkt) {
            char* nb = sKV + ((kt + 1) & 1) * 32768;
            int kb = k0 + (kt + 1) * 64;
            const __nv_bfloat16* gs[4] = { gKh, gKl, gVh, gVl };
#pragma unroll
            for (int a = 0; a < 4; a++)
#pragma unroll
                for (int j = 0; j < 2; j++) {
                    int chunk = t + 256 * j;
                    int row = chunk >> 3, jj = chunk & 7;
                    cpa16(smu32(nb + a * 8192 + SW(row, jj << 4)),
                          gs[a] + (size_t)(kb + row) * 64 + jj * 8);
                }
        }
        CP_COMMIT();
        CP_WAIT1();
        __syncthreads();

        int nkv = min(64, nk - kt * 64);
        char* sKh = sb;
        char* sKl = sb + 8192;
        char* sVh = sb + 16384;
        char* sVl = sb + 24576;

        // ---- S = Q K^T ----
        float c4[4][4];
#pragma unroll
        for (int nt = 0; nt < 4; nt++)
#pragma unroll
            for (int k = 0; k < 4; k++) c4[nt][k] = 0.f;

#pragma unroll
        for (int ch = 0; ch < 4; ch++) {
            unsigned qh[4], ql[4];
            {
                int r = qg * 16 + (lane & 7) + ((lane & 8) ? 8 : 0);
                int cb = ch * 32 + ((lane & 16) ? 16 : 0);
                ldsm4(qh, smu32(sQ + SW(r, cb)));
                ldsm4(ql, smu32(sQ + 8192 + SW(r, cb)));
            }
            unsigned kh[8], kl[8];
            {
                int r = 32 * h + (lane & 7) + ((lane & 16) ? 8 : 0);
                int cb = ch * 32 + ((lane & 8) ? 16 : 0);
                ldsm4(kh,     smu32(sKh + SW(r, cb)));
                ldsm4(kh + 4, smu32(sKh + SW(r + 16, cb)));
                ldsm4(kl,     smu32(sKl + SW(r, cb)));
                ldsm4(kl + 4, smu32(sKl + SW(r + 16, cb)));
            }
#pragma unroll
            for (int nt = 0; nt < 4; nt++) {
                mma_bf(c4[nt], qh, &kh[2 * nt]);
                mma_bf(c4[nt], qh, &kl[2 * nt]);
                mma_bf(c4[nt], ql, &kh[2 * nt]);
            }
        }

        if (nkv < 64) {
#pragma unroll
            for (int nt = 0; nt < 4; nt++) {
                int colb = 32 * h + 8 * nt + 2 * qi;
#pragma unroll
                for (int k = 0; k < 4; k++)
                    if (colb + (k & 1) >= nkv) c4[nt][k] = -1e30f;
            }
        }

        // ---- warp-local online softmax (per half) ----
        float mx0 = -1e30f, mx1 = -1e30f;
#pragma unroll
        for (int nt = 0; nt < 4; nt++) {
            mx0 = fmaxf(mx0, fmaxf(c4[nt][0], c4[nt][1]));
            mx1 = fmaxf(mx1, fmaxf(c4[nt][2], c4[nt][3]));
        }
        mx0 = fmaxf(mx0, __shfl_xor_sync(0xffffffffu, mx0, 1));
        mx0 = fmaxf(mx0, __shfl_xor_sync(0xffffffffu, mx0, 2));
        mx1 = fmaxf(mx1, __shfl_xor_sync(0xffffffffu, mx1, 1));
        mx1 = fmaxf(mx1, __shfl_xor_sync(0xffffffffu, mx1, 2));
        float mnew0 = fmaxf(rmax0, mx0);
        float mnew1 = fmaxf(rmax1, mx1);
        float corr0 = __expf(rmax0 - mnew0);
        float corr1 = __expf(rmax1 - mnew1);
        rmax0 = mnew0; rmax1 = mnew1;

        float ps0 = 0.f, ps1 = 0.f;
#pragma unroll
        for (int nt = 0; nt < 4; nt++) {
            int colcb = (32 * h + 8 * nt + 2 * qi) * 2;
            float p00 = __expf(c4[nt][0] - mnew0);
            float p01 = __expf(c4[nt][1] - mnew0);
            float p10 = __expf(c4[nt][2] - mnew1);
            float p11 = __expf(c4[nt][3] - mnew1);
            ps0 += p00 + p01; ps1 += p10 + p11;
            __nv_bfloat16 h00 = __float2bfloat16(p00), h01 = __float2bfloat16(p01);
            __nv_bfloat16 h10 = __float2bfloat16(p10), h11 = __float2bfloat16(p11);
            unsigned uh0 = (unsigned)__bfloat16_as_ushort(h00) | ((unsigned)__bfloat16_as_ushort(h01) << 16);
            unsigned uh1 = (unsigned)__bfloat16_as_ushort(h10) | ((unsigned)__bfloat16_as_ushort(h11) << 16);
            __nv_bfloat16 l00 = __float2bfloat16(p00 - __bfloat162float(h00));
            __nv_bfloat16 l01 = __float2bfloat16(p01 - __bfloat162float(h01));
            __nv_bfloat16 l10 = __float2bfloat16(p10 - __bfloat162float(h10));
            __nv_bfloat16 l11 = __float2bfloat16(p11 - __bfloat162float(h11));
            unsigned ul0 = (unsigned)__bfloat16_as_ushort(l00) | ((unsigned)__bfloat16_as_ushort(l01) << 16);
            unsigned ul1 = (unsigned)__bfloat16_as_ushort(l10) | ((unsigned)__bfloat16_as_ushort(l11) << 16);
            *(unsigned*)(sP + SW(r0, colcb)) = uh0;
            *(unsigned*)(sP + SW(r1, colcb)) = uh1;
            *(unsigned*)(sP + 8192 + SW(r0, colcb)) = ul0;
            *(unsigned*)(sP + 8192 + SW(r1, colcb)) = ul1;
        }
        ps0 += __shfl_xor_sync(0xffffffffu, ps0, 1);
        ps0 += __shfl_xor_sync(0xffffffffu, ps0, 2);
        ps1 += __shfl_xor_sync(0xffffffffu, ps1, 1);
        ps1 += __shfl_xor_sync(0xffffffffu, ps1, 2);
        rsum0 = rsum0 * corr0 + ps0;
        rsum1 = rsum1 * corr1 + ps1;
#pragma unroll
        for (int nt = 0; nt < 8; nt++) {
            oc[nt * 4 + 0] *= corr0; oc[nt * 4 + 1] *= corr0;
            oc[nt * 4 + 2] *= corr1; oc[nt * 4 + 3] *= corr1;
        }
        __syncwarp();   // P stores visible to cross-lane ldmatrix within warp

        // ---- O += P V ----
#pragma unroll
        for (int ck = 0; ck < 2; ck++) {
            int key0 = 32 * h + 16 * ck;
            unsigned ph[4], pl[4];
            {
                int r = qg * 16 + (lane & 7) + ((lane & 8) ? 8 : 0);
                int cb = key0 * 2 + ((lane & 16) ? 16 : 0);
                ldsm4(ph, smu32(sP + SW(r, cb)));
                ldsm4(pl, smu32(sP + 8192 + SW(r, cb)));
            }
#pragma unroll
            for (int cc = 0; cc < 4; cc++) {
                unsigned vh[4], vl[4];
                {
                    int r = key0 + (lane & 7) + ((lane & 8) ? 8 : 0);
                    int cb = cc * 32 + ((lane & 16) ? 16 : 0);
                    ldsm4t(vh, smu32(sVh + SW(r, cb)));
                    ldsm4t(vl, smu32(sVl + SW(r, cb)));
                }
                mma_bf(&oc[(2 * cc) * 4], ph, &vh[0]);
                mma_bf(&oc[(2 * cc) * 4], ph, &vl[0]);
                mma_bf(&oc[(2 * cc) * 4], pl, &vh[0]);
                mma_bf(&oc[(2 * cc + 1) * 4], ph, &vh[2]);
                mma_bf(&oc[(2 * cc + 1) * 4], ph, &vl[2]);
                mma_bf(&oc[(2 * cc + 1) * 4], pl, &vh[2]);
            }
        }
    }

    // ---- merge halves once ----
    if (qi == 0) {
        red[h * 64 + r0] = rmax0;       red[h * 64 + r1] = rmax1;
        red[128 + h * 64 + r0] = rsum0; red[128 + h * 64 + r1] = rsum1;
    }
    __syncthreads();   // also: all sP reads finished -> reusable as fp32 O

    float m0a = red[r0], m1a = red[64 + r0];
    float mma_ = fmaxf(m0a, m1a);
    float fh_a = __expf(((h == 0) ? m0a : m1a) - mma_);
    float stot_a = red[128 + r0] * __expf(m0a - mma_) + red[192 + r0] * __expf(m1a - mma_);
    float m0b = red[r1], m1b = red[64 + r1];
    float mmb_ = fmaxf(m0b, m1b);
    float fh_b = __expf(((h == 0) ? m0b : m1b) - mmb_);
    float stot_b = red[128 + r1] * __expf(m0b - mmb_) + red[192 + r1] * __expf(m1b - mmb_);

    float* sO = (float*)sP;
    if (h == 1) {
#pragma unroll
        for (int nt = 0; nt < 8; nt++) {
            int colb = 8 * nt + 2 * qi;
            sO[r0 * 64 + colb]     = oc[nt * 4 + 0] * fh_a;
            sO[r0 * 64 + colb + 1] = oc[nt * 4 + 1] * fh_a;
            sO[r1 * 64 + colb]     = oc[nt * 4 + 2] * fh_b;
            sO[r1 * 64 + colb + 1] = oc[nt * 4 + 3] * fh_b;
        }
    }
    __syncthreads();
    if (h == 0) {
        float inva = fh_a / stot_a, invb = fh_b / stot_b;
        float ja = 1.f / stot_a, jb = 1.f / stot_b;
#pragma unroll
        for (int nt = 0; nt < 8; nt++) {
            int colb = 8 * nt + 2 * qi;
            if (r0 < nqv) {
                O[(size_t)(qbase + r0) * 64 + colb]     = oc[nt * 4 + 0] * inva + sO[r0 * 64 + colb] * ja;
                O[(size_t)(qbase + r0) * 64 + colb + 1] = oc[nt * 4 + 1] * inva + sO[r0 * 64 + colb + 1] * ja;
            }
            if (r1 < nqv) {
                O[(size_t)(qbase + r1) * 64 + colb]     = oc[nt * 4 + 2] * invb + sO[r1 * 64 + colb] * jb;
                O[(size_t)(qbase + r1) * 64 + colb + 1] = oc[nt * 4 + 3] * invb + sO[r1 * 64 + colb + 1] * jb;
            }
        }
    }
}

// ---------------------------------------------------------------------------
// BatchNorm pieces
// ---------------------------------------------------------------------------
__global__ void k_bnstats(const float* __restrict__ X, int N)
{
    __shared__ float sh[2][4][64];
    int c = threadIdx.x & 63, rg = threadIdx.x >> 6;
    float s = 0.f, s2 = 0.f;
    for (int r = blockIdx.x * 4 + rg; r < N; r += 256) {
        float v = X[r * 64 + c];
        s += v; s2 += v * v;
    }
    sh[0][rg][c] = s; sh[1][rg][c] = s2;
    __syncthreads();
    if (threadIdx.x < 64) {
        float ts = sh[0][0][c] + sh[0][1][c] + sh[0][2][c] + sh[0][3][c];
        float t2 = sh[1][0][c] + sh[1][1][c] + sh[1][2][c] + sh[1][3][c];
        g_part[blockIdx.x * 128 + c] = ts;
        g_part[blockIdx.x * 128 + 64 + c] = t2;
    }
}

__global__ void k_bnfin(int N)
{
    int c = threadIdx.x;
    float s = 0.f, s2 = 0.f;
    for (int b = 0; b < 64; b++) { s += g_part[b * 128 + c]; s2 += g_part[b * 128 + 64 + c]; }
    float m = s / (float)N;
    float v = s2 / (float)N - m * m;
    g_stats[c] = m;
    g_stats[64 + c] = rsqrtf(v + 1e-4f);
}

__global__ void k_bnapply(const float* __restrict__ X, const float* __restrict__ Res,
                          const float* __restrict__ gamma, const float* __restrict__ beta,
                          float* __restrict__ Out, int N, int mode)
{
    int i = blockIdx.x * blockDim.x + threadIdx.x;
    if (i < N * 64) {
        int c = i & 63;
        float y = (X[i] - g_stats[c]) * g_stats[64 + c] * gamma[c] + beta[c];
        if (mode == 1) y += Res[i];
        if (mode == 2) y = fmaxf(y, 0.f);
        Out[i] = y;
    }
}

__global__ void k_add(const float* __restrict__ X, const float* __restrict__ Y,
                      float* __restrict__ Out, int N)
{
    int i = blockIdx.x * blockDim.x + threadIdx.x;
    if (i < N * 64) Out[i] = X[i] + Y[i];
}

// ---------------------------------------------------------------------------
extern "C" void kernel_launch(void* const* d_in, const int* in_sizes, int n_in,
                              void* d_out, int out_size)
{
    const float* xdec  = (const float*)d_in[0];
    const float* xenc  = (const float*)d_in[1];
    const float* Wp1   = (const float*)d_in[2];
    const float* Wq    = (const float*)d_in[3];
    const float* Wk    = (const float*)d_in[4];
    const float* Wv    = (const float*)d_in[5];
    const float* Wt    = (const float*)d_in[6];
    const float* Wq1   = (const float*)d_in[7];
    const float* Wk1   = (const float*)d_in[8];
    const float* Wv1   = (const float*)d_in[9];
    const float* Wdown = (const float*)d_in[10];
    const float* W3t   = (const float*)d_in[11];
    const float* W3a   = (const float*)d_in[12];
    const float* W3b   = (const float*)d_in[13];
    const float* gam   = (const float*)d_in[14];
    const float* bet   = (const float*)d_in[15];
    const int* nbr     = (const int*)d_in[16];
    const int* kv_nbr  = (const int*)d_in[17];
    const int* pad_idx = (const int*)d_in[18];

    int nd = in_sizes[0] / 64;
    int ne = in_sizes[1] / 64;
    int lq = in_sizes[18] / NBATCH;
    float* out = (float*)d_out;

    float* base = nullptr;
    cudaGetSymbolAddress((void**)&base, g_buf);
    float* B[15];
    for (int i = 0; i < 15; i++) B[i] = base + (size_t)i * CELLS;

    __nv_bfloat16* bfb = nullptr;
    cudaGetSymbolAddress((void**)&bfb, g_bf);
    __nv_bfloat16* BF[6];
    for (int i = 0; i < 6; i++) BF[i] = bfb + (size_t)i * PADCELLS;

    cudaFuncSetAttribute(k_flash_bf, cudaFuncAttributeMaxDynamicSharedMemorySize, FLASH_SMEM_BF);

    dim3 thr(256);
    int gbd = (nd + 63) / 64;
    int gbe = (ne + 63) / 64;
    int gel = (nd * 64 + 255) / 256;

    // Stage 1
    k_gemm64<<<gbd, thr>>>(xdec, Wp1, B[0], nd, nullptr, nullptr);        // xd0
    k_gemm64<<<gbd, thr>>>(B[0], Wq, B[1], nd, BF[0], BF[1]);             // q (+bf)
    k_gemm64<<<gbe, thr>>>(xenc, Wk, B[2], ne, BF[2], BF[3]);             // ke (+bf)
    k_gemm64<<<gbe, thr>>>(xenc, Wv, B[3], ne, BF[4], BF[5]);             // ve (+bf)
    k_prep<<<1, thr>>>(pad_idx, nd, ne, lq);
    k_flash_bf<<<gbd, thr, FLASH_SMEM_BF>>>(BF[0], BF[1], BF[2], BF[3], BF[4], BF[5], B[4], 0, gbd);
    k_gemm64<<<gbd, thr>>>(B[4], Wt, B[5], nd, nullptr, nullptr);         // xr
    k_bnstats<<<64, thr>>>(B[5], nd);
    k_bnfin<<<1, 64>>>(nd);
    k_bnapply<<<gel, thr>>>(B[5], B[0], gam + 0, bet + 0, B[6], nd, 1);   // xd

    // Stage 2
    k_gemm64<<<gbd, thr>>>(B[6], Wq1, B[7], nd, BF[0], BF[1]);            // q1 (+bf)
    k_gconv<<<gbd, thr>>>(B[7], kv_nbr, 8, Wdown, B[8], nd);
    k_bnstats<<<64, thr>>>(B[8], nd);
    k_bnfin<<<1, 64>>>(nd);
    k_bnapply<<<gel, thr>>>(B[8], B[8], gam + 64, bet + 64, B[9], nd, 0); // kv
    k_gemm64<<<gbd, thr>>>(B[9], Wk1, B[10], nd, BF[2], BF[3]);           // k1 (+bf)
    k_gemm64<<<gbd, thr>>>(B[9], Wv1, B[11], nd, BF[4], BF[5]);           // v1 (+bf)
    int tps = (lq + 63) / 64;
    k_flash_bf<<<NBATCH * tps, thr, FLASH_SMEM_BF>>>(BF[0], BF[1], BF[2], BF[3], BF[4], BF[5], B[12], 1, tps);
    k_gconv<<<gbd, thr>>>(B[12], nbr, 27, W3t, B[13], nd);
    k_bnstats<<<64, thr>>>(B[13], nd);
    k_bnfin<<<1, 64>>>(nd);
    k_bnapply<<<gel, thr>>>(B[13], B[6], gam + 128, bet + 128, B[14], nd, 1); // xd2

    // Res block
    k_bnstats<<<64, thr>>>(B[14], nd);
    k_bnfin<<<1, 64>>>(nd);
    k_bnapply<<<gel, thr>>>(B[14], B[14], gam + 192, bet + 192, B[0], nd, 2);
    k_gconv<<<gbd, thr>>>(B[0], nbr, 27, W3a, B[1], nd);
    k_bnstats<<<64, thr>>>(B[1], nd);
    k_bnfin<<<1, 64>>>(nd);
    k_bnapply<<<gel, thr>>>(B[1], B[1], gam + 256, bet + 256, B[2], nd, 2);
    k_gconv<<<gbd, thr>>>(B[2], nbr, 27, W3b, B[3], nd);
    k_add<<<gel, thr>>>(B[14], B[3], B[4], nd);
    k_bnstats<<<64, thr>>>(B[4], nd);
    k_bnfin<<<1, 64>>>(nd);
    k_bnapply<<<gel, thr>>>(B[4], B[4], gam + 320, bet + 320, out, nd, 2);
}

// round 6
// speedup vs baseline: 2.8507x; 1.1634x over previous
#include <cuda_runtime.h>
#include <cuda_bf16.h>
#include <math.h>

#define NF 64
#define NBATCH 8
#define NDMAX 12288
#define CELLS (NDMAX * NF)
#define PADCELLS (CELLS + 64 * 64)

// Static scratch (no runtime allocation). Zero-initialized; bf16 pad rows are
// never written so they remain zero across calls.
__device__ float g_buf[15][CELLS];
__device__ float g_po[2][CELLS];          // split-K partial O
__device__ float g_pms[2][2 * NDMAX];     // split-K per-row (m, s)
__device__ __nv_bfloat16 g_bf[6][PADCELLS];  // Qhi Qlo Khi Klo Vhi Vlo
__device__ float g_stats[128];
__device__ float g_part[64 * 128];
__device__ int   g_seg[64];

// ---------------------------------------------------------------------------
// Helpers
// ---------------------------------------------------------------------------
__device__ __forceinline__ int SW(int r, int cb) {          // swizzled byte offset, 128B pitch
    return r * 128 + (cb ^ ((r & 7) << 4));
}
__device__ __forceinline__ unsigned smu32(const void* p) {
    return (unsigned)__cvta_generic_to_shared(p);
}
__device__ __forceinline__ void cpa16(unsigned dst, const void* src) {
    asm volatile("cp.async.ca.shared.global [%0], [%1], 16;" :: "r"(dst), "l"(src) : "memory");
}
#define CP_COMMIT() asm volatile("cp.async.commit_group;" ::: "memory")
#define CP_WAIT1()  asm volatile("cp.async.wait_group 1;" ::: "memory")

__device__ __forceinline__ void ldsm4(unsigned r[4], unsigned a) {
    asm volatile("ldmatrix.sync.aligned.m8n8.x4.shared.b16 {%0,%1,%2,%3}, [%4];"
                 : "=r"(r[0]), "=r"(r[1]), "=r"(r[2]), "=r"(r[3]) : "r"(a));
}
__device__ __forceinline__ void ldsm4t(unsigned r[4], unsigned a) {
    asm volatile("ldmatrix.sync.aligned.m8n8.x4.trans.shared.b16 {%0,%1,%2,%3}, [%4];"
                 : "=r"(r[0]), "=r"(r[1]), "=r"(r[2]), "=r"(r[3]) : "r"(a));
}
__device__ __forceinline__ void mma_bf(float c[4], const unsigned a[4], const unsigned b[2]) {
    asm volatile(
        "mma.sync.aligned.m16n8k16.row.col.f32.bf16.bf16.f32 "
        "{%0,%1,%2,%3}, {%4,%5,%6,%7}, {%8,%9}, {%0,%1,%2,%3};"
        : "+f"(c[0]), "+f"(c[1]), "+f"(c[2]), "+f"(c[3])
        : "r"(a[0]), "r"(a[1]), "r"(a[2]), "r"(a[3]), "r"(b[0]), "r"(b[1]));
}

// ---------------------------------------------------------------------------
// GEMM: C[N,64] = A[N,64] @ W[64,64]; optional fused fp32->bf16 hi/lo output.
// ---------------------------------------------------------------------------
__global__ void __launch_bounds__(256) k_gemm64(
    const float* __restrict__ A, const float* __restrict__ W,
    float* __restrict__ C, int N,
    __nv_bfloat16* __restrict__ hi, __nv_bfloat16* __restrict__ lo)
{
    __shared__ float sW[64 * 64];
    __shared__ float sA[64 * 65];
    int t = threadIdx.x;
    int row0 = blockIdx.x * 64;
    for (int i = t; i < 4096; i += 256) {
        sW[i] = W[i];
        int r = i >> 6, c = i & 63;
        int gr = row0 + r;
        sA[r * 65 + c] = (gr < N) ? A[gr * 64 + c] : 0.f;
    }
    __syncthreads();
    int a = t >> 4, b = t & 15;
    float4 acc[4];
#pragma unroll
    for (int i = 0; i < 4; i++) acc[i] = make_float4(0.f, 0.f, 0.f, 0.f);
#pragma unroll 8
    for (int m = 0; m < 64; m++) {
        float4 w = *reinterpret_cast<const float4*>(&sW[m * 64 + 4 * b]);
#pragma unroll
        for (int i = 0; i < 4; i++) {
            float av = sA[(a + 16 * i) * 65 + m];
            acc[i].x += av * w.x; acc[i].y += av * w.y;
            acc[i].z += av * w.z; acc[i].w += av * w.w;
        }
    }
#pragma unroll
    for (int i = 0; i < 4; i++) {
        int gr = row0 + a + 16 * i;
        if (gr < N) {
            *reinterpret_cast<float4*>(&C[gr * 64 + 4 * b]) = acc[i];
            if (hi) {
                float v[4] = { acc[i].x, acc[i].y, acc[i].z, acc[i].w };
                unsigned short hbits[4], lbits[4];
#pragma unroll
                for (int j = 0; j < 4; j++) {
                    __nv_bfloat16 h = __float2bfloat16(v[j]);
                    hbits[j] = __bfloat16_as_ushort(h);
                    lbits[j] = __bfloat16_as_ushort(__float2bfloat16(v[j] - __bfloat162float(h)));
                }
                uint2 hp, lp;
                hp.x = (unsigned)hbits[0] | ((unsigned)hbits[1] << 16);
                hp.y = (unsigned)hbits[2] | ((unsigned)hbits[3] << 16);
                lp.x = (unsigned)lbits[0] | ((unsigned)lbits[1] << 16);
                lp.y = (unsigned)lbits[2] | ((unsigned)lbits[3] << 16);
                *reinterpret_cast<uint2*>(&hi[(size_t)gr * 64 + 4 * b]) = hp;
                *reinterpret_cast<uint2*>(&lo[(size_t)gr * 64 + 4 * b]) = lp;
            }
        }
    }
}

// ---------------------------------------------------------------------------
// Rulebook sparse conv with block-wide empty-tap skipping.
// ---------------------------------------------------------------------------
__global__ void __launch_bounds__(256) k_gconv(
    const float* __restrict__ F, const int* __restrict__ idx, int K,
    const float* __restrict__ W, float* __restrict__ out, int N)
{
    __shared__ float sW[64 * 64];
    __shared__ float sF[64 * 68];
    __shared__ int   sIdx[64];
    int t = threadIdx.x;
    int row0 = blockIdx.x * 64;
    int a = t >> 4, b = t & 15;
    float4 acc[4];
#pragma unroll
    for (int i = 0; i < 4; i++) acc[i] = make_float4(0.f, 0.f, 0.f, 0.f);

    for (int k = 0; k < K; k++) {
        __syncthreads();
        int myvalid = 0;
        if (t < 64) {
            int gr = row0 + t;
            int j = (gr < N) ? idx[gr * K + k] : -1;
            sIdx[t] = j;
            myvalid = (j >= 0);
        }
        if (!__syncthreads_or(myvalid)) continue;
        for (int i = t; i < 4096; i += 256) sW[i] = W[k * 4096 + i];
        {
            int rr = t >> 2;
            int j = sIdx[rr];
            if (j >= 0) {
                int c0 = (t & 3) * 16;
#pragma unroll
                for (int q4 = 0; q4 < 4; q4++)
                    *reinterpret_cast<float4*>(&sF[rr * 68 + c0 + 4 * q4]) =
                        *reinterpret_cast<const float4*>(&F[j * 64 + c0 + 4 * q4]);
            }
        }
        __syncthreads();
#pragma unroll
        for (int i = 0; i < 4; i++) {
            int r = a + 16 * i;
            if (sIdx[r] >= 0) {
#pragma unroll 8
                for (int m = 0; m < 64; m++) {
                    float av = sF[r * 68 + m];
                    float4 w = *reinterpret_cast<const float4*>(&sW[m * 64 + 4 * b]);
                    acc[i].x += av * w.x; acc[i].y += av * w.y;
                    acc[i].z += av * w.z; acc[i].w += av * w.w;
                }
            }
        }
    }
#pragma unroll
    for (int i = 0; i < 4; i++) {
        int gr = row0 + a + 16 * i;
        if (gr < N) *reinterpret_cast<float4*>(&out[gr * 64 + 4 * b]) = acc[i];
    }
}

// ---------------------------------------------------------------------------
// Segment prep
// ---------------------------------------------------------------------------
__global__ void k_prep(const int* __restrict__ pad_idx, int nd, int ne, int lq)
{
    int t = threadIdx.x;
    int w = t >> 5, lane = t & 31;
    if (w < NBATCH) {
        int cnt = 0;
        for (int l = lane; l < lq; l += 32)
            cnt += (pad_idx[w * lq + l] >= 0) ? 1 : 0;
#pragma unroll
        for (int o = 16; o > 0; o >>= 1) cnt += __shfl_xor_sync(0xffffffffu, cnt, o);
        if (lane == 0) {
            int s = pad_idx[w * lq];
            g_seg[(1 + w) * 4 + 0] = s;
            g_seg[(1 + w) * 4 + 1] = cnt;
            g_seg[(1 + w) * 4 + 2] = s;
            g_seg[(1 + w) * 4 + 3] = cnt;
        }
    }
    if (t == 0) { g_seg[0] = 0; g_seg[1] = nd; g_seg[2] = 0; g_seg[3] = ne; }
}

// ---------------------------------------------------------------------------
// bf16 3x tensor-core flash attention; warp-local softmax, optional split-K.
// ksplit==1: normalized write to O. ksplit==2: unnormalized partial to
// pO[si] plus per-row (m,s) to pMS[si]; k_fmerge combines.
// ---------------------------------------------------------------------------
#define FLASH_SMEM_BF (65536 + 16384 + 16384 + 1024)

__global__ void __launch_bounds__(256, 2) k_flash_bf(
    const __nv_bfloat16* __restrict__ gQh, const __nv_bfloat16* __restrict__ gQl,
    const __nv_bfloat16* __restrict__ gKh, const __nv_bfloat16* __restrict__ gKl,
    const __nv_bfloat16* __restrict__ gVh, const __nv_bfloat16* __restrict__ gVl,
    float* __restrict__ O, int seg_off, int tiles_per_seg, int ksplit,
    float* __restrict__ pO, float* __restrict__ pMS)
{
    extern __shared__ char smc[];
    char* sKV = smc;
    char* sQ  = smc + 65536;
    char* sP  = smc + 81920;
    float* red = (float*)(smc + 98304);

    int bx = blockIdx.x;
    int segi = bx / tiles_per_seg;
    int traw = bx - segi * tiles_per_seg;
    int tile = traw / ksplit;
    int si = traw - tile * ksplit;
    int seg = seg_off + segi;
    int q0 = g_seg[seg * 4 + 0], nq = g_seg[seg * 4 + 1];
    int k0 = g_seg[seg * 4 + 2], nk = g_seg[seg * 4 + 3];
    if (tile * 64 >= nq) return;
    int qbase = q0 + tile * 64;
    int nqv = min(64, nq - tile * 64);

    // key-range for this split
    int nkt_tot = (nk + 63) >> 6;
    int per = (nkt_tot + ksplit - 1) / ksplit;
    int kt0 = si * per;
    int kt1 = min(nkt_tot, kt0 + per);
    int nkt = kt1 - kt0;

    int t = threadIdx.x;
    int w = t >> 5, lane = t & 31;
    int qg = w & 3, h = w >> 2;
    int quad = lane >> 2, qi = lane & 3;
    int r0 = qg * 16 + quad, r1 = r0 + 8;

    float oc[32];
#pragma unroll
    for (int i = 0; i < 32; i++) oc[i] = 0.f;
    float rmax0 = -1e30f, rmax1 = -1e30f, rsum0 = 0.f, rsum1 = 0.f;

    if (nkt > 0) {
        // prologue: Q + first KV tile
        {
#pragma unroll
            for (int j = 0; j < 2; j++) {
                int chunk = t + 256 * j;
                int row = chunk >> 3, jj = chunk & 7;
                cpa16(smu32(sQ + SW(row, jj << 4)),        gQh + (size_t)(qbase + row) * 64 + jj * 8);
                cpa16(smu32(sQ + 8192 + SW(row, jj << 4)), gQl + (size_t)(qbase + row) * 64 + jj * 8);
            }
            const __nv_bfloat16* gs[4] = { gKh, gKl, gVh, gVl };
            int kb0 = k0 + kt0 * 64;
#pragma unroll
            for (int a = 0; a < 4; a++)
#pragma unroll
                for (int j = 0; j < 2; j++) {
                    int chunk = t + 256 * j;
                    int row = chunk >> 3, jj = chunk & 7;
                    cpa16(smu32(sKV + a * 8192 + SW(row, jj << 4)),
                          gs[a] + (size_t)(kb0 + row) * 64 + jj * 8);
                }
        }
        CP_COMMIT();

        for (int kt = 0; kt < nkt; kt++) {
            char* sb = sKV + (kt & 1) * 32768;
            __syncthreads();
            if (kt + 1 < nkt) {
                char* nb = sKV + ((kt + 1) & 1) * 32768;
                int kb = k0 + (kt0 + kt + 1) * 64;
                const __nv_bfloat16* gs[4] = { gKh, gKl, gVh, gVl };
#pragma unroll
                for (int a = 0; a < 4; a++)
#pragma unroll
                    for (int j = 0; j < 2; j++) {
                        int chunk = t + 256 * j;
                        int row = chunk >> 3, jj = chunk & 7;
                        cpa16(smu32(nb + a * 8192 + SW(row, jj << 4)),
                              gs[a] + (size_t)(kb + row) * 64 + jj * 8);
                    }
            }
            CP_COMMIT();
            CP_WAIT1();
            __syncthreads();

            int nkv = min(64, nk - (kt0 + kt) * 64);
            char* sKh = sb;
            char* sKl = sb + 8192;
            char* sVh = sb + 16384;
            char* sVl = sb + 24576;

            // ---- S = Q K^T ----
            float c4[4][4];
#pragma unroll
            for (int nt = 0; nt < 4; nt++)
#pragma unroll
                for (int k = 0; k < 4; k++) c4[nt][k] = 0.f;

#pragma unroll
            for (int ch = 0; ch < 4; ch++) {
                unsigned qh[4], ql[4];
                {
                    int r = qg * 16 + (lane & 7) + ((lane & 8) ? 8 : 0);
                    int cb = ch * 32 + ((lane & 16) ? 16 : 0);
                    ldsm4(qh, smu32(sQ + SW(r, cb)));
                    ldsm4(ql, smu32(sQ + 8192 + SW(r, cb)));
                }
                unsigned kh[8], kl[8];
                {
                    int r = 32 * h + (lane & 7) + ((lane & 16) ? 8 : 0);
                    int cb = ch * 32 + ((lane & 8) ? 16 : 0);
                    ldsm4(kh,     smu32(sKh + SW(r, cb)));
                    ldsm4(kh + 4, smu32(sKh + SW(r + 16, cb)));
                    ldsm4(kl,     smu32(sKl + SW(r, cb)));
                    ldsm4(kl + 4, smu32(sKl + SW(r + 16, cb)));
                }
#pragma unroll
                for (int nt = 0; nt < 4; nt++) {
                    mma_bf(c4[nt], qh, &kh[2 * nt]);
                    mma_bf(c4[nt], qh, &kl[2 * nt]);
                    mma_bf(c4[nt], ql, &kh[2 * nt]);
                }
            }

            if (nkv < 64) {
#pragma unroll
                for (int nt = 0; nt < 4; nt++) {
                    int colb = 32 * h + 8 * nt + 2 * qi;
#pragma unroll
                    for (int k = 0; k < 4; k++)
                        if (colb + (k & 1) >= nkv) c4[nt][k] = -1e30f;
                }
            }

            // ---- warp-local online softmax ----
            float mx0 = -1e30f, mx1 = -1e30f;
#pragma unroll
            for (int nt = 0; nt < 4; nt++) {
                mx0 = fmaxf(mx0, fmaxf(c4[nt][0], c4[nt][1]));
                mx1 = fmaxf(mx1, fmaxf(c4[nt][2], c4[nt][3]));
            }
            mx0 = fmaxf(mx0, __shfl_xor_sync(0xffffffffu, mx0, 1));
            mx0 = fmaxf(mx0, __shfl_xor_sync(0xffffffffu, mx0, 2));
            mx1 = fmaxf(mx1, __shfl_xor_sync(0xffffffffu, mx1, 1));
            mx1 = fmaxf(mx1, __shfl_xor_sync(0xffffffffu, mx1, 2));
            float mnew0 = fmaxf(rmax0, mx0);
            float mnew1 = fmaxf(rmax1, mx1);
            float corr0 = __expf(rmax0 - mnew0);
            float corr1 = __expf(rmax1 - mnew1);
            rmax0 = mnew0; rmax1 = mnew1;

            float ps0 = 0.f, ps1 = 0.f;
#pragma unroll
            for (int nt = 0; nt < 4; nt++) {
                int colcb = (32 * h + 8 * nt + 2 * qi) * 2;
                float p00 = __expf(c4[nt][0] - mnew0);
                float p01 = __expf(c4[nt][1] - mnew0);
                float p10 = __expf(c4[nt][2] - mnew1);
                float p11 = __expf(c4[nt][3] - mnew1);
                ps0 += p00 + p01; ps1 += p10 + p11;
                __nv_bfloat16 h00 = __float2bfloat16(p00), h01 = __float2bfloat16(p01);
                __nv_bfloat16 h10 = __float2bfloat16(p10), h11 = __float2bfloat16(p11);
                unsigned uh0 = (unsigned)__bfloat16_as_ushort(h00) | ((unsigned)__bfloat16_as_ushort(h01) << 16);
                unsigned uh1 = (unsigned)__bfloat16_as_ushort(h10) | ((unsigned)__bfloat16_as_ushort(h11) << 16);
                __nv_bfloat16 l00 = __float2bfloat16(p00 - __bfloat162float(h00));
                __nv_bfloat16 l01 = __float2bfloat16(p01 - __bfloat162float(h01));
                __nv_bfloat16 l10 = __float2bfloat16(p10 - __bfloat162float(h10));
                __nv_bfloat16 l11 = __float2bfloat16(p11 - __bfloat162float(h11));
                unsigned ul0 = (unsigned)__bfloat16_as_ushort(l00) | ((unsigned)__bfloat16_as_ushort(l01) << 16);
                unsigned ul1 = (unsigned)__bfloat16_as_ushort(l10) | ((unsigned)__bfloat16_as_ushort(l11) << 16);
                *(unsigned*)(sP + SW(r0, colcb)) = uh0;
                *(unsigned*)(sP + SW(r1, colcb)) = uh1;
                *(unsigned*)(sP + 8192 + SW(r0, colcb)) = ul0;
                *(unsigned*)(sP + 8192 + SW(r1, colcb)) = ul1;
            }
            ps0 += __shfl_xor_sync(0xffffffffu, ps0, 1);
            ps0 += __shfl_xor_sync(0xffffffffu, ps0, 2);
            ps1 += __shfl_xor_sync(0xffffffffu, ps1, 1);
            ps1 += __shfl_xor_sync(0xffffffffu, ps1, 2);
            rsum0 = rsum0 * corr0 + ps0;
            rsum1 = rsum1 * corr1 + ps1;
#pragma unroll
            for (int nt = 0; nt < 8; nt++) {
                oc[nt * 4 + 0] *= corr0; oc[nt * 4 + 1] *= corr0;
                oc[nt * 4 + 2] *= corr1; oc[nt * 4 + 3] *= corr1;
            }
            __syncwarp();

            // ---- O += P V ----
#pragma unroll
            for (int ck = 0; ck < 2; ck++) {
                int key0 = 32 * h + 16 * ck;
                unsigned ph[4], pl[4];
                {
                    int r = qg * 16 + (lane & 7) + ((lane & 8) ? 8 : 0);
                    int cb = key0 * 2 + ((lane & 16) ? 16 : 0);
                    ldsm4(ph, smu32(sP + SW(r, cb)));
                    ldsm4(pl, smu32(sP + 8192 + SW(r, cb)));
                }
#pragma unroll
                for (int cc = 0; cc < 4; cc++) {
                    unsigned vh[4], vl[4];
                    {
                        int r = key0 + (lane & 7) + ((lane & 8) ? 8 : 0);
                        int cb = cc * 32 + ((lane & 16) ? 16 : 0);
                        ldsm4t(vh, smu32(sVh + SW(r, cb)));
                        ldsm4t(vl, smu32(sVl + SW(r, cb)));
                    }
                    mma_bf(&oc[(2 * cc) * 4], ph, &vh[0]);
                    mma_bf(&oc[(2 * cc) * 4], ph, &vl[0]);
                    mma_bf(&oc[(2 * cc) * 4], pl, &vh[0]);
                    mma_bf(&oc[(2 * cc + 1) * 4], ph, &vh[2]);
                    mma_bf(&oc[(2 * cc + 1) * 4], ph, &vl[2]);
                    mma_bf(&oc[(2 * cc + 1) * 4], pl, &vh[2]);
                }
            }
        }
    }

    // ---- merge halves ----
    if (qi == 0) {
        red[h * 64 + r0] = rmax0;       red[h * 64 + r1] = rmax1;
        red[128 + h * 64 + r0] = rsum0; red[128 + h * 64 + r1] = rsum1;
    }
    __syncthreads();

    float m0a = red[r0], m1a = red[64 + r0];
    float mma_ = fmaxf(m0a, m1a);
    float fh_a = __expf(((h == 0) ? m0a : m1a) - mma_);
    float stot_a = red[128 + r0] * __expf(m0a - mma_) + red[192 + r0] * __expf(m1a - mma_);
    float m0b = red[r1], m1b = red[64 + r1];
    float mmb_ = fmaxf(m0b, m1b);
    float fh_b = __expf(((h == 0) ? m0b : m1b) - mmb_);
    float stot_b = red[128 + r1] * __expf(m0b - mmb_) + red[192 + r1] * __expf(m1b - mmb_);

    float* sO = (float*)sP;
    if (h == 1) {
#pragma unroll
        for (int nt = 0; nt < 8; nt++) {
            int colb = 8 * nt + 2 * qi;
            sO[r0 * 64 + colb]     = oc[nt * 4 + 0] * fh_a;
            sO[r0 * 64 + colb + 1] = oc[nt * 4 + 1] * fh_a;
            sO[r1 * 64 + colb]     = oc[nt * 4 + 2] * fh_b;
            sO[r1 * 64 + colb + 1] = oc[nt * 4 + 3] * fh_b;
        }
    }
    __syncthreads();
    if (h == 0) {
        if (ksplit == 1) {
            float inva = fh_a / stot_a, invb = fh_b / stot_b;
            float ja = 1.f / stot_a, jb = 1.f / stot_b;
#pragma unroll
            for (int nt = 0; nt < 8; nt++) {
                int colb = 8 * nt + 2 * qi;
                if (r0 < nqv) {
                    O[(size_t)(qbase + r0) * 64 + colb]     = oc[nt * 4 + 0] * inva + sO[r0 * 64 + colb] * ja;
                    O[(size_t)(qbase + r0) * 64 + colb + 1] = oc[nt * 4 + 1] * inva + sO[r0 * 64 + colb + 1] * ja;
                }
                if (r1 < nqv) {
                    O[(size_t)(qbase + r1) * 64 + colb]     = oc[nt * 4 + 2] * invb + sO[r1 * 64 + colb] * jb;
                    O[(size_t)(qbase + r1) * 64 + colb + 1] = oc[nt * 4 + 3] * invb + sO[r1 * 64 + colb + 1] * jb;
                }
            }
        } else {
            float* pOo = pO + (size_t)si * CELLS;
            float* pM  = pMS + (size_t)si * 2 * NDMAX;
#pragma unroll
            for (int nt = 0; nt < 8; nt++) {
                int colb = 8 * nt + 2 * qi;
                if (r0 < nqv) {
                    pOo[(size_t)(qbase + r0) * 64 + colb]     = oc[nt * 4 + 0] * fh_a + sO[r0 * 64 + colb];
                    pOo[(size_t)(qbase + r0) * 64 + colb + 1] = oc[nt * 4 + 1] * fh_a + sO[r0 * 64 + colb + 1];
                }
                if (r1 < nqv) {
                    pOo[(size_t)(qbase + r1) * 64 + colb]     = oc[nt * 4 + 2] * fh_b + sO[r1 * 64 + colb];
                    pOo[(size_t)(qbase + r1) * 64 + colb + 1] = oc[nt * 4 + 3] * fh_b + sO[r1 * 64 + colb + 1];
                }
            }
            if (qi == 0) {
                if (r0 < nqv) { pM[(qbase + r0) * 2] = mma_; pM[(qbase + r0) * 2 + 1] = stot_a; }
                if (r1 < nqv) { pM[(qbase + r1) * 2] = mmb_; pM[(qbase + r1) * 2 + 1] = stot_b; }
            }
        }
    }
}

// ---------------------------------------------------------------------------
// Split-K merge: O = (O0 e^{m0-m} + O1 e^{m1-m}) / (s0 e^{m0-m} + s1 e^{m1-m})
// ---------------------------------------------------------------------------
__global__ void k_fmerge(const float* __restrict__ pO0, const float* __restrict__ pO1,
                         const float* __restrict__ pM0, const float* __restrict__ pM1,
                         float* __restrict__ O, int N)
{
    int i = blockIdx.x * blockDim.x + threadIdx.x;
    if (i < N * 64) {
        int r = i >> 6;
        float m0 = pM0[r * 2], s0 = pM0[r * 2 + 1];
        float m1 = pM1[r * 2], s1 = pM1[r * 2 + 1];
        float m = fmaxf(m0, m1);
        float e0 = __expf(m0 - m), e1 = __expf(m1 - m);
        O[i] = (pO0[i] * e0 + pO1[i] * e1) / (s0 * e0 + s1 * e1);
    }
}

// ---------------------------------------------------------------------------
// BatchNorm pieces
// ---------------------------------------------------------------------------
__global__ void k_bnstats(const float* __restrict__ X, int N)
{
    __shared__ float sh[2][4][64];
    int c = threadIdx.x & 63, rg = threadIdx.x >> 6;
    float s = 0.f, s2 = 0.f;
    for (int r = blockIdx.x * 4 + rg; r < N; r += 256) {
        float v = X[r * 64 + c];
        s += v; s2 += v * v;
    }
    sh[0][rg][c] = s; sh[1][rg][c] = s2;
    __syncthreads();
    if (threadIdx.x < 64) {
        float ts = sh[0][0][c] + sh[0][1][c] + sh[0][2][c] + sh[0][3][c];
        float t2 = sh[1][0][c] + sh[1][1][c] + sh[1][2][c] + sh[1][3][c];
        g_part[blockIdx.x * 128 + c] = ts;
        g_part[blockIdx.x * 128 + 64 + c] = t2;
    }
}

// fused: S = X + Y (written), stats of S
__global__ void k_bnstats_add(const float* __restrict__ X, const float* __restrict__ Y,
                              float* __restrict__ S, int N)
{
    __shared__ float sh[2][4][64];
    int c = threadIdx.x & 63, rg = threadIdx.x >> 6;
    float s = 0.f, s2 = 0.f;
    for (int r = blockIdx.x * 4 + rg; r < N; r += 256) {
        float v = X[r * 64 + c] + Y[r * 64 + c];
        S[r * 64 + c] = v;
        s += v; s2 += v * v;
    }
    sh[0][rg][c] = s; sh[1][rg][c] = s2;
    __syncthreads();
    if (threadIdx.x < 64) {
        float ts = sh[0][0][c] + sh[0][1][c] + sh[0][2][c] + sh[0][3][c];
        float t2 = sh[1][0][c] + sh[1][1][c] + sh[1][2][c] + sh[1][3][c];
        g_part[blockIdx.x * 128 + c] = ts;
        g_part[blockIdx.x * 128 + 64 + c] = t2;
    }
}

__global__ void k_bnfin(int N)
{
    int c = threadIdx.x;
    float s = 0.f, s2 = 0.f;
    for (int b = 0; b < 64; b++) { s += g_part[b * 128 + c]; s2 += g_part[b * 128 + 64 + c]; }
    float m = s / (float)N;
    float v = s2 / (float)N - m * m;
    g_stats[c] = m;
    g_stats[64 + c] = rsqrtf(v + 1e-4f);
}

__global__ void k_bnapply(const float* __restrict__ X, const float* __restrict__ Res,
                          const float* __restrict__ gamma, const float* __restrict__ beta,
                          float* __restrict__ Out, int N, int mode)
{
    int i = blockIdx.x * blockDim.x + threadIdx.x;
    if (i < N * 64) {
        int c = i & 63;
        float y = (X[i] - g_stats[c]) * g_stats[64 + c] * gamma[c] + beta[c];
        if (mode == 1) y += Res[i];
        if (mode == 2) y = fmaxf(y, 0.f);
        Out[i] = y;
    }
}

// ---------------------------------------------------------------------------
extern "C" void kernel_launch(void* const* d_in, const int* in_sizes, int n_in,
                              void* d_out, int out_size)
{
    const float* xdec  = (const float*)d_in[0];
    const float* xenc  = (const float*)d_in[1];
    const float* Wp1   = (const float*)d_in[2];
    const float* Wq    = (const float*)d_in[3];
    const float* Wk    = (const float*)d_in[4];
    const float* Wv    = (const float*)d_in[5];
    const float* Wt    = (const float*)d_in[6];
    const float* Wq1   = (const float*)d_in[7];
    const float* Wk1   = (const float*)d_in[8];
    const float* Wv1   = (const float*)d_in[9];
    const float* Wdown = (const float*)d_in[10];
    const float* W3t   = (const float*)d_in[11];
    const float* W3a   = (const float*)d_in[12];
    const float* W3b   = (const float*)d_in[13];
    const float* gam   = (const float*)d_in[14];
    const float* bet   = (const float*)d_in[15];
    const int* nbr     = (const int*)d_in[16];
    const int* kv_nbr  = (const int*)d_in[17];
    const int* pad_idx = (const int*)d_in[18];

    int nd = in_sizes[0] / 64;
    int ne = in_sizes[1] / 64;
    int lq = in_sizes[18] / NBATCH;
    float* out = (float*)d_out;

    float* base = nullptr;
    cudaGetSymbolAddress((void**)&base, g_buf);
    float* B[15];
    for (int i = 0; i < 15; i++) B[i] = base + (size_t)i * CELLS;

    float* pob = nullptr;
    cudaGetSymbolAddress((void**)&pob, g_po);
    float* pmsb = nullptr;
    cudaGetSymbolAddress((void**)&pmsb, g_pms);

    __nv_bfloat16* bfb = nullptr;
    cudaGetSymbolAddress((void**)&bfb, g_bf);
    __nv_bfloat16* BF[6];
    for (int i = 0; i < 6; i++) BF[i] = bfb + (size_t)i * PADCELLS;

    cudaFuncSetAttribute(k_flash_bf, cudaFuncAttributeMaxDynamicSharedMemorySize, FLASH_SMEM_BF);

    dim3 thr(256);
    int gbd = (nd + 63) / 64;
    int gbe = (ne + 63) / 64;
    int gel = (nd * 64 + 255) / 256;

    // Stage 1
    k_gemm64<<<gbd, thr>>>(xdec, Wp1, B[0], nd, nullptr, nullptr);        // xd0
    k_gemm64<<<gbd, thr>>>(B[0], Wq, B[1], nd, BF[0], BF[1]);             // q (+bf)
    k_gemm64<<<gbe, thr>>>(xenc, Wk, B[2], ne, BF[2], BF[3]);             // ke (+bf)
    k_gemm64<<<gbe, thr>>>(xenc, Wv, B[3], ne, BF[4], BF[5]);             // ve (+bf)
    k_prep<<<1, thr>>>(pad_idx, nd, ne, lq);
    // split-K flash: 2 key halves per q-tile
    k_flash_bf<<<gbd * 2, thr, FLASH_SMEM_BF>>>(BF[0], BF[1], BF[2], BF[3], BF[4], BF[5],
                                                B[4], 0, gbd * 2, 2, pob, pmsb);
    k_fmerge<<<gel, thr>>>(pob, pob + CELLS, pmsb, pmsb + 2 * NDMAX, B[4], nd);
    k_gemm64<<<gbd, thr>>>(B[4], Wt, B[5], nd, nullptr, nullptr);         // xr
    k_bnstats<<<64, thr>>>(B[5], nd);
    k_bnfin<<<1, 64>>>(nd);
    k_bnapply<<<gel, thr>>>(B[5], B[0], gam + 0, bet + 0, B[6], nd, 1);   // xd

    // Stage 2
    k_gemm64<<<gbd, thr>>>(B[6], Wq1, B[7], nd, BF[0], BF[1]);            // q1 (+bf)
    k_gconv<<<gbd, thr>>>(B[7], kv_nbr, 8, Wdown, B[8], nd);
    k_bnstats<<<64, thr>>>(B[8], nd);
    k_bnfin<<<1, 64>>>(nd);
    k_bnapply<<<gel, thr>>>(B[8], B[8], gam + 64, bet + 64, B[9], nd, 0); // kv
    k_gemm64<<<gbd, thr>>>(B[9], Wk1, B[10], nd, BF[2], BF[3]);           // k1 (+bf)
    k_gemm64<<<gbd, thr>>>(B[9], Wv1, B[11], nd, BF[4], BF[5]);           // v1 (+bf)
    int tps = (lq + 63) / 64;
    k_flash_bf<<<NBATCH * tps, thr, FLASH_SMEM_BF>>>(BF[0], BF[1], BF[2], BF[3], BF[4], BF[5],
                                                     B[12], 1, tps, 1, nullptr, nullptr);
    k_gconv<<<gbd, thr>>>(B[12], nbr, 27, W3t, B[13], nd);
    k_bnstats<<<64, thr>>>(B[13], nd);
    k_bnfin<<<1, 64>>>(nd);
    k_bnapply<<<gel, thr>>>(B[13], B[6], gam + 128, bet + 128, B[14], nd, 1); // xd2

    // Res block
    k_bnstats<<<64, thr>>>(B[14], nd);
    k_bnfin<<<1, 64>>>(nd);
    k_bnapply<<<gel, thr>>>(B[14], B[14], gam + 192, bet + 192, B[0], nd, 2);
    k_gconv<<<gbd, thr>>>(B[0], nbr, 27, W3a, B[1], nd);
    k_bnstats<<<64, thr>>>(B[1], nd);
    k_bnfin<<<1, 64>>>(nd);
    k_bnapply<<<gel, thr>>>(B[1], B[1], gam + 256, bet + 256, B[2], nd, 2);
    k_gconv<<<gbd, thr>>>(B[2], nbr, 27, W3b, B[3], nd);
    k_bnstats_add<<<64, thr>>>(B[14], B[3], B[4], nd);
    k_bnfin<<<1, 64>>>(nd);
    k_bnapply<<<gel, thr>>>(B[4], B[4], gam + 320, bet + 320, out, nd, 2);
}

// round 7
// speedup vs baseline: 2.9406x; 1.0316x over previous
#include <cuda_runtime.h>
#include <cuda_bf16.h>
#include <math.h>

#define NF 64
#define NBATCH 8
#define NDMAX 12288
#define CELLS (NDMAX * NF)
#define PADCELLS (CELLS + 64 * 64)
#define KS 3

// Static scratch (no runtime allocation). Zero-initialized; bf16 pad rows are
// never written so they remain zero across calls.
__device__ float g_buf[15][CELLS];
__device__ float g_po[KS][CELLS];          // split-K partial O
__device__ float g_pms[KS][2 * NDMAX];     // split-K per-row (m, s)
__device__ __nv_bfloat16 g_bf[6][PADCELLS];  // Qhi Qlo Khi Klo Vhi Vlo
__device__ float g_stats[128];
__device__ float g_part[256 * 128];
__device__ int   g_seg[64];

// ---------------------------------------------------------------------------
// Helpers
// ---------------------------------------------------------------------------
__device__ __forceinline__ int SW(int r, int cb) {          // swizzled byte offset, 128B pitch
    return r * 128 + (cb ^ ((r & 7) << 4));
}
__device__ __forceinline__ unsigned smu32(const void* p) {
    return (unsigned)__cvta_generic_to_shared(p);
}
__device__ __forceinline__ void cpa16(unsigned dst, const void* src) {
    asm volatile("cp.async.ca.shared.global [%0], [%1], 16;" :: "r"(dst), "l"(src) : "memory");
}
#define CP_COMMIT() asm volatile("cp.async.commit_group;" ::: "memory")
#define CP_WAIT1()  asm volatile("cp.async.wait_group 1;" ::: "memory")

__device__ __forceinline__ void ldsm4(unsigned r[4], unsigned a) {
    asm volatile("ldmatrix.sync.aligned.m8n8.x4.shared.b16 {%0,%1,%2,%3}, [%4];"
                 : "=r"(r[0]), "=r"(r[1]), "=r"(r[2]), "=r"(r[3]) : "r"(a));
}
__device__ __forceinline__ void ldsm4t(unsigned r[4], unsigned a) {
    asm volatile("ldmatrix.sync.aligned.m8n8.x4.trans.shared.b16 {%0,%1,%2,%3}, [%4];"
                 : "=r"(r[0]), "=r"(r[1]), "=r"(r[2]), "=r"(r[3]) : "r"(a));
}
__device__ __forceinline__ void mma_bf(float c[4], const unsigned a[4], const unsigned b[2]) {
    asm volatile(
        "mma.sync.aligned.m16n8k16.row.col.f32.bf16.bf16.f32 "
        "{%0,%1,%2,%3}, {%4,%5,%6,%7}, {%8,%9}, {%0,%1,%2,%3};"
        : "+f"(c[0]), "+f"(c[1]), "+f"(c[2]), "+f"(c[3])
        : "r"(a[0]), "r"(a[1]), "r"(a[2]), "r"(a[3]), "r"(b[0]), "r"(b[1]));
}

// ---------------------------------------------------------------------------
// GEMM: C[N,64] = A[N,64] @ W[64,64]; optional fused fp32->bf16 hi/lo output.
// ---------------------------------------------------------------------------
__global__ void __launch_bounds__(256) k_gemm64(
    const float* __restrict__ A, const float* __restrict__ W,
    float* __restrict__ C, int N,
    __nv_bfloat16* __restrict__ hi, __nv_bfloat16* __restrict__ lo)
{
    __shared__ float sW[64 * 64];
    __shared__ float sA[64 * 65];
    int t = threadIdx.x;
    int row0 = blockIdx.x * 64;
    for (int i = t; i < 4096; i += 256) {
        sW[i] = W[i];
        int r = i >> 6, c = i & 63;
        int gr = row0 + r;
        sA[r * 65 + c] = (gr < N) ? A[gr * 64 + c] : 0.f;
    }
    __syncthreads();
    int a = t >> 4, b = t & 15;
    float4 acc[4];
#pragma unroll
    for (int i = 0; i < 4; i++) acc[i] = make_float4(0.f, 0.f, 0.f, 0.f);
#pragma unroll 8
    for (int m = 0; m < 64; m++) {
        float4 w = *reinterpret_cast<const float4*>(&sW[m * 64 + 4 * b]);
#pragma unroll
        for (int i = 0; i < 4; i++) {
            float av = sA[(a + 16 * i) * 65 + m];
            acc[i].x += av * w.x; acc[i].y += av * w.y;
            acc[i].z += av * w.z; acc[i].w += av * w.w;
        }
    }
#pragma unroll
    for (int i = 0; i < 4; i++) {
        int gr = row0 + a + 16 * i;
        if (gr < N) {
            *reinterpret_cast<float4*>(&C[gr * 64 + 4 * b]) = acc[i];
            if (hi) {
                float v[4] = { acc[i].x, acc[i].y, acc[i].z, acc[i].w };
                unsigned short hbits[4], lbits[4];
#pragma unroll
                for (int j = 0; j < 4; j++) {
                    __nv_bfloat16 h = __float2bfloat16(v[j]);
                    hbits[j] = __bfloat16_as_ushort(h);
                    lbits[j] = __bfloat16_as_ushort(__float2bfloat16(v[j] - __bfloat162float(h)));
                }
                uint2 hp, lp;
                hp.x = (unsigned)hbits[0] | ((unsigned)hbits[1] << 16);
                hp.y = (unsigned)hbits[2] | ((unsigned)hbits[3] << 16);
                lp.x = (unsigned)lbits[0] | ((unsigned)lbits[1] << 16);
                lp.y = (unsigned)lbits[2] | ((unsigned)lbits[3] << 16);
                *reinterpret_cast<uint2*>(&hi[(size_t)gr * 64 + 4 * b]) = hp;
                *reinterpret_cast<uint2*>(&lo[(size_t)gr * 64 + 4 * b]) = lp;
            }
        }
    }
}

// ---------------------------------------------------------------------------
// GEMM with fused split-K merge on the A operand + fused BN partial stats.
// A_row = (sum_i pO[i] * e^{m_i - m}) / (sum_i s_i * e^{m_i - m})
// ---------------------------------------------------------------------------
__global__ void __launch_bounds__(256) k_gemm64m(
    const float* __restrict__ pO, const float* __restrict__ pMS,
    const float* __restrict__ W, float* __restrict__ C, int N,
    float* __restrict__ part)
{
    __shared__ float sW[64 * 64];
    __shared__ float sA[64 * 65];
    __shared__ float sRow[64][KS];
    __shared__ float sred[2][16][64];
    int t = threadIdx.x;
    int row0 = blockIdx.x * 64;

    if (t < 64) {
        int gr = row0 + t;
        float m[KS], s[KS];
        if (gr < N) {
#pragma unroll
            for (int i = 0; i < KS; i++) {
                m[i] = pMS[(size_t)i * 2 * NDMAX + gr * 2];
                s[i] = pMS[(size_t)i * 2 * NDMAX + gr * 2 + 1];
            }
            float mx = m[0];
#pragma unroll
            for (int i = 1; i < KS; i++) mx = fmaxf(mx, m[i]);
            float e[KS], denom = 0.f;
#pragma unroll
            for (int i = 0; i < KS; i++) { e[i] = __expf(m[i] - mx); denom += s[i] * e[i]; }
            float inv = 1.f / denom;
#pragma unroll
            for (int i = 0; i < KS; i++) sRow[t][i] = e[i] * inv;
        } else {
#pragma unroll
            for (int i = 0; i < KS; i++) sRow[t][i] = 0.f;
        }
    }
    for (int i = t; i < 4096; i += 256) sW[i] = W[i];
    __syncthreads();
    for (int i = t; i < 4096; i += 256) {
        int r = i >> 6, c = i & 63;
        int gr = row0 + r;
        float v = 0.f;
        if (gr < N) {
#pragma unroll
            for (int k = 0; k < KS; k++)
                v += pO[(size_t)k * CELLS + (size_t)gr * 64 + c] * sRow[r][k];
        }
        sA[r * 65 + c] = v;
    }
    __syncthreads();
    int a = t >> 4, b = t & 15;
    float4 acc[4];
#pragma unroll
    for (int i = 0; i < 4; i++) acc[i] = make_float4(0.f, 0.f, 0.f, 0.f);
#pragma unroll 8
    for (int m = 0; m < 64; m++) {
        float4 w = *reinterpret_cast<const float4*>(&sW[m * 64 + 4 * b]);
#pragma unroll
        for (int i = 0; i < 4; i++) {
            float av = sA[(a + 16 * i) * 65 + m];
            acc[i].x += av * w.x; acc[i].y += av * w.y;
            acc[i].z += av * w.z; acc[i].w += av * w.w;
        }
    }
    float ls[4] = {0.f, 0.f, 0.f, 0.f}, ls2[4] = {0.f, 0.f, 0.f, 0.f};
#pragma unroll
    for (int i = 0; i < 4; i++) {
        int gr = row0 + a + 16 * i;
        if (gr < N) {
            *reinterpret_cast<float4*>(&C[gr * 64 + 4 * b]) = acc[i];
            float v[4] = { acc[i].x, acc[i].y, acc[i].z, acc[i].w };
#pragma unroll
            for (int j = 0; j < 4; j++) { ls[j] += v[j]; ls2[j] += v[j] * v[j]; }
        }
    }
#pragma unroll
    for (int j = 0; j < 4; j++) { sred[0][a][4 * b + j] = ls[j]; sred[1][a][4 * b + j] = ls2[j]; }
    __syncthreads();
    if (t < 64) {
        float s = 0.f, s2 = 0.f;
#pragma unroll
        for (int aa = 0; aa < 16; aa++) { s += sred[0][aa][t]; s2 += sred[1][aa][t]; }
        part[blockIdx.x * 128 + t] = s;
        part[blockIdx.x * 128 + 64 + t] = s2;
    }
}

// ---------------------------------------------------------------------------
// Rulebook sparse conv with empty-tap skipping; optional fused BN stats.
// ---------------------------------------------------------------------------
__global__ void __launch_bounds__(256) k_gconv(
    const float* __restrict__ F, const int* __restrict__ idx, int K,
    const float* __restrict__ W, float* __restrict__ out, int N,
    float* __restrict__ part)
{
    __shared__ float sW[64 * 64];
    __shared__ float sF[64 * 68];
    __shared__ int   sIdx[64];
    __shared__ float sred[2][16][64];
    int t = threadIdx.x;
    int row0 = blockIdx.x * 64;
    int a = t >> 4, b = t & 15;
    float4 acc[4];
#pragma unroll
    for (int i = 0; i < 4; i++) acc[i] = make_float4(0.f, 0.f, 0.f, 0.f);

    for (int k = 0; k < K; k++) {
        __syncthreads();
        int myvalid = 0;
        if (t < 64) {
            int gr = row0 + t;
            int j = (gr < N) ? idx[gr * K + k] : -1;
            sIdx[t] = j;
            myvalid = (j >= 0);
        }
        if (!__syncthreads_or(myvalid)) continue;
        for (int i = t; i < 4096; i += 256) sW[i] = W[k * 4096 + i];
        {
            int rr = t >> 2;
            int j = sIdx[rr];
            if (j >= 0) {
                int c0 = (t & 3) * 16;
#pragma unroll
                for (int q4 = 0; q4 < 4; q4++)
                    *reinterpret_cast<float4*>(&sF[rr * 68 + c0 + 4 * q4]) =
                        *reinterpret_cast<const float4*>(&F[j * 64 + c0 + 4 * q4]);
            }
        }
        __syncthreads();
#pragma unroll
        for (int i = 0; i < 4; i++) {
            int r = a + 16 * i;
            if (sIdx[r] >= 0) {
#pragma unroll 8
                for (int m = 0; m < 64; m++) {
                    float av = sF[r * 68 + m];
                    float4 w = *reinterpret_cast<const float4*>(&sW[m * 64 + 4 * b]);
                    acc[i].x += av * w.x; acc[i].y += av * w.y;
                    acc[i].z += av * w.z; acc[i].w += av * w.w;
                }
            }
        }
    }
    float ls[4] = {0.f, 0.f, 0.f, 0.f}, ls2[4] = {0.f, 0.f, 0.f, 0.f};
#pragma unroll
    for (int i = 0; i < 4; i++) {
        int gr = row0 + a + 16 * i;
        if (gr < N) {
            *reinterpret_cast<float4*>(&out[gr * 64 + 4 * b]) = acc[i];
            if (part) {
                float v[4] = { acc[i].x, acc[i].y, acc[i].z, acc[i].w };
#pragma unroll
                for (int j = 0; j < 4; j++) { ls[j] += v[j]; ls2[j] += v[j] * v[j]; }
            }
        }
    }
    if (part) {
        __syncthreads();
#pragma unroll
        for (int j = 0; j < 4; j++) { sred[0][a][4 * b + j] = ls[j]; sred[1][a][4 * b + j] = ls2[j]; }
        __syncthreads();
        if (t < 64) {
            float s = 0.f, s2 = 0.f;
#pragma unroll
            for (int aa = 0; aa < 16; aa++) { s += sred[0][aa][t]; s2 += sred[1][aa][t]; }
            part[blockIdx.x * 128 + t] = s;
            part[blockIdx.x * 128 + 64 + t] = s2;
        }
    }
}

// ---------------------------------------------------------------------------
// Segment prep
// ---------------------------------------------------------------------------
__global__ void k_prep(const int* __restrict__ pad_idx, int nd, int ne, int lq)
{
    int t = threadIdx.x;
    int w = t >> 5, lane = t & 31;
    if (w < NBATCH) {
        int cnt = 0;
        for (int l = lane; l < lq; l += 32)
            cnt += (pad_idx[w * lq + l] >= 0) ? 1 : 0;
#pragma unroll
        for (int o = 16; o > 0; o >>= 1) cnt += __shfl_xor_sync(0xffffffffu, cnt, o);
        if (lane == 0) {
            int s = pad_idx[w * lq];
            g_seg[(1 + w) * 4 + 0] = s;
            g_seg[(1 + w) * 4 + 1] = cnt;
            g_seg[(1 + w) * 4 + 2] = s;
            g_seg[(1 + w) * 4 + 3] = cnt;
        }
    }
    if (t == 0) { g_seg[0] = 0; g_seg[1] = nd; g_seg[2] = 0; g_seg[3] = ne; }
}

// ---------------------------------------------------------------------------
// bf16 3x tensor-core flash attention; warp-local softmax, optional split-K.
// ---------------------------------------------------------------------------
#define FLASH_SMEM_BF (65536 + 16384 + 16384 + 1024)

__global__ void __launch_bounds__(256, 2) k_flash_bf(
    const __nv_bfloat16* __restrict__ gQh, const __nv_bfloat16* __restrict__ gQl,
    const __nv_bfloat16* __restrict__ gKh, const __nv_bfloat16* __restrict__ gKl,
    const __nv_bfloat16* __restrict__ gVh, const __nv_bfloat16* __restrict__ gVl,
    float* __restrict__ O, int seg_off, int tiles_per_seg, int ksplit,
    float* __restrict__ pO, float* __restrict__ pMS)
{
    extern __shared__ char smc[];
    char* sKV = smc;
    char* sQ  = smc + 65536;
    char* sP  = smc + 81920;
    float* red = (float*)(smc + 98304);

    int bx = blockIdx.x;
    int segi = bx / tiles_per_seg;
    int traw = bx - segi * tiles_per_seg;
    int tile = traw / ksplit;
    int si = traw - tile * ksplit;
    int seg = seg_off + segi;
    int q0 = g_seg[seg * 4 + 0], nq = g_seg[seg * 4 + 1];
    int k0 = g_seg[seg * 4 + 2], nk = g_seg[seg * 4 + 3];
    if (tile * 64 >= nq) return;
    int qbase = q0 + tile * 64;
    int nqv = min(64, nq - tile * 64);

    int nkt_tot = (nk + 63) >> 6;
    int per = (nkt_tot + ksplit - 1) / ksplit;
    int kt0 = si * per;
    int kt1 = min(nkt_tot, kt0 + per);
    int nkt = kt1 - kt0;

    int t = threadIdx.x;
    int w = t >> 5, lane = t & 31;
    int qg = w & 3, h = w >> 2;
    int quad = lane >> 2, qi = lane & 3;
    int r0 = qg * 16 + quad, r1 = r0 + 8;

    float oc[32];
#pragma unroll
    for (int i = 0; i < 32; i++) oc[i] = 0.f;
    float rmax0 = -1e30f, rmax1 = -1e30f, rsum0 = 0.f, rsum1 = 0.f;

    if (nkt > 0) {
        {
#pragma unroll
            for (int j = 0; j < 2; j++) {
                int chunk = t + 256 * j;
                int row = chunk >> 3, jj = chunk & 7;
                cpa16(smu32(sQ + SW(row, jj << 4)),        gQh + (size_t)(qbase + row) * 64 + jj * 8);
                cpa16(smu32(sQ + 8192 + SW(row, jj << 4)), gQl + (size_t)(qbase + row) * 64 + jj * 8);
            }
            const __nv_bfloat16* gs[4] = { gKh, gKl, gVh, gVl };
            int kb0 = k0 + kt0 * 64;
#pragma unroll
            for (int a = 0; a < 4; a++)
#pragma unroll
                for (int j = 0; j < 2; j++) {
                    int chunk = t + 256 * j;
                    int row = chunk >> 3, jj = chunk & 7;
                    cpa16(smu32(sKV + a * 8192 + SW(row, jj << 4)),
                          gs[a] + (size_t)(kb0 + row) * 64 + jj * 8);
                }
        }
        CP_COMMIT();

        for (int kt = 0; kt < nkt; kt++) {
            char* sb = sKV + (kt & 1) * 32768;
            __syncthreads();
            if (kt + 1 < nkt) {
                char* nb = sKV + ((kt + 1) & 1) * 32768;
                int kb = k0 + (kt0 + kt + 1) * 64;
                const __nv_bfloat16* gs[4] = { gKh, gKl, gVh, gVl };
#pragma unroll
                for (int a = 0; a < 4; a++)
#pragma unroll
                    for (int j = 0; j < 2; j++) {
                        int chunk = t + 256 * j;
                        int row = chunk >> 3, jj = chunk & 7;
                        cpa16(smu32(nb + a * 8192 + SW(row, jj << 4)),
                              gs[a] + (size_t)(kb + row) * 64 + jj * 8);
                    }
            }
            CP_COMMIT();
            CP_WAIT1();
            __syncthreads();

            int nkv = min(64, nk - (kt0 + kt) * 64);
            char* sKh = sb;
            char* sKl = sb + 8192;
            char* sVh = sb + 16384;
            char* sVl = sb + 24576;

            float c4[4][4];
#pragma unroll
            for (int nt = 0; nt < 4; nt++)
#pragma unroll
                for (int k = 0; k < 4; k++) c4[nt][k] = 0.f;

#pragma unroll
            for (int ch = 0; ch < 4; ch++) {
                unsigned qh[4], ql[4];
                {
                    int r = qg * 16 + (lane & 7) + ((lane & 8) ? 8 : 0);
                    int cb = ch * 32 + ((lane & 16) ? 16 : 0);
                    ldsm4(qh, smu32(sQ + SW(r, cb)));
                    ldsm4(ql, smu32(sQ + 8192 + SW(r, cb)));
                }
                unsigned kh[8], kl[8];
                {
                    int r = 32 * h + (lane & 7) + ((lane & 16) ? 8 : 0);
                    int cb = ch * 32 + ((lane & 8) ? 16 : 0);
                    ldsm4(kh,     smu32(sKh + SW(r, cb)));
                    ldsm4(kh + 4, smu32(sKh + SW(r + 16, cb)));
                    ldsm4(kl,     smu32(sKl + SW(r, cb)));
                    ldsm4(kl + 4, smu32(sKl + SW(r + 16, cb)));
                }
#pragma unroll
                for (int nt = 0; nt < 4; nt++) {
                    mma_bf(c4[nt], qh, &kh[2 * nt]);
                    mma_bf(c4[nt], qh, &kl[2 * nt]);
                    mma_bf(c4[nt], ql, &kh[2 * nt]);
                }
            }

            if (nkv < 64) {
#pragma unroll
                for (int nt = 0; nt < 4; nt++) {
                    int colb = 32 * h + 8 * nt + 2 * qi;
#pragma unroll
                    for (int k = 0; k < 4; k++)
                        if (colb + (k & 1) >= nkv) c4[nt][k] = -1e30f;
                }
            }

            float mx0 = -1e30f, mx1 = -1e30f;
#pragma unroll
            for (int nt = 0; nt < 4; nt++) {
                mx0 = fmaxf(mx0, fmaxf(c4[nt][0], c4[nt][1]));
                mx1 = fmaxf(mx1, fmaxf(c4[nt][2], c4[nt][3]));
            }
            mx0 = fmaxf(mx0, __shfl_xor_sync(0xffffffffu, mx0, 1));
            mx0 = fmaxf(mx0, __shfl_xor_sync(0xffffffffu, mx0, 2));
            mx1 = fmaxf(mx1, __shfl_xor_sync(0xffffffffu, mx1, 1));
            mx1 = fmaxf(mx1, __shfl_xor_sync(0xffffffffu, mx1, 2));
            float mnew0 = fmaxf(rmax0, mx0);
            float mnew1 = fmaxf(rmax1, mx1);
            float corr0 = __expf(rmax0 - mnew0);
            float corr1 = __expf(rmax1 - mnew1);
            rmax0 = mnew0; rmax1 = mnew1;

            float ps0 = 0.f, ps1 = 0.f;
#pragma unroll
            for (int nt = 0; nt < 4; nt++) {
                int colcb = (32 * h + 8 * nt + 2 * qi) * 2;
                float p00 = __expf(c4[nt][0] - mnew0);
                float p01 = __expf(c4[nt][1] - mnew0);
                float p10 = __expf(c4[nt][2] - mnew1);
                float p11 = __expf(c4[nt][3] - mnew1);
                ps0 += p00 + p01; ps1 += p10 + p11;
                __nv_bfloat16 h00 = __float2bfloat16(p00), h01 = __float2bfloat16(p01);
                __nv_bfloat16 h10 = __float2bfloat16(p10), h11 = __float2bfloat16(p11);
                unsigned uh0 = (unsigned)__bfloat16_as_ushort(h00) | ((unsigned)__bfloat16_as_ushort(h01) << 16);
                unsigned uh1 = (unsigned)__bfloat16_as_ushort(h10) | ((unsigned)__bfloat16_as_ushort(h11) << 16);
                __nv_bfloat16 l00 = __float2bfloat16(p00 - __bfloat162float(h00));
                __nv_bfloat16 l01 = __float2bfloat16(p01 - __bfloat162float(h01));
                __nv_bfloat16 l10 = __float2bfloat16(p10 - __bfloat162float(h10));
                __nv_bfloat16 l11 = __float2bfloat16(p11 - __bfloat162float(h11));
                unsigned ul0 = (unsigned)__bfloat16_as_ushort(l00) | ((unsigned)__bfloat16_as_ushort(l01) << 16);
                unsigned ul1 = (unsigned)__bfloat16_as_ushort(l10) | ((unsigned)__bfloat16_as_ushort(l11) << 16);
                *(unsigned*)(sP + SW(r0, colcb)) = uh0;
                *(unsigned*)(sP + SW(r1, colcb)) = uh1;
                *(unsigned*)(sP + 8192 + SW(r0, colcb)) = ul0;
                *(unsigned*)(sP + 8192 + SW(r1, colcb)) = ul1;
            }
            ps0 += __shfl_xor_sync(0xffffffffu, ps0, 1);
            ps0 += __shfl_xor_sync(0xffffffffu, ps0, 2);
            ps1 += __shfl_xor_sync(0xffffffffu, ps1, 1);
            ps1 += __shfl_xor_sync(0xffffffffu, ps1, 2);
            rsum0 = rsum0 * corr0 + ps0;
            rsum1 = rsum1 * corr1 + ps1;
#pragma unroll
            for (int nt = 0; nt < 8; nt++) {
                oc[nt * 4 + 0] *= corr0; oc[nt * 4 + 1] *= corr0;
                oc[nt * 4 + 2] *= corr1; oc[nt * 4 + 3] *= corr1;
            }
            __syncwarp();

#pragma unroll
            for (int ck = 0; ck < 2; ck++) {
                int key0 = 32 * h + 16 * ck;
                unsigned ph[4], pl[4];
                {
                    int r = qg * 16 + (lane & 7) + ((lane & 8) ? 8 : 0);
                    int cb = key0 * 2 + ((lane & 16) ? 16 : 0);
                    ldsm4(ph, smu32(sP + SW(r, cb)));
                    ldsm4(pl, smu32(sP + 8192 + SW(r, cb)));
                }
#pragma unroll
                for (int cc = 0; cc < 4; cc++) {
                    unsigned vh[4], vl[4];
                    {
                        int r = key0 + (lane & 7) + ((lane & 8) ? 8 : 0);
                        int cb = cc * 32 + ((lane & 16) ? 16 : 0);
                        ldsm4t(vh, smu32(sVh + SW(r, cb)));
                        ldsm4t(vl, smu32(sVl + SW(r, cb)));
                    }
                    mma_bf(&oc[(2 * cc) * 4], ph, &vh[0]);
                    mma_bf(&oc[(2 * cc) * 4], ph, &vl[0]);
                    mma_bf(&oc[(2 * cc) * 4], pl, &vh[0]);
                    mma_bf(&oc[(2 * cc + 1) * 4], ph, &vh[2]);
                    mma_bf(&oc[(2 * cc + 1) * 4], ph, &vl[2]);
                    mma_bf(&oc[(2 * cc + 1) * 4], pl, &vh[2]);
                }
            }
        }
    }

    // ---- merge halves ----
    if (qi == 0) {
        red[h * 64 + r0] = rmax0;       red[h * 64 + r1] = rmax1;
        red[128 + h * 64 + r0] = rsum0; red[128 + h * 64 + r1] = rsum1;
    }
    __syncthreads();

    float m0a = red[r0], m1a = red[64 + r0];
    float mma_ = fmaxf(m0a, m1a);
    float fh_a = __expf(((h == 0) ? m0a : m1a) - mma_);
    float stot_a = red[128 + r0] * __expf(m0a - mma_) + red[192 + r0] * __expf(m1a - mma_);
    float m0b = red[r1], m1b = red[64 + r1];
    float mmb_ = fmaxf(m0b, m1b);
    float fh_b = __expf(((h == 0) ? m0b : m1b) - mmb_);
    float stot_b = red[128 + r1] * __expf(m0b - mmb_) + red[192 + r1] * __expf(m1b - mmb_);

    float* sO = (float*)sP;
    if (h == 1) {
#pragma unroll
        for (int nt = 0; nt < 8; nt++) {
            int colb = 8 * nt + 2 * qi;
            sO[r0 * 64 + colb]     = oc[nt * 4 + 0] * fh_a;
            sO[r0 * 64 + colb + 1] = oc[nt * 4 + 1] * fh_a;
            sO[r1 * 64 + colb]     = oc[nt * 4 + 2] * fh_b;
            sO[r1 * 64 + colb + 1] = oc[nt * 4 + 3] * fh_b;
        }
    }
    __syncthreads();
    if (h == 0) {
        if (ksplit == 1) {
            float inva = fh_a / stot_a, invb = fh_b / stot_b;
            float ja = 1.f / stot_a, jb = 1.f / stot_b;
#pragma unroll
            for (int nt = 0; nt < 8; nt++) {
                int colb = 8 * nt + 2 * qi;
                if (r0 < nqv) {
                    O[(size_t)(qbase + r0) * 64 + colb]     = oc[nt * 4 + 0] * inva + sO[r0 * 64 + colb] * ja;
                    O[(size_t)(qbase + r0) * 64 + colb + 1] = oc[nt * 4 + 1] * inva + sO[r0 * 64 + colb + 1] * ja;
                }
                if (r1 < nqv) {
                    O[(size_t)(qbase + r1) * 64 + colb]     = oc[nt * 4 + 2] * invb + sO[r1 * 64 + colb] * jb;
                    O[(size_t)(qbase + r1) * 64 + colb + 1] = oc[nt * 4 + 3] * invb + sO[r1 * 64 + colb + 1] * jb;
                }
            }
        } else {
            float* pOo = pO + (size_t)si * CELLS;
            float* pM  = pMS + (size_t)si * 2 * NDMAX;
#pragma unroll
            for (int nt = 0; nt < 8; nt++) {
                int colb = 8 * nt + 2 * qi;
                if (r0 < nqv) {
                    pOo[(size_t)(qbase + r0) * 64 + colb]     = oc[nt * 4 + 0] * fh_a + sO[r0 * 64 + colb];
                    pOo[(size_t)(qbase + r0) * 64 + colb + 1] = oc[nt * 4 + 1] * fh_a + sO[r0 * 64 + colb + 1];
                }
                if (r1 < nqv) {
                    pOo[(size_t)(qbase + r1) * 64 + colb]     = oc[nt * 4 + 2] * fh_b + sO[r1 * 64 + colb];
                    pOo[(size_t)(qbase + r1) * 64 + colb + 1] = oc[nt * 4 + 3] * fh_b + sO[r1 * 64 + colb + 1];
                }
            }
            if (qi == 0) {
                if (r0 < nqv) { pM[(qbase + r0) * 2] = mma_; pM[(qbase + r0) * 2 + 1] = stot_a; }
                if (r1 < nqv) { pM[(qbase + r1) * 2] = mmb_; pM[(qbase + r1) * 2 + 1] = stot_b; }
            }
        }
    }
}

// ---------------------------------------------------------------------------
// BatchNorm pieces
// ---------------------------------------------------------------------------
__global__ void k_bnstats_add(const float* __restrict__ X, const float* __restrict__ Y,
                              float* __restrict__ S, int N)
{
    __shared__ float sh[2][4][64];
    int c = threadIdx.x & 63, rg = threadIdx.x >> 6;
    float s = 0.f, s2 = 0.f;
    for (int r = blockIdx.x * 4 + rg; r < N; r += 256) {
        float v = X[r * 64 + c] + Y[r * 64 + c];
        S[r * 64 + c] = v;
        s += v; s2 += v * v;
    }
    sh[0][rg][c] = s; sh[1][rg][c] = s2;
    __syncthreads();
    if (threadIdx.x < 64) {
        float ts = sh[0][0][c] + sh[0][1][c] + sh[0][2][c] + sh[0][3][c];
        float t2 = sh[1][0][c] + sh[1][1][c] + sh[1][2][c] + sh[1][3][c];
        g_part[blockIdx.x * 128 + c] = ts;
        g_part[blockIdx.x * 128 + 64 + c] = t2;
    }
}

__global__ void k_bnfin(int N, int nblk)
{
    int c = threadIdx.x;
    float s = 0.f, s2 = 0.f;
    for (int b = 0; b < nblk; b++) { s += g_part[b * 128 + c]; s2 += g_part[b * 128 + 64 + c]; }
    float m = s / (float)N;
    float v = s2 / (float)N - m * m;
    g_stats[c] = m;
    g_stats[64 + c] = rsqrtf(v + 1e-4f);
}

// mode 0: bn(x); 1: res + bn(x); 2: relu(bn(x))
__global__ void k_bnapply(const float* __restrict__ X, const float* __restrict__ Res,
                          const float* __restrict__ gamma, const float* __restrict__ beta,
                          float* __restrict__ Out, int N, int mode)
{
    int i = blockIdx.x * blockDim.x + threadIdx.x;
    if (i < N * 64) {
        int c = i & 63;
        float y = (X[i] - g_stats[c]) * g_stats[64 + c] * gamma[c] + beta[c];
        if (mode == 1) y += Res[i];
        if (mode == 2) y = fmaxf(y, 0.f);
        Out[i] = y;
    }
}

// bn(x)+res, writing Out and fused partial stats of Out (row-blocked).
__global__ void __launch_bounds__(256) k_bnapply_stats(
    const float* __restrict__ X, const float* __restrict__ Res,
    const float* __restrict__ gamma, const float* __restrict__ beta,
    float* __restrict__ Out, int N, float* __restrict__ part)
{
    __shared__ float sh[2][4][64];
    int c = threadIdx.x & 63, rg = threadIdx.x >> 6;
    int row0 = blockIdx.x * 64;
    float g = gamma[c], be = beta[c];
    float mu = g_stats[c], rs = g_stats[64 + c];
    float s = 0.f, s2 = 0.f;
#pragma unroll
    for (int i = 0; i < 16; i++) {
        int r = row0 + rg + 4 * i;
        if (r < N) {
            float y = (X[r * 64 + c] - mu) * rs * g + be + Res[r * 64 + c];
            Out[r * 64 + c] = y;
            s += y; s2 += y * y;
        }
    }
    sh[0][rg][c] = s; sh[1][rg][c] = s2;
    __syncthreads();
    if (threadIdx.x < 64) {
        float ts = sh[0][0][c] + sh[0][1][c] + sh[0][2][c] + sh[0][3][c];
        float t2 = sh[1][0][c] + sh[1][1][c] + sh[1][2][c] + sh[1][3][c];
        part[blockIdx.x * 128 + c] = ts;
        part[blockIdx.x * 128 + 64 + c] = t2;
    }
}

// ---------------------------------------------------------------------------
extern "C" void kernel_launch(void* const* d_in, const int* in_sizes, int n_in,
                              void* d_out, int out_size)
{
    const float* xdec  = (const float*)d_in[0];
    const float* xenc  = (const float*)d_in[1];
    const float* Wp1   = (const float*)d_in[2];
    const float* Wq    = (const float*)d_in[3];
    const float* Wk    = (const float*)d_in[4];
    const float* Wv    = (const float*)d_in[5];
    const float* Wt    = (const float*)d_in[6];
    const float* Wq1   = (const float*)d_in[7];
    const float* Wk1   = (const float*)d_in[8];
    const float* Wv1   = (const float*)d_in[9];
    const float* Wdown = (const float*)d_in[10];
    const float* W3t   = (const float*)d_in[11];
    const float* W3a   = (const float*)d_in[12];
    const float* W3b   = (const float*)d_in[13];
    const float* gam   = (const float*)d_in[14];
    const float* bet   = (const float*)d_in[15];
    const int* nbr     = (const int*)d_in[16];
    const int* kv_nbr  = (const int*)d_in[17];
    const int* pad_idx = (const int*)d_in[18];

    int nd = in_sizes[0] / 64;
    int ne = in_sizes[1] / 64;
    int lq = in_sizes[18] / NBATCH;
    float* out = (float*)d_out;

    float* base = nullptr;
    cudaGetSymbolAddress((void**)&base, g_buf);
    float* B[15];
    for (int i = 0; i < 15; i++) B[i] = base + (size_t)i * CELLS;

    float* pob = nullptr;
    cudaGetSymbolAddress((void**)&pob, g_po);
    float* pmsb = nullptr;
    cudaGetSymbolAddress((void**)&pmsb, g_pms);
    float* partb = nullptr;
    cudaGetSymbolAddress((void**)&partb, g_part);

    __nv_bfloat16* bfb = nullptr;
    cudaGetSymbolAddress((void**)&bfb, g_bf);
    __nv_bfloat16* BF[6];
    for (int i = 0; i < 6; i++) BF[i] = bfb + (size_t)i * PADCELLS;

    cudaFuncSetAttribute(k_flash_bf, cudaFuncAttributeMaxDynamicSharedMemorySize, FLASH_SMEM_BF);

    dim3 thr(256);
    int gbd = (nd + 63) / 64;
    int gbe = (ne + 63) / 64;
    int gel = (nd * 64 + 255) / 256;

    // Stage 1
    k_gemm64<<<gbd, thr>>>(xdec, Wp1, B[0], nd, nullptr, nullptr);        // xd0
    k_gemm64<<<gbd, thr>>>(B[0], Wq, B[1], nd, BF[0], BF[1]);             // q (+bf)
    k_gemm64<<<gbe, thr>>>(xenc, Wk, B[2], ne, BF[2], BF[3]);             // ke (+bf)
    k_gemm64<<<gbe, thr>>>(xenc, Wv, B[3], ne, BF[4], BF[5]);             // ve (+bf)
    k_prep<<<1, thr>>>(pad_idx, nd, ne, lq);
    // split-K flash: KS key slices per q-tile
    k_flash_bf<<<gbd * KS, thr, FLASH_SMEM_BF>>>(BF[0], BF[1], BF[2], BF[3], BF[4], BF[5],
                                                 B[4], 0, gbd * KS, KS, pob, pmsb);
    k_gemm64m<<<gbd, thr>>>(pob, pmsb, Wt, B[5], nd, partb);              // xr = merge @ Wt (+stats)
    k_bnfin<<<1, 64>>>(nd, gbd);
    k_bnapply<<<gel, thr>>>(B[5], B[0], gam + 0, bet + 0, B[6], nd, 1);   // xd

    // Stage 2
    k_gemm64<<<gbd, thr>>>(B[6], Wq1, B[7], nd, BF[0], BF[1]);            // q1 (+bf)
    k_gconv<<<gbd, thr>>>(B[7], kv_nbr, 8, Wdown, B[8], nd, partb);
    k_bnfin<<<1, 64>>>(nd, gbd);
    k_bnapply<<<gel, thr>>>(B[8], B[8], gam + 64, bet + 64, B[9], nd, 0); // kv
    k_gemm64<<<gbd, thr>>>(B[9], Wk1, B[10], nd, BF[2], BF[3]);           // k1 (+bf)
    k_gemm64<<<gbd, thr>>>(B[9], Wv1, B[11], nd, BF[4], BF[5]);           // v1 (+bf)
    int tps = (lq + 63) / 64;
    k_flash_bf<<<NBATCH * tps, thr, FLASH_SMEM_BF>>>(BF[0], BF[1], BF[2], BF[3], BF[4], BF[5],
                                                     B[12], 1, tps, 1, nullptr, nullptr);
    k_gconv<<<gbd, thr>>>(B[12], nbr, 27, W3t, B[13], nd, partb);
    k_bnfin<<<1, 64>>>(nd, gbd);
    k_bnapply_stats<<<gbd, thr>>>(B[13], B[6], gam + 128, bet + 128, B[14], nd, partb); // xd2 (+stats)

    // Res block
    k_bnfin<<<1, 64>>>(nd, gbd);
    k_bnapply<<<gel, thr>>>(B[14], B[14], gam + 192, bet + 192, B[0], nd, 2);
    k_gconv<<<gbd, thr>>>(B[0], nbr, 27, W3a, B[1], nd, partb);
    k_bnfin<<<1, 64>>>(nd, gbd);
    k_bnapply<<<gel, thr>>>(B[1], B[1], gam + 256, bet + 256, B[2], nd, 2);
    k_gconv<<<gbd, thr>>>(B[2], nbr, 27, W3b, B[3], nd, nullptr);
    k_bnstats_add<<<64, thr>>>(B[14], B[3], B[4], nd);
    k_bnfin<<<1, 64>>>(nd, 64);
    k_bnapply<<<gel, thr>>>(B[4], B[4], gam + 320, bet + 320, out, nd, 2);
}

// round 8
// speedup vs baseline: 3.1290x; 1.0641x over previous
#include <cuda_runtime.h>
#include <cuda_bf16.h>
#include <math.h>

#define NF 64
#define NBATCH 8
#define NDMAX 12288
#define CELLS (NDMAX * NF)
#define PADCELLS (CELLS + 64 * 64)
#define KS 3

__device__ float g_buf[15][CELLS];
__device__ float g_po[KS][CELLS];
__device__ float g_pms[KS][2 * NDMAX];
__device__ __nv_bfloat16 g_bf[6][PADCELLS];  // Qhi Qlo Khi Klo Vhi Vlo
__device__ float g_stats[128];
__device__ float g_part[256 * 128];
__device__ int   g_seg[64];
__device__ float g_wc[4096];

// ---------------------------------------------------------------------------
// Helpers
// ---------------------------------------------------------------------------
__device__ __forceinline__ int SW(int r, int cb) {
    return r * 128 + (cb ^ ((r & 7) << 4));
}
__device__ __forceinline__ unsigned smu32(const void* p) {
    return (unsigned)__cvta_generic_to_shared(p);
}
__device__ __forceinline__ void cpa16(unsigned dst, const void* src) {
    asm volatile("cp.async.ca.shared.global [%0], [%1], 16;" :: "r"(dst), "l"(src) : "memory");
}
#define CP_COMMIT() asm volatile("cp.async.commit_group;" ::: "memory")
#define CP_WAIT1()  asm volatile("cp.async.wait_group 1;" ::: "memory")

__device__ __forceinline__ void ldsm4(unsigned r[4], unsigned a) {
    asm volatile("ldmatrix.sync.aligned.m8n8.x4.shared.b16 {%0,%1,%2,%3}, [%4];"
                 : "=r"(r[0]), "=r"(r[1]), "=r"(r[2]), "=r"(r[3]) : "r"(a));
}
__device__ __forceinline__ void ldsm4t(unsigned r[4], unsigned a) {
    asm volatile("ldmatrix.sync.aligned.m8n8.x4.trans.shared.b16 {%0,%1,%2,%3}, [%4];"
                 : "=r"(r[0]), "=r"(r[1]), "=r"(r[2]), "=r"(r[3]) : "r"(a));
}
__device__ __forceinline__ void mma_bf(float c[4], const unsigned a[4], const unsigned b[2]) {
    asm volatile(
        "mma.sync.aligned.m16n8k16.row.col.f32.bf16.bf16.f32 "
        "{%0,%1,%2,%3}, {%4,%5,%6,%7}, {%8,%9}, {%0,%1,%2,%3};"
        : "+f"(c[0]), "+f"(c[1]), "+f"(c[2]), "+f"(c[3])
        : "r"(a[0]), "r"(a[1]), "r"(a[2]), "r"(a[3]), "r"(b[0]), "r"(b[1]));
}

__device__ __forceinline__ void bf_split(float v, unsigned short& hb, unsigned short& lb) {
    __nv_bfloat16 h = __float2bfloat16(v);
    hb = __bfloat16_as_ushort(h);
    lb = __bfloat16_as_ushort(__float2bfloat16(v - __bfloat162float(h)));
}

// ---------------------------------------------------------------------------
// Composite weight: Wout = W1 @ W2  (1 block, 256 threads)
// ---------------------------------------------------------------------------
__global__ void __launch_bounds__(256) k_wcomp(const float* __restrict__ W1,
                                               const float* __restrict__ W2,
                                               float* __restrict__ Wout)
{
    __shared__ float s1[64 * 64], s2[64 * 64];
    int t = threadIdx.x;
    for (int i = t; i < 4096; i += 256) { s1[i] = W1[i]; s2[i] = W2[i]; }
    __syncthreads();
    // thread t: rows r = t>>2 (16 rows per... ) -> each thread 16 outputs:
    // r = t >> 2, cols (t&3)*16 .. +15
    int r = t >> 2, c0 = (t & 3) * 16;
    float acc[16];
#pragma unroll
    for (int j = 0; j < 16; j++) acc[j] = 0.f;
    for (int m = 0; m < 64; m++) {
        float a = s1[r * 64 + m];
#pragma unroll
        for (int j = 0; j < 16; j++) acc[j] += a * s2[m * 64 + c0 + j];
    }
#pragma unroll
    for (int j = 0; j < 16; j++) Wout[r * 64 + c0 + j] = acc[j];
}

// ---------------------------------------------------------------------------
// Batched GEMM: up to 4 independent jobs (blockIdx.y). Optional BN on A-load,
// optional fp32 C output, optional bf16 hi/lo output.
// ---------------------------------------------------------------------------
struct GJobs {
    const float* A[4];
    const float* W[4];
    float* C[4];
    __nv_bfloat16* hi[4];
    __nv_bfloat16* lo[4];
    const float* bg[4];   // BN gamma (null = no BN on A)
    const float* bb[4];
    int N[4];
};

__global__ void __launch_bounds__(256) k_gemm64b(GJobs J)
{
    int jy = blockIdx.y;
    int N = J.N[jy];
    int row0 = blockIdx.x * 64;
    if (row0 >= N) return;
    const float* A = J.A[jy];
    const float* W = J.W[jy];
    float* C = J.C[jy];
    __nv_bfloat16* hi = J.hi[jy];
    __nv_bfloat16* lo = J.lo[jy];
    const float* bg = J.bg[jy];

    __shared__ float sW[64 * 64];
    __shared__ float sA[64 * 65];
    __shared__ float sa[64], sb[64];
    int t = threadIdx.x;
    if (bg && t < 64) {
        float a = g_stats[64 + t] * bg[t];
        sa[t] = a;
        sb[t] = J.bb[jy][t] - g_stats[t] * a;
    }
    if (!bg && t < 64) { sa[t] = 1.f; sb[t] = 0.f; }
    __syncthreads();
    for (int i = t; i < 4096; i += 256) {
        sW[i] = W[i];
        int r = i >> 6, c = i & 63;
        int gr = row0 + r;
        float v = (gr < N) ? A[(size_t)gr * 64 + c] : 0.f;
        sA[r * 65 + c] = v * sa[c] + sb[c];
    }
    __syncthreads();
    int a = t >> 4, b = t & 15;
    float4 acc[4];
#pragma unroll
    for (int i = 0; i < 4; i++) acc[i] = make_float4(0.f, 0.f, 0.f, 0.f);
#pragma unroll 8
    for (int m = 0; m < 64; m++) {
        float4 w = *reinterpret_cast<const float4*>(&sW[m * 64 + 4 * b]);
#pragma unroll
        for (int i = 0; i < 4; i++) {
            float av = sA[(a + 16 * i) * 65 + m];
            acc[i].x += av * w.x; acc[i].y += av * w.y;
            acc[i].z += av * w.z; acc[i].w += av * w.w;
        }
    }
#pragma unroll
    for (int i = 0; i < 4; i++) {
        int gr = row0 + a + 16 * i;
        if (gr < N) {
            if (C) *reinterpret_cast<float4*>(&C[(size_t)gr * 64 + 4 * b]) = acc[i];
            if (hi) {
                float v[4] = { acc[i].x, acc[i].y, acc[i].z, acc[i].w };
                unsigned short hb[4], lb[4];
#pragma unroll
                for (int j = 0; j < 4; j++) bf_split(v[j], hb[j], lb[j]);
                uint2 hp, lp;
                hp.x = (unsigned)hb[0] | ((unsigned)hb[1] << 16);
                hp.y = (unsigned)hb[2] | ((unsigned)hb[3] << 16);
                lp.x = (unsigned)lb[0] | ((unsigned)lb[1] << 16);
                lp.y = (unsigned)lb[2] | ((unsigned)lb[3] << 16);
                *reinterpret_cast<uint2*>(&hi[(size_t)gr * 64 + 4 * b]) = hp;
                *reinterpret_cast<uint2*>(&lo[(size_t)gr * 64 + 4 * b]) = lp;
            }
        }
    }
}

// ---------------------------------------------------------------------------
// GEMM with A = bn(X)+Res computed on load (written to Aout), C + bf16 out.
// ---------------------------------------------------------------------------
__global__ void __launch_bounds__(256) k_gemm64br(
    const float* __restrict__ X, const float* __restrict__ Res,
    const float* __restrict__ bg, const float* __restrict__ bb,
    float* __restrict__ Aout,
    const float* __restrict__ W, float* __restrict__ C, int N,
    __nv_bfloat16* __restrict__ hi, __nv_bfloat16* __restrict__ lo)
{
    __shared__ float sW[64 * 64];
    __shared__ float sA[64 * 65];
    __shared__ float sa[64], sb[64];
    int t = threadIdx.x;
    int row0 = blockIdx.x * 64;
    if (t < 64) {
        float a = g_stats[64 + t] * bg[t];
        sa[t] = a;
        sb[t] = bb[t] - g_stats[t] * a;
    }
    __syncthreads();
    for (int i = t; i < 4096; i += 256) {
        sW[i] = W[i];
        int r = i >> 6, c = i & 63;
        int gr = row0 + r;
        float v = 0.f;
        if (gr < N) {
            v = X[(size_t)gr * 64 + c] * sa[c] + sb[c] + Res[(size_t)gr * 64 + c];
            Aout[(size_t)gr * 64 + c] = v;
        }
        sA[r * 65 + c] = v;
    }
    __syncthreads();
    int a = t >> 4, b = t & 15;
    float4 acc[4];
#pragma unroll
    for (int i = 0; i < 4; i++) acc[i] = make_float4(0.f, 0.f, 0.f, 0.f);
#pragma unroll 8
    for (int m = 0; m < 64; m++) {
        float4 w = *reinterpret_cast<const float4*>(&sW[m * 64 + 4 * b]);
#pragma unroll
        for (int i = 0; i < 4; i++) {
            float av = sA[(a + 16 * i) * 65 + m];
            acc[i].x += av * w.x; acc[i].y += av * w.y;
            acc[i].z += av * w.z; acc[i].w += av * w.w;
        }
    }
#pragma unroll
    for (int i = 0; i < 4; i++) {
        int gr = row0 + a + 16 * i;
        if (gr < N) {
            *reinterpret_cast<float4*>(&C[(size_t)gr * 64 + 4 * b]) = acc[i];
            float v[4] = { acc[i].x, acc[i].y, acc[i].z, acc[i].w };
            unsigned short hb[4], lb[4];
#pragma unroll
            for (int j = 0; j < 4; j++) bf_split(v[j], hb[j], lb[j]);
            uint2 hp, lp;
            hp.x = (unsigned)hb[0] | ((unsigned)hb[1] << 16);
            hp.y = (unsigned)hb[2] | ((unsigned)hb[3] << 16);
            lp.x = (unsigned)lb[0] | ((unsigned)lb[1] << 16);
            lp.y = (unsigned)lb[2] | ((unsigned)lb[3] << 16);
            *reinterpret_cast<uint2*>(&hi[(size_t)gr * 64 + 4 * b]) = hp;
            *reinterpret_cast<uint2*>(&lo[(size_t)gr * 64 + 4 * b]) = lp;
        }
    }
}

// ---------------------------------------------------------------------------
// GEMM with fused split-K merge on A + fused BN partial stats.
// ---------------------------------------------------------------------------
__global__ void __launch_bounds__(256) k_gemm64m(
    const float* __restrict__ pO, const float* __restrict__ pMS,
    const float* __restrict__ W, float* __restrict__ C, int N,
    float* __restrict__ part)
{
    __shared__ float sW[64 * 64];
    __shared__ float sA[64 * 65];
    __shared__ float sRow[64][KS];
    __shared__ float sred[2][16][64];
    int t = threadIdx.x;
    int row0 = blockIdx.x * 64;

    if (t < 64) {
        int gr = row0 + t;
        float m[KS], s[KS];
        if (gr < N) {
#pragma unroll
            for (int i = 0; i < KS; i++) {
                m[i] = pMS[(size_t)i * 2 * NDMAX + gr * 2];
                s[i] = pMS[(size_t)i * 2 * NDMAX + gr * 2 + 1];
            }
            float mx = m[0];
#pragma unroll
            for (int i = 1; i < KS; i++) mx = fmaxf(mx, m[i]);
            float e[KS], denom = 0.f;
#pragma unroll
            for (int i = 0; i < KS; i++) { e[i] = __expf(m[i] - mx); denom += s[i] * e[i]; }
            float inv = 1.f / denom;
#pragma unroll
            for (int i = 0; i < KS; i++) sRow[t][i] = e[i] * inv;
        } else {
#pragma unroll
            for (int i = 0; i < KS; i++) sRow[t][i] = 0.f;
        }
    }
    for (int i = t; i < 4096; i += 256) sW[i] = W[i];
    __syncthreads();
    for (int i = t; i < 4096; i += 256) {
        int r = i >> 6, c = i & 63;
        int gr = row0 + r;
        float v = 0.f;
        if (gr < N) {
#pragma unroll
            for (int k = 0; k < KS; k++)
                v += pO[(size_t)k * CELLS + (size_t)gr * 64 + c] * sRow[r][k];
        }
        sA[r * 65 + c] = v;
    }
    __syncthreads();
    int a = t >> 4, b = t & 15;
    float4 acc[4];
#pragma unroll
    for (int i = 0; i < 4; i++) acc[i] = make_float4(0.f, 0.f, 0.f, 0.f);
#pragma unroll 8
    for (int m = 0; m < 64; m++) {
        float4 w = *reinterpret_cast<const float4*>(&sW[m * 64 + 4 * b]);
#pragma unroll
        for (int i = 0; i < 4; i++) {
            float av = sA[(a + 16 * i) * 65 + m];
            acc[i].x += av * w.x; acc[i].y += av * w.y;
            acc[i].z += av * w.z; acc[i].w += av * w.w;
        }
    }
    float ls[4] = {0.f, 0.f, 0.f, 0.f}, ls2[4] = {0.f, 0.f, 0.f, 0.f};
#pragma unroll
    for (int i = 0; i < 4; i++) {
        int gr = row0 + a + 16 * i;
        if (gr < N) {
            *reinterpret_cast<float4*>(&C[(size_t)gr * 64 + 4 * b]) = acc[i];
            float v[4] = { acc[i].x, acc[i].y, acc[i].z, acc[i].w };
#pragma unroll
            for (int j = 0; j < 4; j++) { ls[j] += v[j]; ls2[j] += v[j] * v[j]; }
        }
    }
#pragma unroll
    for (int j = 0; j < 4; j++) { sred[0][a][4 * b + j] = ls[j]; sred[1][a][4 * b + j] = ls2[j]; }
    __syncthreads();
    if (t < 64) {
        float s = 0.f, s2 = 0.f;
#pragma unroll
        for (int aa = 0; aa < 16; aa++) { s += sred[0][aa][t]; s2 += sred[1][aa][t]; }
        part[blockIdx.x * 128 + t] = s;
        part[blockIdx.x * 128 + 64 + t] = s2;
    }
}

// ---------------------------------------------------------------------------
// Rulebook sparse conv: empty-tap skipping, optional BN+ReLU on gathered input,
// optional fused BN stats on output.
// ---------------------------------------------------------------------------
__global__ void __launch_bounds__(256) k_gconv(
    const float* __restrict__ F, const int* __restrict__ idx, int K,
    const float* __restrict__ W, float* __restrict__ out, int N,
    float* __restrict__ part,
    const float* __restrict__ bg, const float* __restrict__ bb)
{
    __shared__ float sW[64 * 64];
    __shared__ float sF[64 * 68];
    __shared__ int   sIdx[64];
    __shared__ float sred[2][16][64];
    __shared__ float sa[64], sb[64];
    int t = threadIdx.x;
    int row0 = blockIdx.x * 64;
    int a = t >> 4, b = t & 15;
    if (bg && t < 64) {
        float av = g_stats[64 + t] * bg[t];
        sa[t] = av;
        sb[t] = bb[t] - g_stats[t] * av;
    }
    float4 acc[4];
#pragma unroll
    for (int i = 0; i < 4; i++) acc[i] = make_float4(0.f, 0.f, 0.f, 0.f);

    for (int k = 0; k < K; k++) {
        __syncthreads();
        int myvalid = 0;
        if (t < 64) {
            int gr = row0 + t;
            int j = (gr < N) ? idx[gr * K + k] : -1;
            sIdx[t] = j;
            myvalid = (j >= 0);
        }
        if (!__syncthreads_or(myvalid)) continue;
        for (int i = t; i < 4096; i += 256) sW[i] = W[k * 4096 + i];
        {
            int rr = t >> 2;
            int j = sIdx[rr];
            if (j >= 0) {
                int c0 = (t & 3) * 16;
#pragma unroll
                for (int q4 = 0; q4 < 4; q4++) {
                    float4 v = *reinterpret_cast<const float4*>(&F[(size_t)j * 64 + c0 + 4 * q4]);
                    if (bg) {
                        int c = c0 + 4 * q4;
                        v.x = fmaxf(v.x * sa[c] + sb[c], 0.f);
                        v.y = fmaxf(v.y * sa[c + 1] + sb[c + 1], 0.f);
                        v.z = fmaxf(v.z * sa[c + 2] + sb[c + 2], 0.f);
                        v.w = fmaxf(v.w * sa[c + 3] + sb[c + 3], 0.f);
                    }
                    *reinterpret_cast<float4*>(&sF[rr * 68 + c0 + 4 * q4]) = v;
                }
            }
        }
        __syncthreads();
#pragma unroll
        for (int i = 0; i < 4; i++) {
            int r = a + 16 * i;
            if (sIdx[r] >= 0) {
#pragma unroll 8
                for (int m = 0; m < 64; m++) {
                    float av = sF[r * 68 + m];
                    float4 w = *reinterpret_cast<const float4*>(&sW[m * 64 + 4 * b]);
                    acc[i].x += av * w.x; acc[i].y += av * w.y;
                    acc[i].z += av * w.z; acc[i].w += av * w.w;
                }
            }
        }
    }
    float ls[4] = {0.f, 0.f, 0.f, 0.f}, ls2[4] = {0.f, 0.f, 0.f, 0.f};
#pragma unroll
    for (int i = 0; i < 4; i++) {
        int gr = row0 + a + 16 * i;
        if (gr < N) {
            *reinterpret_cast<float4*>(&out[(size_t)gr * 64 + 4 * b]) = acc[i];
            if (part) {
                float v[4] = { acc[i].x, acc[i].y, acc[i].z, acc[i].w };
#pragma unroll
                for (int j = 0; j < 4; j++) { ls[j] += v[j]; ls2[j] += v[j] * v[j]; }
            }
        }
    }
    if (part) {
        __syncthreads();
#pragma unroll
        for (int j = 0; j < 4; j++) { sred[0][a][4 * b + j] = ls[j]; sred[1][a][4 * b + j] = ls2[j]; }
        __syncthreads();
        if (t < 64) {
            float s = 0.f, s2 = 0.f;
#pragma unroll
            for (int aa = 0; aa < 16; aa++) { s += sred[0][aa][t]; s2 += sred[1][aa][t]; }
            part[blockIdx.x * 128 + t] = s;
            part[blockIdx.x * 128 + 64 + t] = s2;
        }
    }
}

// ---------------------------------------------------------------------------
// Segment prep
// ---------------------------------------------------------------------------
__global__ void k_prep(const int* __restrict__ pad_idx, int nd, int ne, int lq)
{
    int t = threadIdx.x;
    int w = t >> 5, lane = t & 31;
    if (w < NBATCH) {
        int cnt = 0;
        for (int l = lane; l < lq; l += 32)
            cnt += (pad_idx[w * lq + l] >= 0) ? 1 : 0;
#pragma unroll
        for (int o = 16; o > 0; o >>= 1) cnt += __shfl_xor_sync(0xffffffffu, cnt, o);
        if (lane == 0) {
            int s = pad_idx[w * lq];
            g_seg[(1 + w) * 4 + 0] = s;
            g_seg[(1 + w) * 4 + 1] = cnt;
            g_seg[(1 + w) * 4 + 2] = s;
            g_seg[(1 + w) * 4 + 3] = cnt;
        }
    }
    if (t == 0) { g_seg[0] = 0; g_seg[1] = nd; g_seg[2] = 0; g_seg[3] = ne; }
}

// ---------------------------------------------------------------------------
// bf16 3x tensor-core flash attention (unchanged from R6).
// ---------------------------------------------------------------------------
#define FLASH_SMEM_BF (65536 + 16384 + 16384 + 1024)

__global__ void __launch_bounds__(256, 2) k_flash_bf(
    const __nv_bfloat16* __restrict__ gQh, const __nv_bfloat16* __restrict__ gQl,
    const __nv_bfloat16* __restrict__ gKh, const __nv_bfloat16* __restrict__ gKl,
    const __nv_bfloat16* __restrict__ gVh, const __nv_bfloat16* __restrict__ gVl,
    float* __restrict__ O, int seg_off, int tiles_per_seg, int ksplit,
    float* __restrict__ pO, float* __restrict__ pMS)
{
    extern __shared__ char smc[];
    char* sKV = smc;
    char* sQ  = smc + 65536;
    char* sP  = smc + 81920;
    float* red = (float*)(smc + 98304);

    int bx = blockIdx.x;
    int segi = bx / tiles_per_seg;
    int traw = bx - segi * tiles_per_seg;
    int tile = traw / ksplit;
    int si = traw - tile * ksplit;
    int seg = seg_off + segi;
    int q0 = g_seg[seg * 4 + 0], nq = g_seg[seg * 4 + 1];
    int k0 = g_seg[seg * 4 + 2], nk = g_seg[seg * 4 + 3];
    if (tile * 64 >= nq) return;
    int qbase = q0 + tile * 64;
    int nqv = min(64, nq - tile * 64);

    int nkt_tot = (nk + 63) >> 6;
    int per = (nkt_tot + ksplit - 1) / ksplit;
    int kt0 = si * per;
    int kt1 = min(nkt_tot, kt0 + per);
    int nkt = kt1 - kt0;

    int t = threadIdx.x;
    int w = t >> 5, lane = t & 31;
    int qg = w & 3, h = w >> 2;
    int quad = lane >> 2, qi = lane & 3;
    int r0 = qg * 16 + quad, r1 = r0 + 8;

    float oc[32];
#pragma unroll
    for (int i = 0; i < 32; i++) oc[i] = 0.f;
    float rmax0 = -1e30f, rmax1 = -1e30f, rsum0 = 0.f, rsum1 = 0.f;

    if (nkt > 0) {
        {
#pragma unroll
            for (int j = 0; j < 2; j++) {
                int chunk = t + 256 * j;
                int row = chunk >> 3, jj = chunk & 7;
                cpa16(smu32(sQ + SW(row, jj << 4)),        gQh + (size_t)(qbase + row) * 64 + jj * 8);
                cpa16(smu32(sQ + 8192 + SW(row, jj << 4)), gQl + (size_t)(qbase + row) * 64 + jj * 8);
            }
            const __nv_bfloat16* gs[4] = { gKh, gKl, gVh, gVl };
            int kb0 = k0 + kt0 * 64;
#pragma unroll
            for (int a = 0; a < 4; a++)
#pragma unroll
                for (int j = 0; j < 2; j++) {
                    int chunk = t + 256 * j;
                    int row = chunk >> 3, jj = chunk & 7;
                    cpa16(smu32(sKV + a * 8192 + SW(row, jj << 4)),
                          gs[a] + (size_t)(kb0 + row) * 64 + jj * 8);
                }
        }
        CP_COMMIT();

        for (int kt = 0; kt < nkt; kt++) {
            char* sb = sKV + (kt & 1) * 32768;
            __syncthreads();
            if (kt + 1 < nkt) {
                char* nb = sKV + ((kt + 1) & 1) * 32768;
                int kb = k0 + (kt0 + kt + 1) * 64;
                const __nv_bfloat16* gs[4] = { gKh, gKl, gVh, gVl };
#pragma unroll
                for (int a = 0; a < 4; a++)
#pragma unroll
                    for (int j = 0; j < 2; j++) {
                        int chunk = t + 256 * j;
                        int row = chunk >> 3, jj = chunk & 7;
                        cpa16(smu32(nb + a * 8192 + SW(row, jj << 4)),
                              gs[a] + (size_t)(kb + row) * 64 + jj * 8);
                    }
            }
            CP_COMMIT();
            CP_WAIT1();
            __syncthreads();

            int nkv = min(64, nk - (kt0 + kt) * 64);
            char* sKh = sb;
            char* sKl = sb + 8192;
            char* sVh = sb + 16384;
            char* sVl = sb + 24576;

            float c4[4][4];
#pragma unroll
            for (int nt = 0; nt < 4; nt++)
#pragma unroll
                for (int k = 0; k < 4; k++) c4[nt][k] = 0.f;

#pragma unroll
            for (int ch = 0; ch < 4; ch++) {
                unsigned qh[4], ql[4];
                {
                    int r = qg * 16 + (lane & 7) + ((lane & 8) ? 8 : 0);
                    int cb = ch * 32 + ((lane & 16) ? 16 : 0);
                    ldsm4(qh, smu32(sQ + SW(r, cb)));
                    ldsm4(ql, smu32(sQ + 8192 + SW(r, cb)));
                }
                unsigned kh[8], kl[8];
                {
                    int r = 32 * h + (lane & 7) + ((lane & 16) ? 8 : 0);
                    int cb = ch * 32 + ((lane & 8) ? 16 : 0);
                    ldsm4(kh,     smu32(sKh + SW(r, cb)));
                    ldsm4(kh + 4, smu32(sKh + SW(r + 16, cb)));
                    ldsm4(kl,     smu32(sKl + SW(r, cb)));
                    ldsm4(kl + 4, smu32(sKl + SW(r + 16, cb)));
                }
#pragma unroll
                for (int nt = 0; nt < 4; nt++) {
                    mma_bf(c4[nt], qh, &kh[2 * nt]);
                    mma_bf(c4[nt], qh, &kl[2 * nt]);
                    mma_bf(c4[nt], ql, &kh[2 * nt]);
                }
            }

            if (nkv < 64) {
#pragma unroll
                for (int nt = 0; nt < 4; nt++) {
                    int colb = 32 * h + 8 * nt + 2 * qi;
#pragma unroll
                    for (int k = 0; k < 4; k++)
                        if (colb + (k & 1) >= nkv) c4[nt][k] = -1e30f;
                }
            }

            float mx0 = -1e30f, mx1 = -1e30f;
#pragma unroll
            for (int nt = 0; nt < 4; nt++) {
                mx0 = fmaxf(mx0, fmaxf(c4[nt][0], c4[nt][1]));
                mx1 = fmaxf(mx1, fmaxf(c4[nt][2], c4[nt][3]));
            }
            mx0 = fmaxf(mx0, __shfl_xor_sync(0xffffffffu, mx0, 1));
            mx0 = fmaxf(mx0, __shfl_xor_sync(0xffffffffu, mx0, 2));
            mx1 = fmaxf(mx1, __shfl_xor_sync(0xffffffffu, mx1, 1));
            mx1 = fmaxf(mx1, __shfl_xor_sync(0xffffffffu, mx1, 2));
            float mnew0 = fmaxf(rmax0, mx0);
            float mnew1 = fmaxf(rmax1, mx1);
            float corr0 = __expf(rmax0 - mnew0);
            float corr1 = __expf(rmax1 - mnew1);
            rmax0 = mnew0; rmax1 = mnew1;

            float ps0 = 0.f, ps1 = 0.f;
#pragma unroll
            for (int nt = 0; nt < 4; nt++) {
                int colcb = (32 * h + 8 * nt + 2 * qi) * 2;
                float p00 = __expf(c4[nt][0] - mnew0);
                float p01 = __expf(c4[nt][1] - mnew0);
                float p10 = __expf(c4[nt][2] - mnew1);
                float p11 = __expf(c4[nt][3] - mnew1);
                ps0 += p00 + p01; ps1 += p10 + p11;
                unsigned short h00, h01, h10, h11, l00, l01, l10, l11;
                bf_split(p00, h00, l00); bf_split(p01, h01, l01);
                bf_split(p10, h10, l10); bf_split(p11, h11, l11);
                *(unsigned*)(sP + SW(r0, colcb)) = (unsigned)h00 | ((unsigned)h01 << 16);
                *(unsigned*)(sP + SW(r1, colcb)) = (unsigned)h10 | ((unsigned)h11 << 16);
                *(unsigned*)(sP + 8192 + SW(r0, colcb)) = (unsigned)l00 | ((unsigned)l01 << 16);
                *(unsigned*)(sP + 8192 + SW(r1, colcb)) = (unsigned)l10 | ((unsigned)l11 << 16);
            }
            ps0 += __shfl_xor_sync(0xffffffffu, ps0, 1);
            ps0 += __shfl_xor_sync(0xffffffffu, ps0, 2);
            ps1 += __shfl_xor_sync(0xffffffffu, ps1, 1);
            ps1 += __shfl_xor_sync(0xffffffffu, ps1, 2);
            rsum0 = rsum0 * corr0 + ps0;
            rsum1 = rsum1 * corr1 + ps1;
#pragma unroll
            for (int nt = 0; nt < 8; nt++) {
                oc[nt * 4 + 0] *= corr0; oc[nt * 4 + 1] *= corr0;
                oc[nt * 4 + 2] *= corr1; oc[nt * 4 + 3] *= corr1;
            }
            __syncwarp();

#pragma unroll
            for (int ck = 0; ck < 2; ck++) {
                int key0 = 32 * h + 16 * ck;
                unsigned ph[4], pl[4];
                {
                    int r = qg * 16 + (lane & 7) + ((lane & 8) ? 8 : 0);
                    int cb = key0 * 2 + ((lane & 16) ? 16 : 0);
                    ldsm4(ph, smu32(sP + SW(r, cb)));
                    ldsm4(pl, smu32(sP + 8192 + SW(r, cb)));
                }
#pragma unroll
                for (int cc = 0; cc < 4; cc++) {
                    unsigned vh[4], vl[4];
                    {
                        int r = key0 + (lane & 7) + ((lane & 8) ? 8 : 0);
                        int cb = cc * 32 + ((lane & 16) ? 16 : 0);
                        ldsm4t(vh, smu32(sVh + SW(r, cb)));
                        ldsm4t(vl, smu32(sVl + SW(r, cb)));
                    }
                    mma_bf(&oc[(2 * cc) * 4], ph, &vh[0]);
                    mma_bf(&oc[(2 * cc) * 4], ph, &vl[0]);
                    mma_bf(&oc[(2 * cc) * 4], pl, &vh[0]);
                    mma_bf(&oc[(2 * cc + 1) * 4], ph, &vh[2]);
                    mma_bf(&oc[(2 * cc + 1) * 4], ph, &vl[2]);
                    mma_bf(&oc[(2 * cc + 1) * 4], pl, &vh[2]);
                }
            }
        }
    }

    if (qi == 0) {
        red[h * 64 + r0] = rmax0;       red[h * 64 + r1] = rmax1;
        red[128 + h * 64 + r0] = rsum0; red[128 + h * 64 + r1] = rsum1;
    }
    __syncthreads();

    float m0a = red[r0], m1a = red[64 + r0];
    float mma_ = fmaxf(m0a, m1a);
    float fh_a = __expf(((h == 0) ? m0a : m1a) - mma_);
    float stot_a = red[128 + r0] * __expf(m0a - mma_) + red[192 + r0] * __expf(m1a - mma_);
    float m0b = red[r1], m1b = red[64 + r1];
    float mmb_ = fmaxf(m0b, m1b);
    float fh_b = __expf(((h == 0) ? m0b : m1b) - mmb_);
    float stot_b = red[128 + r1] * __expf(m0b - mmb_) + red[192 + r1] * __expf(m1b - mmb_);

    float* sO = (float*)sP;
    if (h == 1) {
#pragma unroll
        for (int nt = 0; nt < 8; nt++) {
            int colb = 8 * nt + 2 * qi;
            sO[r0 * 64 + colb]     = oc[nt * 4 + 0] * fh_a;
            sO[r0 * 64 + colb + 1] = oc[nt * 4 + 1] * fh_a;
            sO[r1 * 64 + colb]     = oc[nt * 4 + 2] * fh_b;
            sO[r1 * 64 + colb + 1] = oc[nt * 4 + 3] * fh_b;
        }
    }
    __syncthreads();
    if (h == 0) {
        if (ksplit == 1) {
            float inva = fh_a / stot_a, invb = fh_b / stot_b;
            float ja = 1.f / stot_a, jb = 1.f / stot_b;
#pragma unroll
            for (int nt = 0; nt < 8; nt++) {
                int colb = 8 * nt + 2 * qi;
                if (r0 < nqv) {
                    O[(size_t)(qbase + r0) * 64 + colb]     = oc[nt * 4 + 0] * inva + sO[r0 * 64 + colb] * ja;
                    O[(size_t)(qbase + r0) * 64 + colb + 1] = oc[nt * 4 + 1] * inva + sO[r0 * 64 + colb + 1] * ja;
                }
                if (r1 < nqv) {
                    O[(size_t)(qbase + r1) * 64 + colb]     = oc[nt * 4 + 2] * invb + sO[r1 * 64 + colb] * jb;
                    O[(size_t)(qbase + r1) * 64 + colb + 1] = oc[nt * 4 + 3] * invb + sO[r1 * 64 + colb + 1] * jb;
                }
            }
        } else {
            float* pOo = pO + (size_t)si * CELLS;
            float* pM  = pMS + (size_t)si * 2 * NDMAX;
#pragma unroll
            for (int nt = 0; nt < 8; nt++) {
                int colb = 8 * nt + 2 * qi;
                if (r0 < nqv) {
                    pOo[(size_t)(qbase + r0) * 64 + colb]     = oc[nt * 4 + 0] * fh_a + sO[r0 * 64 + colb];
                    pOo[(size_t)(qbase + r0) * 64 + colb + 1] = oc[nt * 4 + 1] * fh_a + sO[r0 * 64 + colb + 1];
                }
                if (r1 < nqv) {
                    pOo[(size_t)(qbase + r1) * 64 + colb]     = oc[nt * 4 + 2] * fh_b + sO[r1 * 64 + colb];
                    pOo[(size_t)(qbase + r1) * 64 + colb + 1] = oc[nt * 4 + 3] * fh_b + sO[r1 * 64 + colb + 1];
                }
            }
            if (qi == 0) {
                if (r0 < nqv) { pM[(qbase + r0) * 2] = mma_; pM[(qbase + r0) * 2 + 1] = stot_a; }
                if (r1 < nqv) { pM[(qbase + r1) * 2] = mmb_; pM[(qbase + r1) * 2 + 1] = stot_b; }
            }
        }
    }
}

// ---------------------------------------------------------------------------
// BatchNorm pieces
// ---------------------------------------------------------------------------
__global__ void k_bnstats_add(const float* __restrict__ X, const float* __restrict__ Y,
                              float* __restrict__ S, int N)
{
    __shared__ float sh[2][4][64];
    int c = threadIdx.x & 63, rg = threadIdx.x >> 6;
    float s = 0.f, s2 = 0.f;
    for (int r = blockIdx.x * 4 + rg; r < N; r += 256) {
        float v = X[r * 64 + c] + Y[r * 64 + c];
        S[r * 64 + c] = v;
        s += v; s2 += v * v;
    }
    sh[0][rg][c] = s; sh[1][rg][c] = s2;
    __syncthreads();
    if (threadIdx.x < 64) {
        float ts = sh[0][0][c] + sh[0][1][c] + sh[0][2][c] + sh[0][3][c];
        float t2 = sh[1][0][c] + sh[1][1][c] + sh[1][2][c] + sh[1][3][c];
        g_part[blockIdx.x * 128 + c] = ts;
        g_part[blockIdx.x * 128 + 64 + c] = t2;
    }
}

__global__ void k_bnfin(int N, int nblk)
{
    int c = threadIdx.x;
    float s = 0.f, s2 = 0.f;
    for (int b = 0; b < nblk; b++) { s += g_part[b * 128 + c]; s2 += g_part[b * 128 + 64 + c]; }
    float m = s / (float)N;
    float v = s2 / (float)N - m * m;
    g_stats[c] = m;
    g_stats[64 + c] = rsqrtf(v + 1e-4f);
}

__global__ void k_bnapply(const float* __restrict__ X, const float* __restrict__ Res,
                          const float* __restrict__ gamma, const float* __restrict__ beta,
                          float* __restrict__ Out, int N, int mode)
{
    int i = blockIdx.x * blockDim.x + threadIdx.x;
    if (i < N * 64) {
        int c = i & 63;
        float y = (X[i] - g_stats[c]) * g_stats[64 + c] * gamma[c] + beta[c];
        if (mode == 1) y += Res[i];
        if (mode == 2) y = fmaxf(y, 0.f);
        Out[i] = y;
    }
}

__global__ void __launch_bounds__(256) k_bnapply_stats(
    const float* __restrict__ X, const float* __restrict__ Res,
    const float* __restrict__ gamma, const float* __restrict__ beta,
    float* __restrict__ Out, int N, float* __restrict__ part)
{
    __shared__ float sh[2][4][64];
    int c = threadIdx.x & 63, rg = threadIdx.x >> 6;
    int row0 = blockIdx.x * 64;
    float g = gamma[c], be = beta[c];
    float mu = g_stats[c], rs = g_stats[64 + c];
    float s = 0.f, s2 = 0.f;
#pragma unroll
    for (int i = 0; i < 16; i++) {
        int r = row0 + rg + 4 * i;
        if (r < N) {
            float y = (X[r * 64 + c] - mu) * rs * g + be + Res[r * 64 + c];
            Out[r * 64 + c] = y;
            s += y; s2 += y * y;
        }
    }
    sh[0][rg][c] = s; sh[1][rg][c] = s2;
    __syncthreads();
    if (threadIdx.x < 64) {
        float ts = sh[0][0][c] + sh[0][1][c] + sh[0][2][c] + sh[0][3][c];
        float t2 = sh[1][0][c] + sh[1][1][c] + sh[1][2][c] + sh[1][3][c];
        part[blockIdx.x * 128 + c] = ts;
        part[blockIdx.x * 128 + 64 + c] = t2;
    }
}

// ---------------------------------------------------------------------------
extern "C" void kernel_launch(void* const* d_in, const int* in_sizes, int n_in,
                              void* d_out, int out_size)
{
    const float* xdec  = (const float*)d_in[0];
    const float* xenc  = (const float*)d_in[1];
    const float* Wp1   = (const float*)d_in[2];
    const float* Wq    = (const float*)d_in[3];
    const float* Wk    = (const float*)d_in[4];
    const float* Wv    = (const float*)d_in[5];
    const float* Wt    = (const float*)d_in[6];
    const float* Wq1   = (const float*)d_in[7];
    const float* Wk1   = (const float*)d_in[8];
    const float* Wv1   = (const float*)d_in[9];
    const float* Wdown = (const float*)d_in[10];
    const float* W3t   = (const float*)d_in[11];
    const float* W3a   = (const float*)d_in[12];
    const float* W3b   = (const float*)d_in[13];
    const float* gam   = (const float*)d_in[14];
    const float* bet   = (const float*)d_in[15];
    const int* nbr     = (const int*)d_in[16];
    const int* kv_nbr  = (const int*)d_in[17];
    const int* pad_idx = (const int*)d_in[18];

    int nd = in_sizes[0] / 64;
    int ne = in_sizes[1] / 64;
    int lq = in_sizes[18] / NBATCH;
    float* out = (float*)d_out;

    float* base = nullptr;   cudaGetSymbolAddress((void**)&base, g_buf);
    float* pob = nullptr;    cudaGetSymbolAddress((void**)&pob, g_po);
    float* pmsb = nullptr;   cudaGetSymbolAddress((void**)&pmsb, g_pms);
    float* partb = nullptr;  cudaGetSymbolAddress((void**)&partb, g_part);
    float* wcb = nullptr;    cudaGetSymbolAddress((void**)&wcb, g_wc);
    __nv_bfloat16* bfb = nullptr; cudaGetSymbolAddress((void**)&bfb, g_bf);

    float* B[15];
    for (int i = 0; i < 15; i++) B[i] = base + (size_t)i * CELLS;
    __nv_bfloat16* BF[6];
    for (int i = 0; i < 6; i++) BF[i] = bfb + (size_t)i * PADCELLS;

    cudaFuncSetAttribute(k_flash_bf, cudaFuncAttributeMaxDynamicSharedMemorySize, FLASH_SMEM_BF);

    dim3 thr(256);
    int gbd = (nd + 63) / 64;
    int gbe = (ne + 63) / 64;
    int gel = (nd * 64 + 255) / 256;
    int gx = gbd > gbe ? gbd : gbe;

    // ---- Stage 1 ----
    k_wcomp<<<1, thr>>>(Wp1, Wq, wcb);  // Wc = Wp1@Wq  => q = xdec@Wc
    {
        GJobs J = {};
        J.A[0] = xdec; J.W[0] = Wp1; J.C[0] = B[0]; J.N[0] = nd;                         // xd0
        J.A[1] = xdec; J.W[1] = wcb; J.hi[1] = BF[0]; J.lo[1] = BF[1]; J.N[1] = nd;      // q
        J.A[2] = xenc; J.W[2] = Wk;  J.hi[2] = BF[2]; J.lo[2] = BF[3]; J.N[2] = ne;      // ke
        J.A[3] = xenc; J.W[3] = Wv;  J.hi[3] = BF[4]; J.lo[3] = BF[5]; J.N[3] = ne;      // ve
        k_gemm64b<<<dim3(gx, 4), thr>>>(J);
    }
    k_prep<<<1, thr>>>(pad_idx, nd, ne, lq);
    k_flash_bf<<<gbd * KS, thr, FLASH_SMEM_BF>>>(BF[0], BF[1], BF[2], BF[3], BF[4], BF[5],
                                                 B[4], 0, gbd * KS, KS, pob, pmsb);
    k_gemm64m<<<gbd, thr>>>(pob, pmsb, Wt, B[5], nd, partb);     // xr = merge @ Wt (+stats)
    k_bnfin<<<1, 64>>>(nd, gbd);
    // xd = bn(xr)+xd0 (written to B6) ; q1 = xd@Wq1 -> B7 fp32 + BF0/1
    k_gemm64br<<<gbd, thr>>>(B[5], B[0], gam + 0, bet + 0, B[6], Wq1, B[7], nd, BF[0], BF[1]);

    // ---- Stage 2 ----
    k_gconv<<<gbd, thr>>>(B[7], kv_nbr, 8, Wdown, B[8], nd, partb, nullptr, nullptr);
    k_bnfin<<<1, 64>>>(nd, gbd);
    {
        GJobs J = {};
        J.A[0] = B[8]; J.W[0] = Wk1; J.hi[0] = BF[2]; J.lo[0] = BF[3]; J.N[0] = nd;
        J.bg[0] = gam + 64; J.bb[0] = bet + 64;                                           // k1 = bn(kv)@Wk1
        J.A[1] = B[8]; J.W[1] = Wv1; J.hi[1] = BF[4]; J.lo[1] = BF[5]; J.N[1] = nd;
        J.bg[1] = gam + 64; J.bb[1] = bet + 64;                                           // v1
        k_gemm64b<<<dim3(gbd, 2), thr>>>(J);
    }
    int tps = (lq + 63) / 64;
    k_flash_bf<<<NBATCH * tps, thr, FLASH_SMEM_BF>>>(BF[0], BF[1], BF[2], BF[3], BF[4], BF[5],
                                                     B[12], 1, tps, 1, nullptr, nullptr);
    k_gconv<<<gbd, thr>>>(B[12], nbr, 27, W3t, B[13], nd, partb, nullptr, nullptr);
    k_bnfin<<<1, 64>>>(nd, gbd);
    k_bnapply_stats<<<gbd, thr>>>(B[13], B[6], gam + 128, bet + 128, B[14], nd, partb);   // xd2 (+stats)

    // ---- Res block ----
    k_bnfin<<<1, 64>>>(nd, gbd);
    k_gconv<<<gbd, thr>>>(B[14], nbr, 27, W3a, B[1], nd, partb, gam + 192, bet + 192);    // z (+stats), F=relu(bn(xd2))
    k_bnfin<<<1, 64>>>(nd, gbd);
    k_gconv<<<gbd, thr>>>(B[1], nbr, 27, W3b, B[3], nd, nullptr, gam + 256, bet + 256);   // z2, F=relu(bn(z))
    k_bnstats_add<<<64, thr>>>(B[14], B[3], B[4], nd);
    k_bnfin<<<1, 64>>>(nd, 64);
    k_bnapply<<<gel, thr>>>(B[4], B[4], gam + 320, bet + 320, out, nd, 2);
}

// round 9
// speedup vs baseline: 3.2931x; 1.0524x over previous
#include <cuda_runtime.h>
#include <cuda_bf16.h>
#include <math.h>

#define NF 64
#define NBATCH 8
#define NDMAX 12288
#define CELLS (NDMAX * NF)
#define PADCELLS (CELLS + 64 * 64)
#define KS 3

__device__ float g_buf[15][CELLS];
__device__ float g_po[KS][CELLS];
__device__ float g_pms[KS][2 * NDMAX];
__device__ __nv_bfloat16 g_bf[6][PADCELLS];  // Qhi Qlo Khi Klo Vhi Vlo
__device__ float g_stats[128];
__device__ float g_part[256 * 128];
__device__ int   g_seg[64];
__device__ float g_wc[4096];

// ---------------------------------------------------------------------------
// Helpers
// ---------------------------------------------------------------------------
__device__ __forceinline__ int SW(int r, int cb) {
    return r * 128 + (cb ^ ((r & 7) << 4));
}
__device__ __forceinline__ unsigned smu32(const void* p) {
    return (unsigned)__cvta_generic_to_shared(p);
}
__device__ __forceinline__ void cpa16(unsigned dst, const void* src) {
    asm volatile("cp.async.ca.shared.global [%0], [%1], 16;" :: "r"(dst), "l"(src) : "memory");
}
#define CP_COMMIT() asm volatile("cp.async.commit_group;" ::: "memory")
#define CP_WAIT1()  asm volatile("cp.async.wait_group 1;" ::: "memory")

__device__ __forceinline__ void ldsm4(unsigned r[4], unsigned a) {
    asm volatile("ldmatrix.sync.aligned.m8n8.x4.shared.b16 {%0,%1,%2,%3}, [%4];"
                 : "=r"(r[0]), "=r"(r[1]), "=r"(r[2]), "=r"(r[3]) : "r"(a));
}
__device__ __forceinline__ void ldsm4t(unsigned r[4], unsigned a) {
    asm volatile("ldmatrix.sync.aligned.m8n8.x4.trans.shared.b16 {%0,%1,%2,%3}, [%4];"
                 : "=r"(r[0]), "=r"(r[1]), "=r"(r[2]), "=r"(r[3]) : "r"(a));
}
__device__ __forceinline__ void mma_bf(float c[4], const unsigned a[4], const unsigned b[2]) {
    asm volatile(
        "mma.sync.aligned.m16n8k16.row.col.f32.bf16.bf16.f32 "
        "{%0,%1,%2,%3}, {%4,%5,%6,%7}, {%8,%9}, {%0,%1,%2,%3};"
        : "+f"(c[0]), "+f"(c[1]), "+f"(c[2]), "+f"(c[3])
        : "r"(a[0]), "r"(a[1]), "r"(a[2]), "r"(a[3]), "r"(b[0]), "r"(b[1]));
}

__device__ __forceinline__ void bf_split(float v, unsigned short& hb, unsigned short& lb) {
    __nv_bfloat16 h = __float2bfloat16(v);
    hb = __bfloat16_as_ushort(h);
    lb = __bfloat16_as_ushort(__float2bfloat16(v - __bfloat162float(h)));
}

// pack two floats into bf16x2 hi and lo words
__device__ __forceinline__ void bf_split2(float a, float b, unsigned& hw, unsigned& lw) {
    unsigned short ha, la, hb, lb;
    bf_split(a, ha, la);
    bf_split(b, hb, lb);
    hw = (unsigned)ha | ((unsigned)hb << 16);
    lw = (unsigned)la | ((unsigned)lb << 16);
}

// ---------------------------------------------------------------------------
// Composite weight: Wout = W1 @ W2
// ---------------------------------------------------------------------------
__global__ void __launch_bounds__(256) k_wcomp(const float* __restrict__ W1,
                                               const float* __restrict__ W2,
                                               float* __restrict__ Wout)
{
    __shared__ float s1[64 * 64], s2[64 * 64];
    int t = threadIdx.x;
    for (int i = t; i < 4096; i += 256) { s1[i] = W1[i]; s2[i] = W2[i]; }
    __syncthreads();
    int r = t >> 2, c0 = (t & 3) * 16;
    float acc[16];
#pragma unroll
    for (int j = 0; j < 16; j++) acc[j] = 0.f;
    for (int m = 0; m < 64; m++) {
        float a = s1[r * 64 + m];
#pragma unroll
        for (int j = 0; j < 16; j++) acc[j] += a * s2[m * 64 + c0 + j];
    }
#pragma unroll
    for (int j = 0; j < 16; j++) Wout[r * 64 + c0 + j] = acc[j];
}

// ---------------------------------------------------------------------------
// Batched GEMM (up to 4 jobs via blockIdx.y), optional BN on A, bf16 outs.
// ---------------------------------------------------------------------------
struct GJobs {
    const float* A[4];
    const float* W[4];
    float* C[4];
    __nv_bfloat16* hi[4];
    __nv_bfloat16* lo[4];
    const float* bg[4];
    const float* bb[4];
    int N[4];
};

__global__ void __launch_bounds__(256) k_gemm64b(GJobs J)
{
    int jy = blockIdx.y;
    int N = J.N[jy];
    int row0 = blockIdx.x * 64;
    if (row0 >= N) return;
    const float* A = J.A[jy];
    const float* W = J.W[jy];
    float* C = J.C[jy];
    __nv_bfloat16* hi = J.hi[jy];
    __nv_bfloat16* lo = J.lo[jy];
    const float* bg = J.bg[jy];

    __shared__ float sW[64 * 64];
    __shared__ float sA[64 * 65];
    __shared__ float sa[64], sb[64];
    int t = threadIdx.x;
    if (bg && t < 64) {
        float a = g_stats[64 + t] * bg[t];
        sa[t] = a;
        sb[t] = J.bb[jy][t] - g_stats[t] * a;
    }
    if (!bg && t < 64) { sa[t] = 1.f; sb[t] = 0.f; }
    __syncthreads();
    for (int i = t; i < 4096; i += 256) {
        sW[i] = W[i];
        int r = i >> 6, c = i & 63;
        int gr = row0 + r;
        float v = (gr < N) ? A[(size_t)gr * 64 + c] : 0.f;
        sA[r * 65 + c] = v * sa[c] + sb[c];
    }
    __syncthreads();
    int a = t >> 4, b = t & 15;
    float4 acc[4];
#pragma unroll
    for (int i = 0; i < 4; i++) acc[i] = make_float4(0.f, 0.f, 0.f, 0.f);
#pragma unroll 8
    for (int m = 0; m < 64; m++) {
        float4 w = *reinterpret_cast<const float4*>(&sW[m * 64 + 4 * b]);
#pragma unroll
        for (int i = 0; i < 4; i++) {
            float av = sA[(a + 16 * i) * 65 + m];
            acc[i].x += av * w.x; acc[i].y += av * w.y;
            acc[i].z += av * w.z; acc[i].w += av * w.w;
        }
    }
#pragma unroll
    for (int i = 0; i < 4; i++) {
        int gr = row0 + a + 16 * i;
        if (gr < N) {
            if (C) *reinterpret_cast<float4*>(&C[(size_t)gr * 64 + 4 * b]) = acc[i];
            if (hi) {
                float v[4] = { acc[i].x, acc[i].y, acc[i].z, acc[i].w };
                unsigned short hb[4], lb[4];
#pragma unroll
                for (int j = 0; j < 4; j++) bf_split(v[j], hb[j], lb[j]);
                uint2 hp, lp;
                hp.x = (unsigned)hb[0] | ((unsigned)hb[1] << 16);
                hp.y = (unsigned)hb[2] | ((unsigned)hb[3] << 16);
                lp.x = (unsigned)lb[0] | ((unsigned)lb[1] << 16);
                lp.y = (unsigned)lb[2] | ((unsigned)lb[3] << 16);
                *reinterpret_cast<uint2*>(&hi[(size_t)gr * 64 + 4 * b]) = hp;
                *reinterpret_cast<uint2*>(&lo[(size_t)gr * 64 + 4 * b]) = lp;
            }
        }
    }
}

// ---------------------------------------------------------------------------
// GEMM with A = bn(X)+Res computed on load (written to Aout), C + bf16 out.
// ---------------------------------------------------------------------------
__global__ void __launch_bounds__(256) k_gemm64br(
    const float* __restrict__ X, const float* __restrict__ Res,
    const float* __restrict__ bg, const float* __restrict__ bb,
    float* __restrict__ Aout,
    const float* __restrict__ W, float* __restrict__ C, int N,
    __nv_bfloat16* __restrict__ hi, __nv_bfloat16* __restrict__ lo)
{
    __shared__ float sW[64 * 64];
    __shared__ float sA[64 * 65];
    __shared__ float sa[64], sb[64];
    int t = threadIdx.x;
    int row0 = blockIdx.x * 64;
    if (t < 64) {
        float a = g_stats[64 + t] * bg[t];
        sa[t] = a;
        sb[t] = bb[t] - g_stats[t] * a;
    }
    __syncthreads();
    for (int i = t; i < 4096; i += 256) {
        sW[i] = W[i];
        int r = i >> 6, c = i & 63;
        int gr = row0 + r;
        float v = 0.f;
        if (gr < N) {
            v = X[(size_t)gr * 64 + c] * sa[c] + sb[c] + Res[(size_t)gr * 64 + c];
            Aout[(size_t)gr * 64 + c] = v;
        }
        sA[r * 65 + c] = v;
    }
    __syncthreads();
    int a = t >> 4, b = t & 15;
    float4 acc[4];
#pragma unroll
    for (int i = 0; i < 4; i++) acc[i] = make_float4(0.f, 0.f, 0.f, 0.f);
#pragma unroll 8
    for (int m = 0; m < 64; m++) {
        float4 w = *reinterpret_cast<const float4*>(&sW[m * 64 + 4 * b]);
#pragma unroll
        for (int i = 0; i < 4; i++) {
            float av = sA[(a + 16 * i) * 65 + m];
            acc[i].x += av * w.x; acc[i].y += av * w.y;
            acc[i].z += av * w.z; acc[i].w += av * w.w;
        }
    }
#pragma unroll
    for (int i = 0; i < 4; i++) {
        int gr = row0 + a + 16 * i;
        if (gr < N) {
            *reinterpret_cast<float4*>(&C[(size_t)gr * 64 + 4 * b]) = acc[i];
            float v[4] = { acc[i].x, acc[i].y, acc[i].z, acc[i].w };
            unsigned short hb[4], lb[4];
#pragma unroll
            for (int j = 0; j < 4; j++) bf_split(v[j], hb[j], lb[j]);
            uint2 hp, lp;
            hp.x = (unsigned)hb[0] | ((unsigned)hb[1] << 16);
            hp.y = (unsigned)hb[2] | ((unsigned)hb[3] << 16);
            lp.x = (unsigned)lb[0] | ((unsigned)lb[1] << 16);
            lp.y = (unsigned)lb[2] | ((unsigned)lb[3] << 16);
            *reinterpret_cast<uint2*>(&hi[(size_t)gr * 64 + 4 * b]) = hp;
            *reinterpret_cast<uint2*>(&lo[(size_t)gr * 64 + 4 * b]) = lp;
        }
    }
}

// ---------------------------------------------------------------------------
// GEMM with fused split-K merge on A + fused BN partial stats.
// ---------------------------------------------------------------------------
__global__ void __launch_bounds__(256) k_gemm64m(
    const float* __restrict__ pO, const float* __restrict__ pMS,
    const float* __restrict__ W, float* __restrict__ C, int N,
    float* __restrict__ part)
{
    __shared__ float sW[64 * 64];
    __shared__ float sA[64 * 65];
    __shared__ float sRow[64][KS];
    __shared__ float sred[2][16][64];
    int t = threadIdx.x;
    int row0 = blockIdx.x * 64;

    if (t < 64) {
        int gr = row0 + t;
        float m[KS], s[KS];
        if (gr < N) {
#pragma unroll
            for (int i = 0; i < KS; i++) {
                m[i] = pMS[(size_t)i * 2 * NDMAX + gr * 2];
                s[i] = pMS[(size_t)i * 2 * NDMAX + gr * 2 + 1];
            }
            float mx = m[0];
#pragma unroll
            for (int i = 1; i < KS; i++) mx = fmaxf(mx, m[i]);
            float e[KS], denom = 0.f;
#pragma unroll
            for (int i = 0; i < KS; i++) { e[i] = __expf(m[i] - mx); denom += s[i] * e[i]; }
            float inv = 1.f / denom;
#pragma unroll
            for (int i = 0; i < KS; i++) sRow[t][i] = e[i] * inv;
        } else {
#pragma unroll
            for (int i = 0; i < KS; i++) sRow[t][i] = 0.f;
        }
    }
    for (int i = t; i < 4096; i += 256) sW[i] = W[i];
    __syncthreads();
    for (int i = t; i < 4096; i += 256) {
        int r = i >> 6, c = i & 63;
        int gr = row0 + r;
        float v = 0.f;
        if (gr < N) {
#pragma unroll
            for (int k = 0; k < KS; k++)
                v += pO[(size_t)k * CELLS + (size_t)gr * 64 + c] * sRow[r][k];
        }
        sA[r * 65 + c] = v;
    }
    __syncthreads();
    int a = t >> 4, b = t & 15;
    float4 acc[4];
#pragma unroll
    for (int i = 0; i < 4; i++) acc[i] = make_float4(0.f, 0.f, 0.f, 0.f);
#pragma unroll 8
    for (int m = 0; m < 64; m++) {
        float4 w = *reinterpret_cast<const float4*>(&sW[m * 64 + 4 * b]);
#pragma unroll
        for (int i = 0; i < 4; i++) {
            float av = sA[(a + 16 * i) * 65 + m];
            acc[i].x += av * w.x; acc[i].y += av * w.y;
            acc[i].z += av * w.z; acc[i].w += av * w.w;
        }
    }
    float ls[4] = {0.f, 0.f, 0.f, 0.f}, ls2[4] = {0.f, 0.f, 0.f, 0.f};
#pragma unroll
    for (int i = 0; i < 4; i++) {
        int gr = row0 + a + 16 * i;
        if (gr < N) {
            *reinterpret_cast<float4*>(&C[(size_t)gr * 64 + 4 * b]) = acc[i];
            float v[4] = { acc[i].x, acc[i].y, acc[i].z, acc[i].w };
#pragma unroll
            for (int j = 0; j < 4; j++) { ls[j] += v[j]; ls2[j] += v[j] * v[j]; }
        }
    }
#pragma unroll
    for (int j = 0; j < 4; j++) { sred[0][a][4 * b + j] = ls[j]; sred[1][a][4 * b + j] = ls2[j]; }
    __syncthreads();
    if (t < 64) {
        float s = 0.f, s2 = 0.f;
#pragma unroll
        for (int aa = 0; aa < 16; aa++) { s += sred[0][aa][t]; s2 += sred[1][aa][t]; }
        part[blockIdx.x * 128 + t] = s;
        part[blockIdx.x * 128 + 64 + t] = s2;
    }
}

// ---------------------------------------------------------------------------
// Rulebook sparse conv: empty-tap skipping, optional BN+ReLU on gathered input,
// optional fused BN stats on output.
// ---------------------------------------------------------------------------
__global__ void __launch_bounds__(256) k_gconv(
    const float* __restrict__ F, const int* __restrict__ idx, int K,
    const float* __restrict__ W, float* __restrict__ out, int N,
    float* __restrict__ part,
    const float* __restrict__ bg, const float* __restrict__ bb)
{
    __shared__ float sW[64 * 64];
    __shared__ float sF[64 * 68];
    __shared__ int   sIdx[64];
    __shared__ float sred[2][16][64];
    __shared__ float sa[64], sb[64];
    int t = threadIdx.x;
    int row0 = blockIdx.x * 64;
    int a = t >> 4, b = t & 15;
    if (bg && t < 64) {
        float av = g_stats[64 + t] * bg[t];
        sa[t] = av;
        sb[t] = bb[t] - g_stats[t] * av;
    }
    float4 acc[4];
#pragma unroll
    for (int i = 0; i < 4; i++) acc[i] = make_float4(0.f, 0.f, 0.f, 0.f);

    for (int k = 0; k < K; k++) {
        __syncthreads();
        int myvalid = 0;
        if (t < 64) {
            int gr = row0 + t;
            int j = (gr < N) ? idx[gr * K + k] : -1;
            sIdx[t] = j;
            myvalid = (j >= 0);
        }
        if (!__syncthreads_or(myvalid)) continue;
        for (int i = t; i < 4096; i += 256) sW[i] = W[k * 4096 + i];
        {
            int rr = t >> 2;
            int j = sIdx[rr];
            if (j >= 0) {
                int c0 = (t & 3) * 16;
#pragma unroll
                for (int q4 = 0; q4 < 4; q4++) {
                    float4 v = *reinterpret_cast<const float4*>(&F[(size_t)j * 64 + c0 + 4 * q4]);
                    if (bg) {
                        int c = c0 + 4 * q4;
                        v.x = fmaxf(v.x * sa[c] + sb[c], 0.f);
                        v.y = fmaxf(v.y * sa[c + 1] + sb[c + 1], 0.f);
                        v.z = fmaxf(v.z * sa[c + 2] + sb[c + 2], 0.f);
                        v.w = fmaxf(v.w * sa[c + 3] + sb[c + 3], 0.f);
                    }
                    *reinterpret_cast<float4*>(&sF[rr * 68 + c0 + 4 * q4]) = v;
                }
            }
        }
        __syncthreads();
#pragma unroll
        for (int i = 0; i < 4; i++) {
            int r = a + 16 * i;
            if (sIdx[r] >= 0) {
#pragma unroll 8
                for (int m = 0; m < 64; m++) {
                    float av = sF[r * 68 + m];
                    float4 w = *reinterpret_cast<const float4*>(&sW[m * 64 + 4 * b]);
                    acc[i].x += av * w.x; acc[i].y += av * w.y;
                    acc[i].z += av * w.z; acc[i].w += av * w.w;
                }
            }
        }
    }
    float ls[4] = {0.f, 0.f, 0.f, 0.f}, ls2[4] = {0.f, 0.f, 0.f, 0.f};
#pragma unroll
    for (int i = 0; i < 4; i++) {
        int gr = row0 + a + 16 * i;
        if (gr < N) {
            *reinterpret_cast<float4*>(&out[(size_t)gr * 64 + 4 * b]) = acc[i];
            if (part) {
                float v[4] = { acc[i].x, acc[i].y, acc[i].z, acc[i].w };
#pragma unroll
                for (int j = 0; j < 4; j++) { ls[j] += v[j]; ls2[j] += v[j] * v[j]; }
            }
        }
    }
    if (part) {
        __syncthreads();
#pragma unroll
        for (int j = 0; j < 4; j++) { sred[0][a][4 * b + j] = ls[j]; sred[1][a][4 * b + j] = ls2[j]; }
        __syncthreads();
        if (t < 64) {
            float s = 0.f, s2 = 0.f;
#pragma unroll
            for (int aa = 0; aa < 16; aa++) { s += sred[0][aa][t]; s2 += sred[1][aa][t]; }
            part[blockIdx.x * 128 + t] = s;
            part[blockIdx.x * 128 + 64 + t] = s2;
        }
    }
}

// ---------------------------------------------------------------------------
// Segment prep
// ---------------------------------------------------------------------------
__global__ void k_prep(const int* __restrict__ pad_idx, int nd, int ne, int lq)
{
    int t = threadIdx.x;
    int w = t >> 5, lane = t & 31;
    if (w < NBATCH) {
        int cnt = 0;
        for (int l = lane; l < lq; l += 32)
            cnt += (pad_idx[w * lq + l] >= 0) ? 1 : 0;
#pragma unroll
        for (int o = 16; o > 0; o >>= 1) cnt += __shfl_xor_sync(0xffffffffu, cnt, o);
        if (lane == 0) {
            int s = pad_idx[w * lq];
            g_seg[(1 + w) * 4 + 0] = s;
            g_seg[(1 + w) * 4 + 1] = cnt;
            g_seg[(1 + w) * 4 + 2] = s;
            g_seg[(1 + w) * 4 + 3] = cnt;
        }
    }
    if (t == 0) { g_seg[0] = 0; g_seg[1] = nd; g_seg[2] = 0; g_seg[3] = ne; }
}

// ---------------------------------------------------------------------------
// bf16 3x tensor-core flash attention with register-resident P and hoisted Q.
// smem: KV double buffer 64KB | Q hi/lo 16KB (reused as fp32 O staging) | red 1KB
// ---------------------------------------------------------------------------
#define FLASH_SMEM_BF (65536 + 16384 + 1024)

__global__ void __launch_bounds__(256, 2) k_flash_bf(
    const __nv_bfloat16* __restrict__ gQh, const __nv_bfloat16* __restrict__ gQl,
    const __nv_bfloat16* __restrict__ gKh, const __nv_bfloat16* __restrict__ gKl,
    const __nv_bfloat16* __restrict__ gVh, const __nv_bfloat16* __restrict__ gVl,
    float* __restrict__ O, int seg_off, int tiles_per_seg, int ksplit,
    float* __restrict__ pO, float* __restrict__ pMS)
{
    extern __shared__ char smc[];
    char* sKV = smc;
    char* sQ  = smc + 65536;
    float* red = (float*)(smc + 65536 + 16384);

    int bx = blockIdx.x;
    int segi = bx / tiles_per_seg;
    int traw = bx - segi * tiles_per_seg;
    int tile = traw / ksplit;
    int si = traw - tile * ksplit;
    int seg = seg_off + segi;
    int q0 = g_seg[seg * 4 + 0], nq = g_seg[seg * 4 + 1];
    int k0 = g_seg[seg * 4 + 2], nk = g_seg[seg * 4 + 3];
    if (tile * 64 >= nq) return;
    int qbase = q0 + tile * 64;
    int nqv = min(64, nq - tile * 64);

    int nkt_tot = (nk + 63) >> 6;
    int per = (nkt_tot + ksplit - 1) / ksplit;
    int kt0 = si * per;
    int kt1 = min(nkt_tot, kt0 + per);
    int nkt = kt1 - kt0;

    int t = threadIdx.x;
    int w = t >> 5, lane = t & 31;
    int qg = w & 3, h = w >> 2;
    int quad = lane >> 2, qi = lane & 3;
    int r0 = qg * 16 + quad, r1 = r0 + 8;

    float oc[32];
#pragma unroll
    for (int i = 0; i < 32; i++) oc[i] = 0.f;
    float rmax0 = -1e30f, rmax1 = -1e30f, rsum0 = 0.f, rsum1 = 0.f;

    unsigned Qh[4][4], Ql[4][4];

    if (nkt > 0) {
        // Q copy (own group)
        {
#pragma unroll
            for (int j = 0; j < 2; j++) {
                int chunk = t + 256 * j;
                int row = chunk >> 3, jj = chunk & 7;
                cpa16(smu32(sQ + SW(row, jj << 4)),        gQh + (size_t)(qbase + row) * 64 + jj * 8);
                cpa16(smu32(sQ + 8192 + SW(row, jj << 4)), gQl + (size_t)(qbase + row) * 64 + jj * 8);
            }
        }
        CP_COMMIT();
        // KV tile 0
        {
            const __nv_bfloat16* gs[4] = { gKh, gKl, gVh, gVl };
            int kb0 = k0 + kt0 * 64;
#pragma unroll
            for (int a = 0; a < 4; a++)
#pragma unroll
                for (int j = 0; j < 2; j++) {
                    int chunk = t + 256 * j;
                    int row = chunk >> 3, jj = chunk & 7;
                    cpa16(smu32(sKV + a * 8192 + SW(row, jj << 4)),
                          gs[a] + (size_t)(kb0 + row) * 64 + jj * 8);
                }
        }
        CP_COMMIT();
        CP_WAIT1();          // Q group done
        __syncthreads();
        // hoist Q fragments into registers for the whole block
        {
            int r = qg * 16 + (lane & 7) + ((lane & 8) ? 8 : 0);
#pragma unroll
            for (int ch = 0; ch < 4; ch++) {
                int cb = ch * 32 + ((lane & 16) ? 16 : 0);
                ldsm4(Qh[ch], smu32(sQ + SW(r, cb)));
                ldsm4(Ql[ch], smu32(sQ + 8192 + SW(r, cb)));
            }
        }

        for (int kt = 0; kt < nkt; kt++) {
            char* sb = sKV + (kt & 1) * 32768;
            __syncthreads();
            if (kt + 1 < nkt) {
                char* nb = sKV + ((kt + 1) & 1) * 32768;
                int kb = k0 + (kt0 + kt + 1) * 64;
                const __nv_bfloat16* gs[4] = { gKh, gKl, gVh, gVl };
#pragma unroll
                for (int a = 0; a < 4; a++)
#pragma unroll
                    for (int j = 0; j < 2; j++) {
                        int chunk = t + 256 * j;
                        int row = chunk >> 3, jj = chunk & 7;
                        cpa16(smu32(nb + a * 8192 + SW(row, jj << 4)),
                              gs[a] + (size_t)(kb + row) * 64 + jj * 8);
                    }
            }
            CP_COMMIT();
            CP_WAIT1();
            __syncthreads();

            int nkv = min(64, nk - (kt0 + kt) * 64);
            char* sKh = sb;
            char* sKl = sb + 8192;
            char* sVh = sb + 16384;
            char* sVl = sb + 24576;

            // ---- S = Q K^T ----
            float c4[4][4];
#pragma unroll
            for (int nt = 0; nt < 4; nt++)
#pragma unroll
                for (int k = 0; k < 4; k++) c4[nt][k] = 0.f;

#pragma unroll
            for (int ch = 0; ch < 4; ch++) {
                unsigned kh[8], kl[8];
                {
                    int r = 32 * h + (lane & 7) + ((lane & 16) ? 8 : 0);
                    int cb = ch * 32 + ((lane & 8) ? 16 : 0);
                    ldsm4(kh,     smu32(sKh + SW(r, cb)));
                    ldsm4(kh + 4, smu32(sKh + SW(r + 16, cb)));
                    ldsm4(kl,     smu32(sKl + SW(r, cb)));
                    ldsm4(kl + 4, smu32(sKl + SW(r + 16, cb)));
                }
#pragma unroll
                for (int nt = 0; nt < 4; nt++) {
                    mma_bf(c4[nt], Qh[ch], &kh[2 * nt]);
                    mma_bf(c4[nt], Qh[ch], &kl[2 * nt]);
                    mma_bf(c4[nt], Ql[ch], &kh[2 * nt]);
                }
            }

            if (nkv < 64) {
#pragma unroll
                for (int nt = 0; nt < 4; nt++) {
                    int colb = 32 * h + 8 * nt + 2 * qi;
#pragma unroll
                    for (int k = 0; k < 4; k++)
                        if (colb + (k & 1) >= nkv) c4[nt][k] = -1e30f;
                }
            }

            // ---- warp-local online softmax ----
            float mx0 = -1e30f, mx1 = -1e30f;
#pragma unroll
            for (int nt = 0; nt < 4; nt++) {
                mx0 = fmaxf(mx0, fmaxf(c4[nt][0], c4[nt][1]));
                mx1 = fmaxf(mx1, fmaxf(c4[nt][2], c4[nt][3]));
            }
            mx0 = fmaxf(mx0, __shfl_xor_sync(0xffffffffu, mx0, 1));
            mx0 = fmaxf(mx0, __shfl_xor_sync(0xffffffffu, mx0, 2));
            mx1 = fmaxf(mx1, __shfl_xor_sync(0xffffffffu, mx1, 1));
            mx1 = fmaxf(mx1, __shfl_xor_sync(0xffffffffu, mx1, 2));
            float mnew0 = fmaxf(rmax0, mx0);
            float mnew1 = fmaxf(rmax1, mx1);
            float corr0 = __expf(rmax0 - mnew0);
            float corr1 = __expf(rmax1 - mnew1);
            rmax0 = mnew0; rmax1 = mnew1;

            float ps0 = 0.f, ps1 = 0.f;
#pragma unroll
            for (int nt = 0; nt < 4; nt++) {
                float p0 = __expf(c4[nt][0] - mnew0);
                float p1 = __expf(c4[nt][1] - mnew0);
                float p2 = __expf(c4[nt][2] - mnew1);
                float p3 = __expf(c4[nt][3] - mnew1);
                ps0 += p0 + p1; ps1 += p2 + p3;
                c4[nt][0] = p0; c4[nt][1] = p1; c4[nt][2] = p2; c4[nt][3] = p3;
            }
            ps0 += __shfl_xor_sync(0xffffffffu, ps0, 1);
            ps0 += __shfl_xor_sync(0xffffffffu, ps0, 2);
            ps1 += __shfl_xor_sync(0xffffffffu, ps1, 1);
            ps1 += __shfl_xor_sync(0xffffffffu, ps1, 2);
            rsum0 = rsum0 * corr0 + ps0;
            rsum1 = rsum1 * corr1 + ps1;
#pragma unroll
            for (int nt = 0; nt < 8; nt++) {
                oc[nt * 4 + 0] *= corr0; oc[nt * 4 + 1] *= corr0;
                oc[nt * 4 + 2] *= corr1; oc[nt * 4 + 3] *= corr1;
            }

            // ---- O += P V with register-resident P (C-frag == A-frag layout) ----
#pragma unroll
            for (int ck = 0; ck < 2; ck++) {
                unsigned pa_h[4], pa_l[4];
                bf_split2(c4[2 * ck][0],     c4[2 * ck][1],     pa_h[0], pa_l[0]);
                bf_split2(c4[2 * ck][2],     c4[2 * ck][3],     pa_h[1], pa_l[1]);
                bf_split2(c4[2 * ck + 1][0], c4[2 * ck + 1][1], pa_h[2], pa_l[2]);
                bf_split2(c4[2 * ck + 1][2], c4[2 * ck + 1][3], pa_h[3], pa_l[3]);
                int key0 = 32 * h + 16 * ck;
#pragma unroll
                for (int cc = 0; cc < 4; cc++) {
                    unsigned vh[4], vl[4];
                    {
                        int r = key0 + (lane & 7) + ((lane & 8) ? 8 : 0);
                        int cb = cc * 32 + ((lane & 16) ? 16 : 0);
                        ldsm4t(vh, smu32(sVh + SW(r, cb)));
                        ldsm4t(vl, smu32(sVl + SW(r, cb)));
                    }
                    mma_bf(&oc[(2 * cc) * 4], pa_h, &vh[0]);
                    mma_bf(&oc[(2 * cc) * 4], pa_h, &vl[0]);
                    mma_bf(&oc[(2 * cc) * 4], pa_l, &vh[0]);
                    mma_bf(&oc[(2 * cc + 1) * 4], pa_h, &vh[2]);
                    mma_bf(&oc[(2 * cc + 1) * 4], pa_h, &vl[2]);
                    mma_bf(&oc[(2 * cc + 1) * 4], pa_l, &vh[2]);
                }
            }
        }
    }

    // ---- merge halves ----
    if (qi == 0) {
        red[h * 64 + r0] = rmax0;       red[h * 64 + r1] = rmax1;
        red[128 + h * 64 + r0] = rsum0; red[128 + h * 64 + r1] = rsum1;
    }
    __syncthreads();

    float m0a = red[r0], m1a = red[64 + r0];
    float mma_ = fmaxf(m0a, m1a);
    float fh_a = __expf(((h == 0) ? m0a : m1a) - mma_);
    float stot_a = red[128 + r0] * __expf(m0a - mma_) + red[192 + r0] * __expf(m1a - mma_);
    float m0b = red[r1], m1b = red[64 + r1];
    float mmb_ = fmaxf(m0b, m1b);
    float fh_b = __expf(((h == 0) ? m0b : m1b) - mmb_);
    float stot_b = red[128 + r1] * __expf(m0b - mmb_) + red[192 + r1] * __expf(m1b - mmb_);

    float* sO = (float*)sQ;   // Q smem no longer needed (fragments in regs)
    if (h == 1) {
#pragma unroll
        for (int nt = 0; nt < 8; nt++) {
            int colb = 8 * nt + 2 * qi;
            sO[r0 * 64 + colb]     = oc[nt * 4 + 0] * fh_a;
            sO[r0 * 64 + colb + 1] = oc[nt * 4 + 1] * fh_a;
            sO[r1 * 64 + colb]     = oc[nt * 4 + 2] * fh_b;
            sO[r1 * 64 + colb + 1] = oc[nt * 4 + 3] * fh_b;
        }
    }
    __syncthreads();
    if (h == 0) {
        if (ksplit == 1) {
            float inva = fh_a / stot_a, invb = fh_b / stot_b;
            float ja = 1.f / stot_a, jb = 1.f / stot_b;
#pragma unroll
            for (int nt = 0; nt < 8; nt++) {
                int colb = 8 * nt + 2 * qi;
                if (r0 < nqv) {
                    O[(size_t)(qbase + r0) * 64 + colb]     = oc[nt * 4 + 0] * inva + sO[r0 * 64 + colb] * ja;
                    O[(size_t)(qbase + r0) * 64 + colb + 1] = oc[nt * 4 + 1] * inva + sO[r0 * 64 + colb + 1] * ja;
                }
                if (r1 < nqv) {
                    O[(size_t)(qbase + r1) * 64 + colb]     = oc[nt * 4 + 2] * invb + sO[r1 * 64 + colb] * jb;
                    O[(size_t)(qbase + r1) * 64 + colb + 1] = oc[nt * 4 + 3] * invb + sO[r1 * 64 + colb + 1] * jb;
                }
            }
        } else {
            float* pOo = pO + (size_t)si * CELLS;
            float* pM  = pMS + (size_t)si * 2 * NDMAX;
#pragma unroll
            for (int nt = 0; nt < 8; nt++) {
                int colb = 8 * nt + 2 * qi;
                if (r0 < nqv) {
                    pOo[(size_t)(qbase + r0) * 64 + colb]     = oc[nt * 4 + 0] * fh_a + sO[r0 * 64 + colb];
                    pOo[(size_t)(qbase + r0) * 64 + colb + 1] = oc[nt * 4 + 1] * fh_a + sO[r0 * 64 + colb + 1];
                }
                if (r1 < nqv) {
                    pOo[(size_t)(qbase + r1) * 64 + colb]     = oc[nt * 4 + 2] * fh_b + sO[r1 * 64 + colb];
                    pOo[(size_t)(qbase + r1) * 64 + colb + 1] = oc[nt * 4 + 3] * fh_b + sO[r1 * 64 + colb + 1];
                }
            }
            if (qi == 0) {
                if (r0 < nqv) { pM[(qbase + r0) * 2] = mma_; pM[(qbase + r0) * 2 + 1] = stot_a; }
                if (r1 < nqv) { pM[(qbase + r1) * 2] = mmb_; pM[(qbase + r1) * 2 + 1] = stot_b; }
            }
        }
    }
}

// ---------------------------------------------------------------------------
// BatchNorm pieces
// ---------------------------------------------------------------------------
__global__ void k_bnstats_add(const float* __restrict__ X, const float* __restrict__ Y,
                              float* __restrict__ S, int N)
{
    __shared__ float sh[2][4][64];
    int c = threadIdx.x & 63, rg = threadIdx.x >> 6;
    float s = 0.f, s2 = 0.f;
    for (int r = blockIdx.x * 4 + rg; r < N; r += 256) {
        float v = X[r * 64 + c] + Y[r * 64 + c];
        S[r * 64 + c] = v;
        s += v; s2 += v * v;
    }
    sh[0][rg][c] = s; sh[1][rg][c] = s2;
    __syncthreads();
    if (threadIdx.x < 64) {
        float ts = sh[0][0][c] + sh[0][1][c] + sh[0][2][c] + sh[0][3][c];
        float t2 = sh[1][0][c] + sh[1][1][c] + sh[1][2][c] + sh[1][3][c];
        g_part[blockIdx.x * 128 + c] = ts;
        g_part[blockIdx.x * 128 + 64 + c] = t2;
    }
}

__global__ void k_bnfin(int N, int nblk)
{
    int c = threadIdx.x;
    float s = 0.f, s2 = 0.f;
    for (int b = 0; b < nblk; b++) { s += g_part[b * 128 + c]; s2 += g_part[b * 128 + 64 + c]; }
    float m = s / (float)N;
    float v = s2 / (float)N - m * m;
    g_stats[c] = m;
    g_stats[64 + c] = rsqrtf(v + 1e-4f);
}

__global__ void k_bnapply(const float* __restrict__ X, const float* __restrict__ Res,
                          const float* __restrict__ gamma, const float* __restrict__ beta,
                          float* __restrict__ Out, int N, int mode)
{
    int i = blockIdx.x * blockDim.x + threadIdx.x;
    if (i < N * 64) {
        int c = i & 63;
        float y = (X[i] - g_stats[c]) * g_stats[64 + c] * gamma[c] + beta[c];
        if (mode == 1) y += Res[i];
        if (mode == 2) y = fmaxf(y, 0.f);
        Out[i] = y;
    }
}

__global__ void __launch_bounds__(256) k_bnapply_stats(
    const float* __restrict__ X, const float* __restrict__ Res,
    const float* __restrict__ gamma, const float* __restrict__ beta,
    float* __restrict__ Out, int N, float* __restrict__ part)
{
    __shared__ float sh[2][4][64];
    int c = threadIdx.x & 63, rg = threadIdx.x >> 6;
    int row0 = blockIdx.x * 64;
    float g = gamma[c], be = beta[c];
    float mu = g_stats[c], rs = g_stats[64 + c];
    float s = 0.f, s2 = 0.f;
#pragma unroll
    for (int i = 0; i < 16; i++) {
        int r = row0 + rg + 4 * i;
        if (r < N) {
            float y = (X[r * 64 + c] - mu) * rs * g + be + Res[r * 64 + c];
            Out[r * 64 + c] = y;
            s += y; s2 += y * y;
        }
    }
    sh[0][rg][c] = s; sh[1][rg][c] = s2;
    __syncthreads();
    if (threadIdx.x < 64) {
        float ts = sh[0][0][c] + sh[0][1][c] + sh[0][2][c] + sh[0][3][c];
        float t2 = sh[1][0][c] + sh[1][1][c] + sh[1][2][c] + sh[1][3][c];
        part[blockIdx.x * 128 + c] = ts;
        part[blockIdx.x * 128 + 64 + c] = t2;
    }
}

// ---------------------------------------------------------------------------
extern "C" void kernel_launch(void* const* d_in, const int* in_sizes, int n_in,
                              void* d_out, int out_size)
{
    const float* xdec  = (const float*)d_in[0];
    const float* xenc  = (const float*)d_in[1];
    const float* Wp1   = (const float*)d_in[2];
    const float* Wq    = (const float*)d_in[3];
    const float* Wk    = (const float*)d_in[4];
    const float* Wv    = (const float*)d_in[5];
    const float* Wt    = (const float*)d_in[6];
    const float* Wq1   = (const float*)d_in[7];
    const float* Wk1   = (const float*)d_in[8];
    const float* Wv1   = (const float*)d_in[9];
    const float* Wdown = (const float*)d_in[10];
    const float* W3t   = (const float*)d_in[11];
    const float* W3a   = (const float*)d_in[12];
    const float* W3b   = (const float*)d_in[13];
    const float* gam   = (const float*)d_in[14];
    const float* bet   = (const float*)d_in[15];
    const int* nbr     = (const int*)d_in[16];
    const int* kv_nbr  = (const int*)d_in[17];
    const int* pad_idx = (const int*)d_in[18];

    int nd = in_sizes[0] / 64;
    int ne = in_sizes[1] / 64;
    int lq = in_sizes[18] / NBATCH;
    float* out = (float*)d_out;

    float* base = nullptr;   cudaGetSymbolAddress((void**)&base, g_buf);
    float* pob = nullptr;    cudaGetSymbolAddress((void**)&pob, g_po);
    float* pmsb = nullptr;   cudaGetSymbolAddress((void**)&pmsb, g_pms);
    float* partb = nullptr;  cudaGetSymbolAddress((void**)&partb, g_part);
    float* wcb = nullptr;    cudaGetSymbolAddress((void**)&wcb, g_wc);
    __nv_bfloat16* bfb = nullptr; cudaGetSymbolAddress((void**)&bfb, g_bf);

    float* B[15];
    for (int i = 0; i < 15; i++) B[i] = base + (size_t)i * CELLS;
    __nv_bfloat16* BF[6];
    for (int i = 0; i < 6; i++) BF[i] = bfb + (size_t)i * PADCELLS;

    cudaFuncSetAttribute(k_flash_bf, cudaFuncAttributeMaxDynamicSharedMemorySize, FLASH_SMEM_BF);

    dim3 thr(256);
    int gbd = (nd + 63) / 64;
    int gbe = (ne + 63) / 64;
    int gel = (nd * 64 + 255) / 256;
    int gx = gbd > gbe ? gbd : gbe;

    // ---- Stage 1 ----
    k_wcomp<<<1, thr>>>(Wp1, Wq, wcb);  // Wc = Wp1@Wq  => q = xdec@Wc
    {
        GJobs J = {};
        J.A[0] = xdec; J.W[0] = Wp1; J.C[0] = B[0]; J.N[0] = nd;                         // xd0
        J.A[1] = xdec; J.W[1] = wcb; J.hi[1] = BF[0]; J.lo[1] = BF[1]; J.N[1] = nd;      // q
        J.A[2] = xenc; J.W[2] = Wk;  J.hi[2] = BF[2]; J.lo[2] = BF[3]; J.N[2] = ne;      // ke
        J.A[3] = xenc; J.W[3] = Wv;  J.hi[3] = BF[4]; J.lo[3] = BF[5]; J.N[3] = ne;      // ve
        k_gemm64b<<<dim3(gx, 4), thr>>>(J);
    }
    k_prep<<<1, thr>>>(pad_idx, nd, ne, lq);
    k_flash_bf<<<gbd * KS, thr, FLASH_SMEM_BF>>>(BF[0], BF[1], BF[2], BF[3], BF[4], BF[5],
                                                 B[4], 0, gbd * KS, KS, pob, pmsb);
    k_gemm64m<<<gbd, thr>>>(pob, pmsb, Wt, B[5], nd, partb);     // xr = merge @ Wt (+stats)
    k_bnfin<<<1, 64>>>(nd, gbd);
    k_gemm64br<<<gbd, thr>>>(B[5], B[0], gam + 0, bet + 0, B[6], Wq1, B[7], nd, BF[0], BF[1]);

    // ---- Stage 2 ----
    k_gconv<<<gbd, thr>>>(B[7], kv_nbr, 8, Wdown, B[8], nd, partb, nullptr, nullptr);
    k_bnfin<<<1, 64>>>(nd, gbd);
    {
        GJobs J = {};
        J.A[0] = B[8]; J.W[0] = Wk1; J.hi[0] = BF[2]; J.lo[0] = BF[3]; J.N[0] = nd;
        J.bg[0] = gam + 64; J.bb[0] = bet + 64;                                           // k1
        J.A[1] = B[8]; J.W[1] = Wv1; J.hi[1] = BF[4]; J.lo[1] = BF[5]; J.N[1] = nd;
        J.bg[1] = gam + 64; J.bb[1] = bet + 64;                                           // v1
        k_gemm64b<<<dim3(gbd, 2), thr>>>(J);
    }
    int tps = (lq + 63) / 64;
    k_flash_bf<<<NBATCH * tps, thr, FLASH_SMEM_BF>>>(BF[0], BF[1], BF[2], BF[3], BF[4], BF[5],
                                                     B[12], 1, tps, 1, nullptr, nullptr);
    k_gconv<<<gbd, thr>>>(B[12], nbr, 27, W3t, B[13], nd, partb, nullptr, nullptr);
    k_bnfin<<<1, 64>>>(nd, gbd);
    k_bnapply_stats<<<gbd, thr>>>(B[13], B[6], gam + 128, bet + 128, B[14], nd, partb);

    // ---- Res block ----
    k_bnfin<<<1, 64>>>(nd, gbd);
    k_gconv<<<gbd, thr>>>(B[14], nbr, 27, W3a, B[1], nd, partb, gam + 192, bet + 192);
    k_bnfin<<<1, 64>>>(nd, gbd);
    k_gconv<<<gbd, thr>>>(B[1], nbr, 27, W3b, B[3], nd, nullptr, gam + 256, bet + 256);
    k_bnstats_add<<<64, thr>>>(B[14], B[3], B[4], nd);
    k_bnfin<<<1, 64>>>(nd, 64);
    k_bnapply<<<gel, thr>>>(B[4], B[4], gam + 320, bet + 320, out, nd, 2);
}

// round 10
// speedup vs baseline: 3.4574x; 1.0499x over previous
#include <cuda_runtime.h>
#include <cuda_bf16.h>
#include <math.h>

#define NF 64
#define NBATCH 8
#define NDMAX 12288
#define CELLS (NDMAX * NF)
#define PADCELLS (CELLS + 64 * 64)
#define KS 3

__device__ float g_buf[15][CELLS];
__device__ float g_po[KS][CELLS];
__device__ float g_pms[KS][2 * NDMAX];
__device__ __nv_bfloat16 g_bf[6][PADCELLS];  // Qhi Qlo Khi Klo Vhi Vlo
__device__ float g_part[2][256 * 128];       // alternating BN partial buffers
__device__ int   g_seg[64];
__device__ float g_wc[4096];

// ---------------------------------------------------------------------------
// Helpers
// ---------------------------------------------------------------------------
__device__ __forceinline__ int SW(int r, int cb) {
    return r * 128 + (cb ^ ((r & 7) << 4));
}
__device__ __forceinline__ unsigned smu32(const void* p) {
    return (unsigned)__cvta_generic_to_shared(p);
}
__device__ __forceinline__ void cpa16(unsigned dst, const void* src) {
    asm volatile("cp.async.ca.shared.global [%0], [%1], 16;" :: "r"(dst), "l"(src) : "memory");
}
#define CP_COMMIT() asm volatile("cp.async.commit_group;" ::: "memory")
#define CP_WAIT1()  asm volatile("cp.async.wait_group 1;" ::: "memory")

__device__ __forceinline__ void ldsm4(unsigned r[4], unsigned a) {
    asm volatile("ldmatrix.sync.aligned.m8n8.x4.shared.b16 {%0,%1,%2,%3}, [%4];"
                 : "=r"(r[0]), "=r"(r[1]), "=r"(r[2]), "=r"(r[3]) : "r"(a));
}
__device__ __forceinline__ void ldsm4t(unsigned r[4], unsigned a) {
    asm volatile("ldmatrix.sync.aligned.m8n8.x4.trans.shared.b16 {%0,%1,%2,%3}, [%4];"
                 : "=r"(r[0]), "=r"(r[1]), "=r"(r[2]), "=r"(r[3]) : "r"(a));
}
__device__ __forceinline__ void mma_bf(float c[4], const unsigned a[4], const unsigned b[2]) {
    asm volatile(
        "mma.sync.aligned.m16n8k16.row.col.f32.bf16.bf16.f32 "
        "{%0,%1,%2,%3}, {%4,%5,%6,%7}, {%8,%9}, {%0,%1,%2,%3};"
        : "+f"(c[0]), "+f"(c[1]), "+f"(c[2]), "+f"(c[3])
        : "r"(a[0]), "r"(a[1]), "r"(a[2]), "r"(a[3]), "r"(b[0]), "r"(b[1]));
}

__device__ __forceinline__ void bf_split(float v, unsigned short& hb, unsigned short& lb) {
    __nv_bfloat16 h = __float2bfloat16(v);
    hb = __bfloat16_as_ushort(h);
    lb = __bfloat16_as_ushort(__float2bfloat16(v - __bfloat162float(h)));
}
__device__ __forceinline__ void bf_split2(float a, float b, unsigned& hw, unsigned& lw) {
    unsigned short ha, la, hb, lb;
    bf_split(a, ha, la);
    bf_split(b, hb, lb);
    hw = (unsigned)ha | ((unsigned)hb << 16);
    lw = (unsigned)la | ((unsigned)lb << 16);
}

// per-column BN coefficients from partial buffer: y = x*sa + sb
__device__ __forceinline__ void bn_coeff(const float* part, int nblk, int N, int c,
                                         float g, float be, float& A, float& Bc) {
    float s = 0.f, s2 = 0.f;
    for (int b = 0; b < nblk; b++) { s += part[b * 128 + c]; s2 += part[b * 128 + 64 + c]; }
    float mu = s / (float)N;
    float rs = rsqrtf(s2 / (float)N - mu * mu + 1e-4f);
    A = rs * g;
    Bc = be - mu * A;
}

// ---------------------------------------------------------------------------
// Composite weight: Wout = W1 @ W2
// ---------------------------------------------------------------------------
__global__ void __launch_bounds__(256) k_wcomp(const float* __restrict__ W1,
                                               const float* __restrict__ W2,
                                               float* __restrict__ Wout)
{
    __shared__ float s1[64 * 64], s2[64 * 64];
    int t = threadIdx.x;
    for (int i = t; i < 4096; i += 256) { s1[i] = W1[i]; s2[i] = W2[i]; }
    __syncthreads();
    int r = t >> 2, c0 = (t & 3) * 16;
    float acc[16];
#pragma unroll
    for (int j = 0; j < 16; j++) acc[j] = 0.f;
    for (int m = 0; m < 64; m++) {
        float a = s1[r * 64 + m];
#pragma unroll
        for (int j = 0; j < 16; j++) acc[j] += a * s2[m * 64 + c0 + j];
    }
#pragma unroll
    for (int j = 0; j < 16; j++) Wout[r * 64 + c0 + j] = acc[j];
}

// ---------------------------------------------------------------------------
// Batched GEMM (up to 4 jobs via blockIdx.y), optional BN-on-A (in-block
// stats from partial buffer), bf16 outs.
// ---------------------------------------------------------------------------
struct GJobs {
    const float* A[4];
    const float* W[4];
    float* C[4];
    __nv_bfloat16* hi[4];
    __nv_bfloat16* lo[4];
    const float* bg[4];
    const float* bb[4];
    const float* sp[4];   // BN partial buffer (null = no BN)
    int snb[4];
    int N[4];
};

__global__ void __launch_bounds__(256) k_gemm64b(GJobs J)
{
    int jy = blockIdx.y;
    int N = J.N[jy];
    int row0 = blockIdx.x * 64;
    if (row0 >= N) return;
    const float* A = J.A[jy];
    const float* W = J.W[jy];
    float* C = J.C[jy];
    __nv_bfloat16* hi = J.hi[jy];
    __nv_bfloat16* lo = J.lo[jy];
    const float* sp = J.sp[jy];

    __shared__ float sW[64 * 64];
    __shared__ float sA[64 * 65];
    __shared__ float sa[64], sb[64];
    int t = threadIdx.x;
    if (t < 64) {
        if (sp) bn_coeff(sp, J.snb[jy], N, t, J.bg[jy][t], J.bb[jy][t], sa[t], sb[t]);
        else { sa[t] = 1.f; sb[t] = 0.f; }
    }
    __syncthreads();
    for (int i = t; i < 4096; i += 256) {
        sW[i] = W[i];
        int r = i >> 6, c = i & 63;
        int gr = row0 + r;
        float v = (gr < N) ? A[(size_t)gr * 64 + c] : 0.f;
        sA[r * 65 + c] = v * sa[c] + sb[c];
    }
    __syncthreads();
    int a = t >> 4, b = t & 15;
    float4 acc[4];
#pragma unroll
    for (int i = 0; i < 4; i++) acc[i] = make_float4(0.f, 0.f, 0.f, 0.f);
#pragma unroll 8
    for (int m = 0; m < 64; m++) {
        float4 w = *reinterpret_cast<const float4*>(&sW[m * 64 + 4 * b]);
#pragma unroll
        for (int i = 0; i < 4; i++) {
            float av = sA[(a + 16 * i) * 65 + m];
            acc[i].x += av * w.x; acc[i].y += av * w.y;
            acc[i].z += av * w.z; acc[i].w += av * w.w;
        }
    }
#pragma unroll
    for (int i = 0; i < 4; i++) {
        int gr = row0 + a + 16 * i;
        if (gr < N) {
            if (C) *reinterpret_cast<float4*>(&C[(size_t)gr * 64 + 4 * b]) = acc[i];
            if (hi) {
                float v[4] = { acc[i].x, acc[i].y, acc[i].z, acc[i].w };
                unsigned short hb[4], lb[4];
#pragma unroll
                for (int j = 0; j < 4; j++) bf_split(v[j], hb[j], lb[j]);
                uint2 hp, lp;
                hp.x = (unsigned)hb[0] | ((unsigned)hb[1] << 16);
                hp.y = (unsigned)hb[2] | ((unsigned)hb[3] << 16);
                lp.x = (unsigned)lb[0] | ((unsigned)lb[1] << 16);
                lp.y = (unsigned)lb[2] | ((unsigned)lb[3] << 16);
                *reinterpret_cast<uint2*>(&hi[(size_t)gr * 64 + 4 * b]) = hp;
                *reinterpret_cast<uint2*>(&lo[(size_t)gr * 64 + 4 * b]) = lp;
            }
        }
    }
}

// ---------------------------------------------------------------------------
// GEMM with A = bn(X)+Res on load (stats in-block), A written out, C + bf16.
// ---------------------------------------------------------------------------
__global__ void __launch_bounds__(256) k_gemm64br(
    const float* __restrict__ X, const float* __restrict__ Res,
    const float* __restrict__ bg, const float* __restrict__ bb,
    const float* __restrict__ sp, int snb,
    float* __restrict__ Aout,
    const float* __restrict__ W, float* __restrict__ C, int N,
    __nv_bfloat16* __restrict__ hi, __nv_bfloat16* __restrict__ lo)
{
    __shared__ float sW[64 * 64];
    __shared__ float sA[64 * 65];
    __shared__ float sa[64], sb[64];
    int t = threadIdx.x;
    int row0 = blockIdx.x * 64;
    if (t < 64) bn_coeff(sp, snb, N, t, bg[t], bb[t], sa[t], sb[t]);
    __syncthreads();
    for (int i = t; i < 4096; i += 256) {
        sW[i] = W[i];
        int r = i >> 6, c = i & 63;
        int gr = row0 + r;
        float v = 0.f;
        if (gr < N) {
            v = X[(size_t)gr * 64 + c] * sa[c] + sb[c] + Res[(size_t)gr * 64 + c];
            Aout[(size_t)gr * 64 + c] = v;
        }
        sA[r * 65 + c] = v;
    }
    __syncthreads();
    int a = t >> 4, b = t & 15;
    float4 acc[4];
#pragma unroll
    for (int i = 0; i < 4; i++) acc[i] = make_float4(0.f, 0.f, 0.f, 0.f);
#pragma unroll 8
    for (int m = 0; m < 64; m++) {
        float4 w = *reinterpret_cast<const float4*>(&sW[m * 64 + 4 * b]);
#pragma unroll
        for (int i = 0; i < 4; i++) {
            float av = sA[(a + 16 * i) * 65 + m];
            acc[i].x += av * w.x; acc[i].y += av * w.y;
            acc[i].z += av * w.z; acc[i].w += av * w.w;
        }
    }
#pragma unroll
    for (int i = 0; i < 4; i++) {
        int gr = row0 + a + 16 * i;
        if (gr < N) {
            *reinterpret_cast<float4*>(&C[(size_t)gr * 64 + 4 * b]) = acc[i];
            float v[4] = { acc[i].x, acc[i].y, acc[i].z, acc[i].w };
            unsigned short hb[4], lb[4];
#pragma unroll
            for (int j = 0; j < 4; j++) bf_split(v[j], hb[j], lb[j]);
            uint2 hp, lp;
            hp.x = (unsigned)hb[0] | ((unsigned)hb[1] << 16);
            hp.y = (unsigned)hb[2] | ((unsigned)hb[3] << 16);
            lp.x = (unsigned)lb[0] | ((unsigned)lb[1] << 16);
            lp.y = (unsigned)lb[2] | ((unsigned)lb[3] << 16);
            *reinterpret_cast<uint2*>(&hi[(size_t)gr * 64 + 4 * b]) = hp;
            *reinterpret_cast<uint2*>(&lo[(size_t)gr * 64 + 4 * b]) = lp;
        }
    }
}

// ---------------------------------------------------------------------------
// GEMM with fused split-K merge on A + fused BN partial stats.
// ---------------------------------------------------------------------------
__global__ void __launch_bounds__(256) k_gemm64m(
    const float* __restrict__ pO, const float* __restrict__ pMS,
    const float* __restrict__ W, float* __restrict__ C, int N,
    float* __restrict__ part)
{
    __shared__ float sW[64 * 64];
    __shared__ float sA[64 * 65];
    __shared__ float sRow[64][KS];
    __shared__ float sred[2][16][64];
    int t = threadIdx.x;
    int row0 = blockIdx.x * 64;

    if (t < 64) {
        int gr = row0 + t;
        float m[KS], s[KS];
        if (gr < N) {
#pragma unroll
            for (int i = 0; i < KS; i++) {
                m[i] = pMS[(size_t)i * 2 * NDMAX + gr * 2];
                s[i] = pMS[(size_t)i * 2 * NDMAX + gr * 2 + 1];
            }
            float mx = m[0];
#pragma unroll
            for (int i = 1; i < KS; i++) mx = fmaxf(mx, m[i]);
            float e[KS], denom = 0.f;
#pragma unroll
            for (int i = 0; i < KS; i++) { e[i] = __expf(m[i] - mx); denom += s[i] * e[i]; }
            float inv = 1.f / denom;
#pragma unroll
            for (int i = 0; i < KS; i++) sRow[t][i] = e[i] * inv;
        } else {
#pragma unroll
            for (int i = 0; i < KS; i++) sRow[t][i] = 0.f;
        }
    }
    for (int i = t; i < 4096; i += 256) sW[i] = W[i];
    __syncthreads();
    for (int i = t; i < 4096; i += 256) {
        int r = i >> 6, c = i & 63;
        int gr = row0 + r;
        float v = 0.f;
        if (gr < N) {
#pragma unroll
            for (int k = 0; k < KS; k++)
                v += pO[(size_t)k * CELLS + (size_t)gr * 64 + c] * sRow[r][k];
        }
        sA[r * 65 + c] = v;
    }
    __syncthreads();
    int a = t >> 4, b = t & 15;
    float4 acc[4];
#pragma unroll
    for (int i = 0; i < 4; i++) acc[i] = make_float4(0.f, 0.f, 0.f, 0.f);
#pragma unroll 8
    for (int m = 0; m < 64; m++) {
        float4 w = *reinterpret_cast<const float4*>(&sW[m * 64 + 4 * b]);
#pragma unroll
        for (int i = 0; i < 4; i++) {
            float av = sA[(a + 16 * i) * 65 + m];
            acc[i].x += av * w.x; acc[i].y += av * w.y;
            acc[i].z += av * w.z; acc[i].w += av * w.w;
        }
    }
    float ls[4] = {0.f, 0.f, 0.f, 0.f}, ls2[4] = {0.f, 0.f, 0.f, 0.f};
#pragma unroll
    for (int i = 0; i < 4; i++) {
        int gr = row0 + a + 16 * i;
        if (gr < N) {
            *reinterpret_cast<float4*>(&C[(size_t)gr * 64 + 4 * b]) = acc[i];
            float v[4] = { acc[i].x, acc[i].y, acc[i].z, acc[i].w };
#pragma unroll
            for (int j = 0; j < 4; j++) { ls[j] += v[j]; ls2[j] += v[j] * v[j]; }
        }
    }
#pragma unroll
    for (int j = 0; j < 4; j++) { sred[0][a][4 * b + j] = ls[j]; sred[1][a][4 * b + j] = ls2[j]; }
    __syncthreads();
    if (t < 64) {
        float s = 0.f, s2 = 0.f;
#pragma unroll
        for (int aa = 0; aa < 16; aa++) { s += sred[0][aa][t]; s2 += sred[1][aa][t]; }
        part[blockIdx.x * 128 + t] = s;
        part[blockIdx.x * 128 + 64 + t] = s2;
    }
}

// ---------------------------------------------------------------------------
// Pipelined rulebook sparse conv: cp.async double-buffered weights + gathers,
// idx preloaded for all taps, optional BN+ReLU on input (in-block stats),
// optional fused BN stats on output.
// dyn smem: W[2][4096] floats | F[2][64*68] floats
// ---------------------------------------------------------------------------
#define GC_SMEM ((2 * 4096 + 2 * 64 * 68) * 4)

__global__ void __launch_bounds__(256) k_gconv(
    const float* __restrict__ F, const int* __restrict__ idx, int K,
    const float* __restrict__ W, float* __restrict__ out, int N,
    float* __restrict__ outpart,
    const float* __restrict__ statpart, int snb,
    const float* __restrict__ bg, const float* __restrict__ bb)
{
    extern __shared__ float dsm[];
    float* sW2 = dsm;                 // [2][4096]
    float* sF2 = dsm + 2 * 4096;      // [2][64*68]
    __shared__ int sIdxAll[27 * 64];
    __shared__ float sred[2][16][64];
    __shared__ float sa[64], sb[64];
    int t = threadIdx.x;
    int row0 = blockIdx.x * 64;
    int a = t >> 4, b = t & 15;

    if (bg && t < 64) bn_coeff(statpart, snb, N, t, bg[t], bb[t], sa[t], sb[t]);
    for (int i = t; i < 64 * K; i += 256) {
        int r = i / K, k = i - r * K;
        int gr = row0 + r;
        sIdxAll[k * 64 + r] = (gr < N) ? idx[gr * K + k] : -1;
    }
    __syncthreads();

    int rr = t >> 2, c0 = t & 3;
    // prologue: stage 0
    {
        char* wd = (char*)sW2;
        const float* ws = W;
#pragma unroll
        for (int q = 0; q < 4; q++) {
            int c = t + 256 * q;
            cpa16(smu32(wd + c * 16), ws + c * 4);
        }
        int j = sIdxAll[rr];
        if (j >= 0) {
            char* fd = (char*)sF2;
#pragma unroll
            for (int q = 0; q < 4; q++)
                cpa16(smu32(fd + rr * 272 + c0 * 64 + q * 16), F + (size_t)j * 64 + c0 * 16 + q * 4);
        }
    }
    CP_COMMIT();

    float4 acc[4];
#pragma unroll
    for (int i = 0; i < 4; i++) acc[i] = make_float4(0.f, 0.f, 0.f, 0.f);

    for (int k = 0; k < K; k++) {
        __syncthreads();          // prior compute done with the buffer we'll fill
        if (k + 1 < K) {
            int nb = (k + 1) & 1;
            char* wd = (char*)(sW2 + nb * 4096);
            const float* ws = W + (size_t)(k + 1) * 4096;
#pragma unroll
            for (int q = 0; q < 4; q++) {
                int c = t + 256 * q;
                cpa16(smu32(wd + c * 16), ws + c * 4);
            }
            int j = sIdxAll[(k + 1) * 64 + rr];
            if (j >= 0) {
                char* fd = (char*)(sF2 + nb * 4352);
#pragma unroll
                for (int q = 0; q < 4; q++)
                    cpa16(smu32(fd + rr * 272 + c0 * 64 + q * 16), F + (size_t)j * 64 + c0 * 16 + q * 4);
            }
        }
        CP_COMMIT();
        CP_WAIT1();
        __syncthreads();

        int cb = k & 1;
        float* sW = sW2 + cb * 4096;
        float* sF = sF2 + cb * 4352;
        const int* sIdx = sIdxAll + k * 64;

        if (bg) {
            // BN+ReLU transform on valid rows (4 threads/row, 16 floats each)
            int j = sIdx[rr];
            if (j >= 0) {
#pragma unroll
                for (int q = 0; q < 4; q++) {
                    int c = c0 * 16 + q * 4;
                    float4 v = *reinterpret_cast<float4*>(&sF[rr * 68 + c]);
                    v.x = fmaxf(v.x * sa[c] + sb[c], 0.f);
                    v.y = fmaxf(v.y * sa[c + 1] + sb[c + 1], 0.f);
                    v.z = fmaxf(v.z * sa[c + 2] + sb[c + 2], 0.f);
                    v.w = fmaxf(v.w * sa[c + 3] + sb[c + 3], 0.f);
                    *reinterpret_cast<float4*>(&sF[rr * 68 + c]) = v;
                }
            }
            __syncthreads();
        }

#pragma unroll
        for (int i = 0; i < 4; i++) {
            int r = a + 16 * i;
            if (sIdx[r] >= 0) {
#pragma unroll 8
                for (int m = 0; m < 64; m++) {
                    float av = sF[r * 68 + m];
                    float4 w = *reinterpret_cast<const float4*>(&sW[m * 64 + 4 * b]);
                    acc[i].x += av * w.x; acc[i].y += av * w.y;
                    acc[i].z += av * w.z; acc[i].w += av * w.w;
                }
            }
        }
    }

    float ls[4] = {0.f, 0.f, 0.f, 0.f}, ls2[4] = {0.f, 0.f, 0.f, 0.f};
#pragma unroll
    for (int i = 0; i < 4; i++) {
        int gr = row0 + a + 16 * i;
        if (gr < N) {
            *reinterpret_cast<float4*>(&out[(size_t)gr * 64 + 4 * b]) = acc[i];
            if (outpart) {
                float v[4] = { acc[i].x, acc[i].y, acc[i].z, acc[i].w };
#pragma unroll
                for (int j = 0; j < 4; j++) { ls[j] += v[j]; ls2[j] += v[j] * v[j]; }
            }
        }
    }
    if (outpart) {
        __syncthreads();
#pragma unroll
        for (int j = 0; j < 4; j++) { sred[0][a][4 * b + j] = ls[j]; sred[1][a][4 * b + j] = ls2[j]; }
        __syncthreads();
        if (t < 64) {
            float s = 0.f, s2 = 0.f;
#pragma unroll
            for (int aa = 0; aa < 16; aa++) { s += sred[0][aa][t]; s2 += sred[1][aa][t]; }
            outpart[blockIdx.x * 128 + t] = s;
            outpart[blockIdx.x * 128 + 64 + t] = s2;
        }
    }
}

// ---------------------------------------------------------------------------
// Segment prep
// ---------------------------------------------------------------------------
__global__ void k_prep(const int* __restrict__ pad_idx, int nd, int ne, int lq)
{
    int t = threadIdx.x;
    int w = t >> 5, lane = t & 31;
    if (w < NBATCH) {
        int cnt = 0;
        for (int l = lane; l < lq; l += 32)
            cnt += (pad_idx[w * lq + l] >= 0) ? 1 : 0;
#pragma unroll
        for (int o = 16; o > 0; o >>= 1) cnt += __shfl_xor_sync(0xffffffffu, cnt, o);
        if (lane == 0) {
            int s = pad_idx[w * lq];
            g_seg[(1 + w) * 4 + 0] = s;
            g_seg[(1 + w) * 4 + 1] = cnt;
            g_seg[(1 + w) * 4 + 2] = s;
            g_seg[(1 + w) * 4 + 3] = cnt;
        }
    }
    if (t == 0) { g_seg[0] = 0; g_seg[1] = nd; g_seg[2] = 0; g_seg[3] = ne; }
}

// ---------------------------------------------------------------------------
// bf16 3x tensor-core flash attention (unchanged from R8).
// ---------------------------------------------------------------------------
#define FLASH_SMEM_BF (65536 + 16384 + 1024)

__global__ void __launch_bounds__(256, 2) k_flash_bf(
    const __nv_bfloat16* __restrict__ gQh, const __nv_bfloat16* __restrict__ gQl,
    const __nv_bfloat16* __restrict__ gKh, const __nv_bfloat16* __restrict__ gKl,
    const __nv_bfloat16* __restrict__ gVh, const __nv_bfloat16* __restrict__ gVl,
    float* __restrict__ O, int seg_off, int tiles_per_seg, int ksplit,
    float* __restrict__ pO, float* __restrict__ pMS)
{
    extern __shared__ char smc[];
    char* sKV = smc;
    char* sQ  = smc + 65536;
    float* red = (float*)(smc + 65536 + 16384);

    int bx = blockIdx.x;
    int segi = bx / tiles_per_seg;
    int traw = bx - segi * tiles_per_seg;
    int tile = traw / ksplit;
    int si = traw - tile * ksplit;
    int seg = seg_off + segi;
    int q0 = g_seg[seg * 4 + 0], nq = g_seg[seg * 4 + 1];
    int k0 = g_seg[seg * 4 + 2], nk = g_seg[seg * 4 + 3];
    if (tile * 64 >= nq) return;
    int qbase = q0 + tile * 64;
    int nqv = min(64, nq - tile * 64);

    int nkt_tot = (nk + 63) >> 6;
    int per = (nkt_tot + ksplit - 1) / ksplit;
    int kt0 = si * per;
    int kt1 = min(nkt_tot, kt0 + per);
    int nkt = kt1 - kt0;

    int t = threadIdx.x;
    int w = t >> 5, lane = t & 31;
    int qg = w & 3, h = w >> 2;
    int quad = lane >> 2, qi = lane & 3;
    int r0 = qg * 16 + quad, r1 = r0 + 8;

    float oc[32];
#pragma unroll
    for (int i = 0; i < 32; i++) oc[i] = 0.f;
    float rmax0 = -1e30f, rmax1 = -1e30f, rsum0 = 0.f, rsum1 = 0.f;

    unsigned Qh[4][4], Ql[4][4];

    if (nkt > 0) {
        {
#pragma unroll
            for (int j = 0; j < 2; j++) {
                int chunk = t + 256 * j;
                int row = chunk >> 3, jj = chunk & 7;
                cpa16(smu32(sQ + SW(row, jj << 4)),        gQh + (size_t)(qbase + row) * 64 + jj * 8);
                cpa16(smu32(sQ + 8192 + SW(row, jj << 4)), gQl + (size_t)(qbase + row) * 64 + jj * 8);
            }
        }
        CP_COMMIT();
        {
            const __nv_bfloat16* gs[4] = { gKh, gKl, gVh, gVl };
            int kb0 = k0 + kt0 * 64;
#pragma unroll
            for (int a = 0; a < 4; a++)
#pragma unroll
                for (int j = 0; j < 2; j++) {
                    int chunk = t + 256 * j;
                    int row = chunk >> 3, jj = chunk & 7;
                    cpa16(smu32(sKV + a * 8192 + SW(row, jj << 4)),
                          gs[a] + (size_t)(kb0 + row) * 64 + jj * 8);
                }
        }
        CP_COMMIT();
        CP_WAIT1();
        __syncthreads();
        {
            int r = qg * 16 + (lane & 7) + ((lane & 8) ? 8 : 0);
#pragma unroll
            for (int ch = 0; ch < 4; ch++) {
                int cb = ch * 32 + ((lane & 16) ? 16 : 0);
                ldsm4(Qh[ch], smu32(sQ + SW(r, cb)));
                ldsm4(Ql[ch], smu32(sQ + 8192 + SW(r, cb)));
            }
        }

        for (int kt = 0; kt < nkt; kt++) {
            char* sb = sKV + (kt & 1) * 32768;
            __syncthreads();
            if (kt + 1 < nkt) {
                char* nb = sKV + ((kt + 1) & 1) * 32768;
                int kb = k0 + (kt0 + kt + 1) * 64;
                const __nv_bfloat16* gs[4] = { gKh, gKl, gVh, gVl };
#pragma unroll
                for (int a = 0; a < 4; a++)
#pragma unroll
                    for (int j = 0; j < 2; j++) {
                        int chunk = t + 256 * j;
                        int row = chunk >> 3, jj = chunk & 7;
                        cpa16(smu32(nb + a * 8192 + SW(row, jj << 4)),
                              gs[a] + (size_t)(kb + row) * 64 + jj * 8);
                    }
            }
            CP_COMMIT();
            CP_WAIT1();
            __syncthreads();

            int nkv = min(64, nk - (kt0 + kt) * 64);
            char* sKh = sb;
            char* sKl = sb + 8192;
            char* sVh = sb + 16384;
            char* sVl = sb + 24576;

            float c4[4][4];
#pragma unroll
            for (int nt = 0; nt < 4; nt++)
#pragma unroll
                for (int k = 0; k < 4; k++) c4[nt][k] = 0.f;

#pragma unroll
            for (int ch = 0; ch < 4; ch++) {
                unsigned kh[8], kl[8];
                {
                    int r = 32 * h + (lane & 7) + ((lane & 16) ? 8 : 0);
                    int cb = ch * 32 + ((lane & 8) ? 16 : 0);
                    ldsm4(kh,     smu32(sKh + SW(r, cb)));
                    ldsm4(kh + 4, smu32(sKh + SW(r + 16, cb)));
                    ldsm4(kl,     smu32(sKl + SW(r, cb)));
                    ldsm4(kl + 4, smu32(sKl + SW(r + 16, cb)));
                }
#pragma unroll
                for (int nt = 0; nt < 4; nt++) {
                    mma_bf(c4[nt], Qh[ch], &kh[2 * nt]);
                    mma_bf(c4[nt], Qh[ch], &kl[2 * nt]);
                    mma_bf(c4[nt], Ql[ch], &kh[2 * nt]);
                }
            }

            if (nkv < 64) {
#pragma unroll
                for (int nt = 0; nt < 4; nt++) {
                    int colb = 32 * h + 8 * nt + 2 * qi;
#pragma unroll
                    for (int k = 0; k < 4; k++)
                        if (colb + (k & 1) >= nkv) c4[nt][k] = -1e30f;
                }
            }

            float mx0 = -1e30f, mx1 = -1e30f;
#pragma unroll
            for (int nt = 0; nt < 4; nt++) {
                mx0 = fmaxf(mx0, fmaxf(c4[nt][0], c4[nt][1]));
                mx1 = fmaxf(mx1, fmaxf(c4[nt][2], c4[nt][3]));
            }
            mx0 = fmaxf(mx0, __shfl_xor_sync(0xffffffffu, mx0, 1));
            mx0 = fmaxf(mx0, __shfl_xor_sync(0xffffffffu, mx0, 2));
            mx1 = fmaxf(mx1, __shfl_xor_sync(0xffffffffu, mx1, 1));
            mx1 = fmaxf(mx1, __shfl_xor_sync(0xffffffffu, mx1, 2));
            float mnew0 = fmaxf(rmax0, mx0);
            float mnew1 = fmaxf(rmax1, mx1);
            float corr0 = __expf(rmax0 - mnew0);
            float corr1 = __expf(rmax1 - mnew1);
            rmax0 = mnew0; rmax1 = mnew1;

            float ps0 = 0.f, ps1 = 0.f;
#pragma unroll
            for (int nt = 0; nt < 4; nt++) {
                float p0 = __expf(c4[nt][0] - mnew0);
                float p1 = __expf(c4[nt][1] - mnew0);
                float p2 = __expf(c4[nt][2] - mnew1);
                float p3 = __expf(c4[nt][3] - mnew1);
                ps0 += p0 + p1; ps1 += p2 + p3;
                c4[nt][0] = p0; c4[nt][1] = p1; c4[nt][2] = p2; c4[nt][3] = p3;
            }
            ps0 += __shfl_xor_sync(0xffffffffu, ps0, 1);
            ps0 += __shfl_xor_sync(0xffffffffu, ps0, 2);
            ps1 += __shfl_xor_sync(0xffffffffu, ps1, 1);
            ps1 += __shfl_xor_sync(0xffffffffu, ps1, 2);
            rsum0 = rsum0 * corr0 + ps0;
            rsum1 = rsum1 * corr1 + ps1;
#pragma unroll
            for (int nt = 0; nt < 8; nt++) {
                oc[nt * 4 + 0] *= corr0; oc[nt * 4 + 1] *= corr0;
                oc[nt * 4 + 2] *= corr1; oc[nt * 4 + 3] *= corr1;
            }

#pragma unroll
            for (int ck = 0; ck < 2; ck++) {
                unsigned pa_h[4], pa_l[4];
                bf_split2(c4[2 * ck][0],     c4[2 * ck][1],     pa_h[0], pa_l[0]);
                bf_split2(c4[2 * ck][2],     c4[2 * ck][3],     pa_h[1], pa_l[1]);
                bf_split2(c4[2 * ck + 1][0], c4[2 * ck + 1][1], pa_h[2], pa_l[2]);
                bf_split2(c4[2 * ck + 1][2], c4[2 * ck + 1][3], pa_h[3], pa_l[3]);
                int key0 = 32 * h + 16 * ck;
#pragma unroll
                for (int cc = 0; cc < 4; cc++) {
                    unsigned vh[4], vl[4];
                    {
                        int r = key0 + (lane & 7) + ((lane & 8) ? 8 : 0);
                        int cb = cc * 32 + ((lane & 16) ? 16 : 0);
                        ldsm4t(vh, smu32(sVh + SW(r, cb)));
                        ldsm4t(vl, smu32(sVl + SW(r, cb)));
                    }
                    mma_bf(&oc[(2 * cc) * 4], pa_h, &vh[0]);
                    mma_bf(&oc[(2 * cc) * 4], pa_h, &vl[0]);
                    mma_bf(&oc[(2 * cc) * 4], pa_l, &vh[0]);
                    mma_bf(&oc[(2 * cc + 1) * 4], pa_h, &vh[2]);
                    mma_bf(&oc[(2 * cc + 1) * 4], pa_h, &vl[2]);
                    mma_bf(&oc[(2 * cc + 1) * 4], pa_l, &vh[2]);
                }
            }
        }
    }

    if (qi == 0) {
        red[h * 64 + r0] = rmax0;       red[h * 64 + r1] = rmax1;
        red[128 + h * 64 + r0] = rsum0; red[128 + h * 64 + r1] = rsum1;
    }
    __syncthreads();

    float m0a = red[r0], m1a = red[64 + r0];
    float mma_ = fmaxf(m0a, m1a);
    float fh_a = __expf(((h == 0) ? m0a : m1a) - mma_);
    float stot_a = red[128 + r0] * __expf(m0a - mma_) + red[192 + r0] * __expf(m1a - mma_);
    float m0b = red[r1], m1b = red[64 + r1];
    float mmb_ = fmaxf(m0b, m1b);
    float fh_b = __expf(((h == 0) ? m0b : m1b) - mmb_);
    float stot_b = red[128 + r1] * __expf(m0b - mmb_) + red[192 + r1] * __expf(m1b - mmb_);

    float* sO = (float*)sQ;
    if (h == 1) {
#pragma unroll
        for (int nt = 0; nt < 8; nt++) {
            int colb = 8 * nt + 2 * qi;
            sO[r0 * 64 + colb]     = oc[nt * 4 + 0] * fh_a;
            sO[r0 * 64 + colb + 1] = oc[nt * 4 + 1] * fh_a;
            sO[r1 * 64 + colb]     = oc[nt * 4 + 2] * fh_b;
            sO[r1 * 64 + colb + 1] = oc[nt * 4 + 3] * fh_b;
        }
    }
    __syncthreads();
    if (h == 0) {
        if (ksplit == 1) {
            float inva = fh_a / stot_a, invb = fh_b / stot_b;
            float ja = 1.f / stot_a, jb = 1.f / stot_b;
#pragma unroll
            for (int nt = 0; nt < 8; nt++) {
                int colb = 8 * nt + 2 * qi;
                if (r0 < nqv) {
                    O[(size_t)(qbase + r0) * 64 + colb]     = oc[nt * 4 + 0] * inva + sO[r0 * 64 + colb] * ja;
                    O[(size_t)(qbase + r0) * 64 + colb + 1] = oc[nt * 4 + 1] * inva + sO[r0 * 64 + colb + 1] * ja;
                }
                if (r1 < nqv) {
                    O[(size_t)(qbase + r1) * 64 + colb]     = oc[nt * 4 + 2] * invb + sO[r1 * 64 + colb] * jb;
                    O[(size_t)(qbase + r1) * 64 + colb + 1] = oc[nt * 4 + 3] * invb + sO[r1 * 64 + colb + 1] * jb;
                }
            }
        } else {
            float* pOo = pO + (size_t)si * CELLS;
            float* pM  = pMS + (size_t)si * 2 * NDMAX;
#pragma unroll
            for (int nt = 0; nt < 8; nt++) {
                int colb = 8 * nt + 2 * qi;
                if (r0 < nqv) {
                    pOo[(size_t)(qbase + r0) * 64 + colb]     = oc[nt * 4 + 0] * fh_a + sO[r0 * 64 + colb];
                    pOo[(size_t)(qbase + r0) * 64 + colb + 1] = oc[nt * 4 + 1] * fh_a + sO[r0 * 64 + colb + 1];
                }
                if (r1 < nqv) {
                    pOo[(size_t)(qbase + r1) * 64 + colb]     = oc[nt * 4 + 2] * fh_b + sO[r1 * 64 + colb];
                    pOo[(size_t)(qbase + r1) * 64 + colb + 1] = oc[nt * 4 + 3] * fh_b + sO[r1 * 64 + colb + 1];
                }
            }
            if (qi == 0) {
                if (r0 < nqv) { pM[(qbase + r0) * 2] = mma_; pM[(qbase + r0) * 2 + 1] = stot_a; }
                if (r1 < nqv) { pM[(qbase + r1) * 2] = mmb_; pM[(qbase + r1) * 2 + 1] = stot_b; }
            }
        }
    }
}

// ---------------------------------------------------------------------------
// BatchNorm pieces
// ---------------------------------------------------------------------------
__global__ void k_bnstats_add(const float* __restrict__ X, const float* __restrict__ Y,
                              float* __restrict__ S, int N, float* __restrict__ part)
{
    __shared__ float sh[2][4][64];
    int c = threadIdx.x & 63, rg = threadIdx.x >> 6;
    float s = 0.f, s2 = 0.f;
    for (int r = blockIdx.x * 4 + rg; r < N; r += 256) {
        float v = X[r * 64 + c] + Y[r * 64 + c];
        S[r * 64 + c] = v;
        s += v; s2 += v * v;
    }
    sh[0][rg][c] = s; sh[1][rg][c] = s2;
    __syncthreads();
    if (threadIdx.x < 64) {
        float ts = sh[0][0][c] + sh[0][1][c] + sh[0][2][c] + sh[0][3][c];
        float t2 = sh[1][0][c] + sh[1][1][c] + sh[1][2][c] + sh[1][3][c];
        part[blockIdx.x * 128 + c] = ts;
        part[blockIdx.x * 128 + 64 + c] = t2;
    }
}

// bn(x)+res with in-block stats read; writes Out + partials to outpart.
__global__ void __launch_bounds__(256) k_bnapply_stats(
    const float* __restrict__ X, const float* __restrict__ Res,
    const float* __restrict__ gamma, const float* __restrict__ beta,
    const float* __restrict__ sp, int snb,
    float* __restrict__ Out, int N, float* __restrict__ outpart)
{
    __shared__ float sh[2][4][64];
    __shared__ float sa[64], sb[64];
    int c = threadIdx.x & 63, rg = threadIdx.x >> 6;
    int row0 = blockIdx.x * 64;
    if (threadIdx.x < 64) bn_coeff(sp, snb, N, c, gamma[c], beta[c], sa[c], sb[c]);
    __syncthreads();
    float A = sa[c], Bc = sb[c];
    float s = 0.f, s2 = 0.f;
#pragma unroll
    for (int i = 0; i < 16; i++) {
        int r = row0 + rg + 4 * i;
        if (r < N) {
            float y = X[r * 64 + c] * A + Bc + Res[r * 64 + c];
            Out[r * 64 + c] = y;
            s += y; s2 += y * y;
        }
    }
    sh[0][rg][c] = s; sh[1][rg][c] = s2;
    __syncthreads();
    if (threadIdx.x < 64) {
        float ts = sh[0][0][c] + sh[0][1][c] + sh[0][2][c] + sh[0][3][c];
        float t2 = sh[1][0][c] + sh[1][1][c] + sh[1][2][c] + sh[1][3][c];
        outpart[blockIdx.x * 128 + c] = ts;
        outpart[blockIdx.x * 128 + 64 + c] = t2;
    }
}

// final: relu(bn(x)) with in-block stats, row-blocked.
__global__ void __launch_bounds__(256) k_bnapply_fin(
    const float* __restrict__ X,
    const float* __restrict__ gamma, const float* __restrict__ beta,
    const float* __restrict__ sp, int snb,
    float* __restrict__ Out, int N)
{
    __shared__ float sa[64], sb[64];
    int c = threadIdx.x & 63, rg = threadIdx.x >> 6;
    int row0 = blockIdx.x * 64;
    if (threadIdx.x < 64) bn_coeff(sp, snb, N, c, gamma[c], beta[c], sa[c], sb[c]);
    __syncthreads();
    float A = sa[c], Bc = sb[c];
#pragma unroll
    for (int i = 0; i < 16; i++) {
        int r = row0 + rg + 4 * i;
        if (r < N) Out[r * 64 + c] = fmaxf(X[r * 64 + c] * A + Bc, 0.f);
    }
}

// ---------------------------------------------------------------------------
extern "C" void kernel_launch(void* const* d_in, const int* in_sizes, int n_in,
                              void* d_out, int out_size)
{
    const float* xdec  = (const float*)d_in[0];
    const float* xenc  = (const float*)d_in[1];
    const float* Wp1   = (const float*)d_in[2];
    const float* Wq    = (const float*)d_in[3];
    const float* Wk    = (const float*)d_in[4];
    const float* Wv    = (const float*)d_in[5];
    const float* Wt    = (const float*)d_in[6];
    const float* Wq1   = (const float*)d_in[7];
    const float* Wk1   = (const float*)d_in[8];
    const float* Wv1   = (const float*)d_in[9];
    const float* Wdown = (const float*)d_in[10];
    const float* W3t   = (const float*)d_in[11];
    const float* W3a   = (const float*)d_in[12];
    const float* W3b   = (const float*)d_in[13];
    const float* gam   = (const float*)d_in[14];
    const float* bet   = (const float*)d_in[15];
    const int* nbr     = (const int*)d_in[16];
    const int* kv_nbr  = (const int*)d_in[17];
    const int* pad_idx = (const int*)d_in[18];

    int nd = in_sizes[0] / 64;
    int ne = in_sizes[1] / 64;
    int lq = in_sizes[18] / NBATCH;
    float* out = (float*)d_out;

    float* base = nullptr;   cudaGetSymbolAddress((void**)&base, g_buf);
    float* pob = nullptr;    cudaGetSymbolAddress((void**)&pob, g_po);
    float* pmsb = nullptr;   cudaGetSymbolAddress((void**)&pmsb, g_pms);
    float* partb = nullptr;  cudaGetSymbolAddress((void**)&partb, g_part);
    float* wcb = nullptr;    cudaGetSymbolAddress((void**)&wcb, g_wc);
    __nv_bfloat16* bfb = nullptr; cudaGetSymbolAddress((void**)&bfb, g_bf);

    float* B[15];
    for (int i = 0; i < 15; i++) B[i] = base + (size_t)i * CELLS;
    __nv_bfloat16* BF[6];
    for (int i = 0; i < 6; i++) BF[i] = bfb + (size_t)i * PADCELLS;
    float* partA = partb;
    float* partB = partb + 256 * 128;

    cudaFuncSetAttribute(k_flash_bf, cudaFuncAttributeMaxDynamicSharedMemorySize, FLASH_SMEM_BF);
    cudaFuncSetAttribute(k_gconv, cudaFuncAttributeMaxDynamicSharedMemorySize, GC_SMEM);

    dim3 thr(256);
    int gbd = (nd + 63) / 64;
    int gbe = (ne + 63) / 64;
    int gx = gbd > gbe ? gbd : gbe;

    // ---- Stage 1 ----
    k_wcomp<<<1, thr>>>(Wp1, Wq, wcb);
    {
        GJobs J = {};
        J.A[0] = xdec; J.W[0] = Wp1; J.C[0] = B[0]; J.N[0] = nd;
        J.A[1] = xdec; J.W[1] = wcb; J.hi[1] = BF[0]; J.lo[1] = BF[1]; J.N[1] = nd;
        J.A[2] = xenc; J.W[2] = Wk;  J.hi[2] = BF[2]; J.lo[2] = BF[3]; J.N[2] = ne;
        J.A[3] = xenc; J.W[3] = Wv;  J.hi[3] = BF[4]; J.lo[3] = BF[5]; J.N[3] = ne;
        k_gemm64b<<<dim3(gx, 4), thr>>>(J);
    }
    k_prep<<<1, thr>>>(pad_idx, nd, ne, lq);
    k_flash_bf<<<gbd * KS, thr, FLASH_SMEM_BF>>>(BF[0], BF[1], BF[2], BF[3], BF[4], BF[5],
                                                 B[4], 0, gbd * KS, KS, pob, pmsb);
    k_gemm64m<<<gbd, thr>>>(pob, pmsb, Wt, B[5], nd, partA);             // xr (+stats A)
    k_gemm64br<<<gbd, thr>>>(B[5], B[0], gam + 0, bet + 0, partA, gbd,
                             B[6], Wq1, B[7], nd, BF[0], BF[1]);         // xd + q1

    // ---- Stage 2 ----
    k_gconv<<<gbd, thr, GC_SMEM>>>(B[7], kv_nbr, 8, Wdown, B[8], nd,
                                   partA, nullptr, 0, nullptr, nullptr); // kv-pre (+stats A)
    {
        GJobs J = {};
        J.A[0] = B[8]; J.W[0] = Wk1; J.hi[0] = BF[2]; J.lo[0] = BF[3]; J.N[0] = nd;
        J.bg[0] = gam + 64; J.bb[0] = bet + 64; J.sp[0] = partA; J.snb[0] = gbd;
        J.A[1] = B[8]; J.W[1] = Wv1; J.hi[1] = BF[4]; J.lo[1] = BF[5]; J.N[1] = nd;
        J.bg[1] = gam + 64; J.bb[1] = bet + 64; J.sp[1] = partA; J.snb[1] = gbd;
        k_gemm64b<<<dim3(gbd, 2), thr>>>(J);
    }
    int tps = (lq + 63) / 64;
    k_flash_bf<<<NBATCH * tps, thr, FLASH_SMEM_BF>>>(BF[0], BF[1], BF[2], BF[3], BF[4], BF[5],
                                                     B[12], 1, tps, 1, nullptr, nullptr);
    k_gconv<<<gbd, thr, GC_SMEM>>>(B[12], nbr, 27, W3t, B[13], nd,
                                   partA, nullptr, 0, nullptr, nullptr); // xr2 (+stats A)
    k_bnapply_stats<<<gbd, thr>>>(B[13], B[6], gam + 128, bet + 128, partA, gbd,
                                  B[14], nd, partB);                     // xd2 (+stats B)

    // ---- Res block ----
    k_gconv<<<gbd, thr, GC_SMEM>>>(B[14], nbr, 27, W3a, B[1], nd,
                                   partA, partB, gbd, gam + 192, bet + 192); // z1 (+stats A)
    k_gconv<<<gbd, thr, GC_SMEM>>>(B[1], nbr, 27, W3b, B[3], nd,
                                   nullptr, partA, gbd, gam + 256, bet + 256); // z2
    k_bnstats_add<<<64, thr>>>(B[14], B[3], B[4], nd, partA);
    k_bnapply_fin<<<gbd, thr>>>(B[4], gam + 320, bet + 320, partA, 64, out, nd);
}

// round 11
// speedup vs baseline: 3.5257x; 1.0198x over previous
#include <cuda_runtime.h>
#include <cuda_bf16.h>
#include <math.h>

#define NF 64
#define NBATCH 8
#define NDMAX 12288
#define CELLS (NDMAX * NF)
#define PADCELLS (CELLS + 64 * 64)
#define KS 3

__device__ float g_buf[15][CELLS];
__device__ float g_po[KS][CELLS];
__device__ float g_pms[KS][2 * NDMAX];
__device__ __nv_bfloat16 g_bf[6][PADCELLS];   // Qhi Qlo Khi Klo Vhi Vlo
__device__ float g_part[2][256 * 128];        // alternating BN partial buffers
__device__ int   g_seg[64];
__device__ __nv_bfloat16 g_wtb[8 * 8192];     // 8 weight mats, bf16 hi+lo, swizzled

// ---------------------------------------------------------------------------
// Helpers
// ---------------------------------------------------------------------------
__device__ __forceinline__ int SW(int r, int cb) {
    return r * 128 + (cb ^ ((r & 7) << 4));
}
__device__ __forceinline__ unsigned smu32(const void* p) {
    return (unsigned)__cvta_generic_to_shared(p);
}
__device__ __forceinline__ void cpa16(unsigned dst, const void* src) {
    asm volatile("cp.async.ca.shared.global [%0], [%1], 16;" :: "r"(dst), "l"(src) : "memory");
}
#define CP_COMMIT() asm volatile("cp.async.commit_group;" ::: "memory")
#define CP_WAIT1()  asm volatile("cp.async.wait_group 1;" ::: "memory")
#define CP_WAIT0()  asm volatile("cp.async.wait_group 0;" ::: "memory")

__device__ __forceinline__ void ldsm4(unsigned r[4], unsigned a) {
    asm volatile("ldmatrix.sync.aligned.m8n8.x4.shared.b16 {%0,%1,%2,%3}, [%4];"
                 : "=r"(r[0]), "=r"(r[1]), "=r"(r[2]), "=r"(r[3]) : "r"(a));
}
__device__ __forceinline__ void ldsm4t(unsigned r[4], unsigned a) {
    asm volatile("ldmatrix.sync.aligned.m8n8.x4.trans.shared.b16 {%0,%1,%2,%3}, [%4];"
                 : "=r"(r[0]), "=r"(r[1]), "=r"(r[2]), "=r"(r[3]) : "r"(a));
}
__device__ __forceinline__ void mma_bf(float c[4], const unsigned a[4], const unsigned b[2]) {
    asm volatile(
        "mma.sync.aligned.m16n8k16.row.col.f32.bf16.bf16.f32 "
        "{%0,%1,%2,%3}, {%4,%5,%6,%7}, {%8,%9}, {%0,%1,%2,%3};"
        : "+f"(c[0]), "+f"(c[1]), "+f"(c[2]), "+f"(c[3])
        : "r"(a[0]), "r"(a[1]), "r"(a[2]), "r"(a[3]), "r"(b[0]), "r"(b[1]));
}

__device__ __forceinline__ void bf_split(float v, unsigned short& hb, unsigned short& lb) {
    __nv_bfloat16 h = __float2bfloat16(v);
    hb = __bfloat16_as_ushort(h);
    lb = __bfloat16_as_ushort(__float2bfloat16(v - __bfloat162float(h)));
}
__device__ __forceinline__ void bf_split2(float a, float b, unsigned& hw, unsigned& lw) {
    unsigned short ha, la, hb, lb;
    bf_split(a, ha, la);
    bf_split(b, hb, lb);
    hw = (unsigned)ha | ((unsigned)hb << 16);
    lw = (unsigned)la | ((unsigned)lb << 16);
}

// per-column BN coefficients from partial buffer: y = x*A + B
__device__ __forceinline__ void bn_coeff(const float* part, int nblk, int N, int c,
                                         float g, float be, float& A, float& Bc) {
    float s = 0.f, s2 = 0.f;
    for (int b = 0; b < nblk; b++) { s += part[b * 128 + c]; s2 += part[b * 128 + 64 + c]; }
    float mu = s / (float)N;
    float rs = rsqrtf(s2 / (float)N - mu * mu + 1e-4f);
    A = rs * g;
    Bc = be - mu * A;
}

// ---------------------------------------------------------------------------
// Init: blocks 0-7 convert weights to swizzled bf16 hi/lo (block1 computes
// Wc = Wp1@Wq first); block 8 does segment prep.
// slots: 0 Wp1, 1 Wc, 2 Wk, 3 Wv, 4 Wt, 5 Wq1, 6 Wk1, 7 Wv1
// ---------------------------------------------------------------------------
__global__ void __launch_bounds__(256) k_init(
    const float* __restrict__ Wp1, const float* __restrict__ Wq,
    const float* __restrict__ Wk,  const float* __restrict__ Wv,
    const float* __restrict__ Wt,  const float* __restrict__ Wq1,
    const float* __restrict__ Wk1, const float* __restrict__ Wv1,
    const int* __restrict__ pad_idx, int nd, int ne, int lq)
{
    int t = threadIdx.x;
    int blk = blockIdx.x;
    if (blk == 8) {  // segment prep
        int w = t >> 5, lane = t & 31;
        if (w < NBATCH) {
            int cnt = 0;
            for (int l = lane; l < lq; l += 32)
                cnt += (pad_idx[w * lq + l] >= 0) ? 1 : 0;
#pragma unroll
            for (int o = 16; o > 0; o >>= 1) cnt += __shfl_xor_sync(0xffffffffu, cnt, o);
            if (lane == 0) {
                int s = pad_idx[w * lq];
                g_seg[(1 + w) * 4 + 0] = s;
                g_seg[(1 + w) * 4 + 1] = cnt;
                g_seg[(1 + w) * 4 + 2] = s;
                g_seg[(1 + w) * 4 + 3] = cnt;
            }
        }
        if (t == 0) { g_seg[0] = 0; g_seg[1] = nd; g_seg[2] = 0; g_seg[3] = ne; }
        return;
    }

    char* dst = (char*)(g_wtb + (size_t)blk * 8192);

    if (blk == 1) {  // compute Wc = Wp1 @ Wq, then convert
        __shared__ float s1[4096], s2[4096];
        for (int i = t; i < 4096; i += 256) { s1[i] = Wp1[i]; s2[i] = Wq[i]; }
        __syncthreads();
        int r = t >> 2, c0 = (t & 3) * 16;
        float acc[16];
#pragma unroll
        for (int j = 0; j < 16; j++) acc[j] = 0.f;
        for (int m = 0; m < 64; m++) {
            float a = s1[r * 64 + m];
#pragma unroll
            for (int j = 0; j < 16; j++) acc[j] += a * s2[m * 64 + c0 + j];
        }
#pragma unroll
        for (int j = 0; j < 16; j++) {
            unsigned short hb, lb;
            bf_split(acc[j], hb, lb);
            int off = SW(r, (c0 + j) * 2);
            *(unsigned short*)(dst + off) = hb;
            *(unsigned short*)(dst + 8192 + off) = lb;
        }
        return;
    }

    const float* src = Wp1;
    if (blk == 2) src = Wk;
    else if (blk == 3) src = Wv;
    else if (blk == 4) src = Wt;
    else if (blk == 5) src = Wq1;
    else if (blk == 6) src = Wk1;
    else if (blk == 7) src = Wv1;
    for (int e = t; e < 4096; e += 256) {
        int r = e >> 6, c = e & 63;
        unsigned short hb, lb;
        bf_split(src[e], hb, lb);
        int off = SW(r, c * 2);
        *(unsigned short*)(dst + off) = hb;
        *(unsigned short*)(dst + 8192 + off) = lb;
    }
}

// ---------------------------------------------------------------------------
// Unified tensor-core GEMM: C[N,64] = f(A)[N,64] @ W[64,64] (bf16 3x MMA).
// mode 0: A plain; 1: bn(A); 2: bn(X)+Res (writes Aout); 3: split-K merge.
// Optional outputs: C fp32, hi/lo bf16, BN partial stats.
// ---------------------------------------------------------------------------
struct TJob {
    const float* A; const float* Res;
    const float* pO; const float* pMS;
    const __nv_bfloat16* Wbf;
    float* C; float* Aout;
    __nv_bfloat16* hi; __nv_bfloat16* lo;
    const float* bg; const float* bb; const float* sp; int snb;
    float* part; int N; int mode;
};
struct TJobs { TJob j[4]; };

__global__ void __launch_bounds__(256) k_tgemm(TJobs JJ)
{
    TJob J = JJ.j[blockIdx.y];
    int N = J.N;
    int row0 = blockIdx.x * 64;
    if (row0 >= N) return;

    __shared__ char sAh[8192];
    __shared__ char sAl[8192];
    __shared__ char sWb[16384];
    __shared__ float saux[64 * 3];
    __shared__ float sred[2][4][64];
    int t = threadIdx.x;

    // W: raw 16KB copy (already swizzled bf16 hi+lo)
    {
        const char* ws = (const char*)J.Wbf;
#pragma unroll
        for (int q = 0; q < 4; q++) {
            int ch = t + 256 * q;
            cpa16(smu32(sWb + ch * 16), ws + ch * 16);
        }
    }
    CP_COMMIT();

    if (t < 64) {
        if (J.mode == 1 || J.mode == 2) {
            bn_coeff(J.sp, J.snb, N, t, J.bg[t], J.bb[t], saux[t], saux[64 + t]);
        } else if (J.mode == 3) {
            int gr = row0 + t;
            if (gr < N) {
                float m[KS], s[KS];
#pragma unroll
                for (int i = 0; i < KS; i++) {
                    m[i] = J.pMS[(size_t)i * 2 * NDMAX + gr * 2];
                    s[i] = J.pMS[(size_t)i * 2 * NDMAX + gr * 2 + 1];
                }
                float mx = m[0];
#pragma unroll
                for (int i = 1; i < KS; i++) mx = fmaxf(mx, m[i]);
                float e[KS], denom = 0.f;
#pragma unroll
                for (int i = 0; i < KS; i++) { e[i] = __expf(m[i] - mx); denom += s[i] * e[i]; }
                float inv = 1.f / denom;
#pragma unroll
                for (int i = 0; i < KS; i++) saux[i * 64 + t] = e[i] * inv;
            } else {
#pragma unroll
                for (int i = 0; i < KS; i++) saux[i * 64 + t] = 0.f;
            }
        } else {
            saux[t] = 1.f; saux[64 + t] = 0.f;
        }
    }
    __syncthreads();

    // Build A bf16 hi/lo planes
#pragma unroll
    for (int i = 0; i < 16; i++) {
        int e = t + 256 * i;
        int r = e >> 6, c = e & 63;
        int gr = row0 + r;
        float v = 0.f;
        if (gr < N) {
            if (J.mode == 3) {
#pragma unroll
                for (int k = 0; k < KS; k++)
                    v += J.pO[(size_t)k * CELLS + (size_t)gr * 64 + c] * saux[k * 64 + r];
            } else if (J.mode == 2) {
                v = J.A[(size_t)gr * 64 + c] * saux[c] + saux[64 + c] + J.Res[(size_t)gr * 64 + c];
                J.Aout[(size_t)gr * 64 + c] = v;
            } else {
                v = J.A[(size_t)gr * 64 + c] * saux[c] + saux[64 + c];
            }
        }
        unsigned short hb, lb;
        bf_split(v, hb, lb);
        int off = SW(r, c * 2);
        *(unsigned short*)(sAh + off) = hb;
        *(unsigned short*)(sAl + off) = lb;
    }
    CP_WAIT0();
    __syncthreads();

    // MMA: warp (mi = w&3 -> 16 rows, nh = w>>2 -> 32 cols)
    int lane = t & 31, w = t >> 5;
    int mi = w & 3, nh = w >> 2;
    float c4[4][4];
#pragma unroll
    for (int nt = 0; nt < 4; nt++)
#pragma unroll
        for (int k = 0; k < 4; k++) c4[nt][k] = 0.f;

    char* wh = sWb;
    char* wl = sWb + 8192;
#pragma unroll
    for (int ch = 0; ch < 4; ch++) {
        unsigned ah[4], al[4];
        {
            int r = mi * 16 + (lane & 7) + ((lane & 8) ? 8 : 0);
            int cb = ch * 32 + ((lane & 16) ? 16 : 0);
            ldsm4(ah, smu32(sAh + SW(r, cb)));
            ldsm4(al, smu32(sAl + SW(r, cb)));
        }
        unsigned b0h[4], b1h[4], b0l[4], b1l[4];
        {
            int r2 = ch * 16 + (lane & 7) + ((lane & 8) ? 8 : 0);
            int cb0 = (nh * 2 + 0) * 32 + ((lane & 16) ? 16 : 0);
            int cb1 = (nh * 2 + 1) * 32 + ((lane & 16) ? 16 : 0);
            ldsm4t(b0h, smu32(wh + SW(r2, cb0)));
            ldsm4t(b1h, smu32(wh + SW(r2, cb1)));
            ldsm4t(b0l, smu32(wl + SW(r2, cb0)));
            ldsm4t(b1l, smu32(wl + SW(r2, cb1)));
        }
        mma_bf(c4[0], ah, &b0h[0]); mma_bf(c4[0], ah, &b0l[0]); mma_bf(c4[0], al, &b0h[0]);
        mma_bf(c4[1], ah, &b0h[2]); mma_bf(c4[1], ah, &b0l[2]); mma_bf(c4[1], al, &b0h[2]);
        mma_bf(c4[2], ah, &b1h[0]); mma_bf(c4[2], ah, &b1l[0]); mma_bf(c4[2], al, &b1h[0]);
        mma_bf(c4[3], ah, &b1h[2]); mma_bf(c4[3], ah, &b1l[2]); mma_bf(c4[3], al, &b1h[2]);
    }
    __syncthreads();   // sA reads done -> reuse as fp32 staging

    float* sO = (float*)sAh;  // sAh+sAl contiguous 16KB
    int quad = lane >> 2, qi = lane & 3;
    int r0 = mi * 16 + quad, r1 = r0 + 8;
#pragma unroll
    for (int nt = 0; nt < 4; nt++) {
        int colb = nh * 32 + nt * 8 + 2 * qi;
        sO[r0 * 64 + colb]     = c4[nt][0];
        sO[r0 * 64 + colb + 1] = c4[nt][1];
        sO[r1 * 64 + colb]     = c4[nt][2];
        sO[r1 * 64 + colb + 1] = c4[nt][3];
    }
    __syncthreads();

    // epilogue: outputs + stats
    int c = t & 63, rg = t >> 6;
    float s = 0.f, s2 = 0.f;
#pragma unroll
    for (int i = 0; i < 16; i++) {
        int r = rg * 16 + i;
        int gr = row0 + r;
        if (gr < N) {
            float v = sO[r * 64 + c];
            if (J.C) J.C[(size_t)gr * 64 + c] = v;
            if (J.hi) {
                unsigned short hb, lb;
                bf_split(v, hb, lb);
                *(unsigned short*)&J.hi[(size_t)gr * 64 + c] = hb;
                *(unsigned short*)&J.lo[(size_t)gr * 64 + c] = lb;
            }
            s += v; s2 += v * v;
        }
    }
    if (J.part) {
        sred[0][rg][c] = s; sred[1][rg][c] = s2;
        __syncthreads();
        if (t < 64) {
            float ts = sred[0][0][c] + sred[0][1][c] + sred[0][2][c] + sred[0][3][c];
            float t2 = sred[1][0][c] + sred[1][1][c] + sred[1][2][c] + sred[1][3][c];
            J.part[blockIdx.x * 128 + c] = ts;
            J.part[blockIdx.x * 128 + 64 + c] = t2;
        }
    }
}

// ---------------------------------------------------------------------------
// Pipelined rulebook sparse conv (unchanged from R9).
// ---------------------------------------------------------------------------
#define GC_SMEM ((2 * 4096 + 2 * 64 * 68) * 4)

__global__ void __launch_bounds__(256) k_gconv(
    const float* __restrict__ F, const int* __restrict__ idx, int K,
    const float* __restrict__ W, float* __restrict__ out, int N,
    float* __restrict__ outpart,
    const float* __restrict__ statpart, int snb,
    const float* __restrict__ bg, const float* __restrict__ bb)
{
    extern __shared__ float dsm[];
    float* sW2 = dsm;
    float* sF2 = dsm + 2 * 4096;
    __shared__ int sIdxAll[27 * 64];
    __shared__ float sred[2][16][64];
    __shared__ float sa[64], sb[64];
    int t = threadIdx.x;
    int row0 = blockIdx.x * 64;
    int a = t >> 4, b = t & 15;

    if (bg && t < 64) bn_coeff(statpart, snb, N, t, bg[t], bb[t], sa[t], sb[t]);
    for (int i = t; i < 64 * K; i += 256) {
        int r = i / K, k = i - r * K;
        int gr = row0 + r;
        sIdxAll[k * 64 + r] = (gr < N) ? idx[gr * K + k] : -1;
    }
    __syncthreads();

    int rr = t >> 2, c0 = t & 3;
    {
        char* wd = (char*)sW2;
        const float* ws = W;
#pragma unroll
        for (int q = 0; q < 4; q++) {
            int c = t + 256 * q;
            cpa16(smu32(wd + c * 16), ws + c * 4);
        }
        int j = sIdxAll[rr];
        if (j >= 0) {
            char* fd = (char*)sF2;
#pragma unroll
            for (int q = 0; q < 4; q++)
                cpa16(smu32(fd + rr * 272 + c0 * 64 + q * 16), F + (size_t)j * 64 + c0 * 16 + q * 4);
        }
    }
    CP_COMMIT();

    float4 acc[4];
#pragma unroll
    for (int i = 0; i < 4; i++) acc[i] = make_float4(0.f, 0.f, 0.f, 0.f);

    for (int k = 0; k < K; k++) {
        __syncthreads();
        if (k + 1 < K) {
            int nb = (k + 1) & 1;
            char* wd = (char*)(sW2 + nb * 4096);
            const float* ws = W + (size_t)(k + 1) * 4096;
#pragma unroll
            for (int q = 0; q < 4; q++) {
                int c = t + 256 * q;
                cpa16(smu32(wd + c * 16), ws + c * 4);
            }
            int j = sIdxAll[(k + 1) * 64 + rr];
            if (j >= 0) {
                char* fd = (char*)(sF2 + nb * 4352);
#pragma unroll
                for (int q = 0; q < 4; q++)
                    cpa16(smu32(fd + rr * 272 + c0 * 64 + q * 16), F + (size_t)j * 64 + c0 * 16 + q * 4);
            }
        }
        CP_COMMIT();
        CP_WAIT1();
        __syncthreads();

        int cb = k & 1;
        float* sW = sW2 + cb * 4096;
        float* sF = sF2 + cb * 4352;
        const int* sIdx = sIdxAll + k * 64;

        if (bg) {
            int j = sIdx[rr];
            if (j >= 0) {
#pragma unroll
                for (int q = 0; q < 4; q++) {
                    int c = c0 * 16 + q * 4;
                    float4 v = *reinterpret_cast<float4*>(&sF[rr * 68 + c]);
                    v.x = fmaxf(v.x * sa[c] + sb[c], 0.f);
                    v.y = fmaxf(v.y * sa[c + 1] + sb[c + 1], 0.f);
                    v.z = fmaxf(v.z * sa[c + 2] + sb[c + 2], 0.f);
                    v.w = fmaxf(v.w * sa[c + 3] + sb[c + 3], 0.f);
                    *reinterpret_cast<float4*>(&sF[rr * 68 + c]) = v;
                }
            }
            __syncthreads();
        }

#pragma unroll
        for (int i = 0; i < 4; i++) {
            int r = a + 16 * i;
            if (sIdx[r] >= 0) {
#pragma unroll 8
                for (int m = 0; m < 64; m++) {
                    float av = sF[r * 68 + m];
                    float4 w = *reinterpret_cast<const float4*>(&sW[m * 64 + 4 * b]);
                    acc[i].x += av * w.x; acc[i].y += av * w.y;
                    acc[i].z += av * w.z; acc[i].w += av * w.w;
                }
            }
        }
    }

    float ls[4] = {0.f, 0.f, 0.f, 0.f}, ls2[4] = {0.f, 0.f, 0.f, 0.f};
#pragma unroll
    for (int i = 0; i < 4; i++) {
        int gr = row0 + a + 16 * i;
        if (gr < N) {
            *reinterpret_cast<float4*>(&out[(size_t)gr * 64 + 4 * b]) = acc[i];
            if (outpart) {
                float v[4] = { acc[i].x, acc[i].y, acc[i].z, acc[i].w };
#pragma unroll
                for (int j = 0; j < 4; j++) { ls[j] += v[j]; ls2[j] += v[j] * v[j]; }
            }
        }
    }
    if (outpart) {
        __syncthreads();
#pragma unroll
        for (int j = 0; j < 4; j++) { sred[0][a][4 * b + j] = ls[j]; sred[1][a][4 * b + j] = ls2[j]; }
        __syncthreads();
        if (t < 64) {
            float s = 0.f, s2 = 0.f;
#pragma unroll
            for (int aa = 0; aa < 16; aa++) { s += sred[0][aa][t]; s2 += sred[1][aa][t]; }
            outpart[blockIdx.x * 128 + t] = s;
            outpart[blockIdx.x * 128 + 64 + t] = s2;
        }
    }
}

// ---------------------------------------------------------------------------
// bf16 3x tensor-core flash attention (unchanged from R8/R9).
// ---------------------------------------------------------------------------
#define FLASH_SMEM_BF (65536 + 16384 + 1024)

__global__ void __launch_bounds__(256, 2) k_flash_bf(
    const __nv_bfloat16* __restrict__ gQh, const __nv_bfloat16* __restrict__ gQl,
    const __nv_bfloat16* __restrict__ gKh, const __nv_bfloat16* __restrict__ gKl,
    const __nv_bfloat16* __restrict__ gVh, const __nv_bfloat16* __restrict__ gVl,
    float* __restrict__ O, int seg_off, int tiles_per_seg, int ksplit,
    float* __restrict__ pO, float* __restrict__ pMS)
{
    extern __shared__ char smc[];
    char* sKV = smc;
    char* sQ  = smc + 65536;
    float* red = (float*)(smc + 65536 + 16384);

    int bx = blockIdx.x;
    int segi = bx / tiles_per_seg;
    int traw = bx - segi * tiles_per_seg;
    int tile = traw / ksplit;
    int si = traw - tile * ksplit;
    int seg = seg_off + segi;
    int q0 = g_seg[seg * 4 + 0], nq = g_seg[seg * 4 + 1];
    int k0 = g_seg[seg * 4 + 2], nk = g_seg[seg * 4 + 3];
    if (tile * 64 >= nq) return;
    int qbase = q0 + tile * 64;
    int nqv = min(64, nq - tile * 64);

    int nkt_tot = (nk + 63) >> 6;
    int per = (nkt_tot + ksplit - 1) / ksplit;
    int kt0 = si * per;
    int kt1 = min(nkt_tot, kt0 + per);
    int nkt = kt1 - kt0;

    int t = threadIdx.x;
    int w = t >> 5, lane = t & 31;
    int qg = w & 3, h = w >> 2;
    int quad = lane >> 2, qi = lane & 3;
    int r0 = qg * 16 + quad, r1 = r0 + 8;

    float oc[32];
#pragma unroll
    for (int i = 0; i < 32; i++) oc[i] = 0.f;
    float rmax0 = -1e30f, rmax1 = -1e30f, rsum0 = 0.f, rsum1 = 0.f;

    unsigned Qh[4][4], Ql[4][4];

    if (nkt > 0) {
        {
#pragma unroll
            for (int j = 0; j < 2; j++) {
                int chunk = t + 256 * j;
                int row = chunk >> 3, jj = chunk & 7;
                cpa16(smu32(sQ + SW(row, jj << 4)),        gQh + (size_t)(qbase + row) * 64 + jj * 8);
                cpa16(smu32(sQ + 8192 + SW(row, jj << 4)), gQl + (size_t)(qbase + row) * 64 + jj * 8);
            }
        }
        CP_COMMIT();
        {
            const __nv_bfloat16* gs[4] = { gKh, gKl, gVh, gVl };
            int kb0 = k0 + kt0 * 64;
#pragma unroll
            for (int a = 0; a < 4; a++)
#pragma unroll
                for (int j = 0; j < 2; j++) {
                    int chunk = t + 256 * j;
                    int row = chunk >> 3, jj = chunk & 7;
                    cpa16(smu32(sKV + a * 8192 + SW(row, jj << 4)),
                          gs[a] + (size_t)(kb0 + row) * 64 + jj * 8);
                }
        }
        CP_COMMIT();
        CP_WAIT1();
        __syncthreads();
        {
            int r = qg * 16 + (lane & 7) + ((lane & 8) ? 8 : 0);
#pragma unroll
            for (int ch = 0; ch < 4; ch++) {
                int cb = ch * 32 + ((lane & 16) ? 16 : 0);
                ldsm4(Qh[ch], smu32(sQ + SW(r, cb)));
                ldsm4(Ql[ch], smu32(sQ + 8192 + SW(r, cb)));
            }
        }

        for (int kt = 0; kt < nkt; kt++) {
            char* sb = sKV + (kt & 1) * 32768;
            __syncthreads();
            if (kt + 1 < nkt) {
                char* nb = sKV + ((kt + 1) & 1) * 32768;
                int kb = k0 + (kt0 + kt + 1) * 64;
                const __nv_bfloat16* gs[4] = { gKh, gKl, gVh, gVl };
#pragma unroll
                for (int a = 0; a < 4; a++)
#pragma unroll
                    for (int j = 0; j < 2; j++) {
                        int chunk = t + 256 * j;
                        int row = chunk >> 3, jj = chunk & 7;
                        cpa16(smu32(nb + a * 8192 + SW(row, jj << 4)),
                              gs[a] + (size_t)(kb + row) * 64 + jj * 8);
                    }
            }
            CP_COMMIT();
            CP_WAIT1();
            __syncthreads();

            int nkv = min(64, nk - (kt0 + kt) * 64);
            char* sKh = sb;
            char* sKl = sb + 8192;
            char* sVh = sb + 16384;
            char* sVl = sb + 24576;

            float c4[4][4];
#pragma unroll
            for (int nt = 0; nt < 4; nt++)
#pragma unroll
                for (int k = 0; k < 4; k++) c4[nt][k] = 0.f;

#pragma unroll
            for (int ch = 0; ch < 4; ch++) {
                unsigned kh[8], kl[8];
                {
                    int r = 32 * h + (lane & 7) + ((lane & 16) ? 8 : 0);
                    int cb = ch * 32 + ((lane & 8) ? 16 : 0);
                    ldsm4(kh,     smu32(sKh + SW(r, cb)));
                    ldsm4(kh + 4, smu32(sKh + SW(r + 16, cb)));
                    ldsm4(kl,     smu32(sKl + SW(r, cb)));
                    ldsm4(kl + 4, smu32(sKl + SW(r + 16, cb)));
                }
#pragma unroll
                for (int nt = 0; nt < 4; nt++) {
                    mma_bf(c4[nt], Qh[ch], &kh[2 * nt]);
                    mma_bf(c4[nt], Qh[ch], &kl[2 * nt]);
                    mma_bf(c4[nt], Ql[ch], &kh[2 * nt]);
                }
            }

            if (nkv < 64) {
#pragma unroll
                for (int nt = 0; nt < 4; nt++) {
                    int colb = 32 * h + 8 * nt + 2 * qi;
#pragma unroll
                    for (int k = 0; k < 4; k++)
                        if (colb + (k & 1) >= nkv) c4[nt][k] = -1e30f;
                }
            }

            float mx0 = -1e30f, mx1 = -1e30f;
#pragma unroll
            for (int nt = 0; nt < 4; nt++) {
                mx0 = fmaxf(mx0, fmaxf(c4[nt][0], c4[nt][1]));
                mx1 = fmaxf(mx1, fmaxf(c4[nt][2], c4[nt][3]));
            }
            mx0 = fmaxf(mx0, __shfl_xor_sync(0xffffffffu, mx0, 1));
            mx0 = fmaxf(mx0, __shfl_xor_sync(0xffffffffu, mx0, 2));
            mx1 = fmaxf(mx1, __shfl_xor_sync(0xffffffffu, mx1, 1));
            mx1 = fmaxf(mx1, __shfl_xor_sync(0xffffffffu, mx1, 2));
            float mnew0 = fmaxf(rmax0, mx0);
            float mnew1 = fmaxf(rmax1, mx1);
            float corr0 = __expf(rmax0 - mnew0);
            float corr1 = __expf(rmax1 - mnew1);
            rmax0 = mnew0; rmax1 = mnew1;

            float ps0 = 0.f, ps1 = 0.f;
#pragma unroll
            for (int nt = 0; nt < 4; nt++) {
                float p0 = __expf(c4[nt][0] - mnew0);
                float p1 = __expf(c4[nt][1] - mnew0);
                float p2 = __expf(c4[nt][2] - mnew1);
                float p3 = __expf(c4[nt][3] - mnew1);
                ps0 += p0 + p1; ps1 += p2 + p3;
                c4[nt][0] = p0; c4[nt][1] = p1; c4[nt][2] = p2; c4[nt][3] = p3;
            }
            ps0 += __shfl_xor_sync(0xffffffffu, ps0, 1);
            ps0 += __shfl_xor_sync(0xffffffffu, ps0, 2);
            ps1 += __shfl_xor_sync(0xffffffffu, ps1, 1);
            ps1 += __shfl_xor_sync(0xffffffffu, ps1, 2);
            rsum0 = rsum0 * corr0 + ps0;
            rsum1 = rsum1 * corr1 + ps1;
#pragma unroll
            for (int nt = 0; nt < 8; nt++) {
                oc[nt * 4 + 0] *= corr0; oc[nt * 4 + 1] *= corr0;
                oc[nt * 4 + 2] *= corr1; oc[nt * 4 + 3] *= corr1;
            }

#pragma unroll
            for (int ck = 0; ck < 2; ck++) {
                unsigned pa_h[4], pa_l[4];
                bf_split2(c4[2 * ck][0],     c4[2 * ck][1],     pa_h[0], pa_l[0]);
                bf_split2(c4[2 * ck][2],     c4[2 * ck][3],     pa_h[1], pa_l[1]);
                bf_split2(c4[2 * ck + 1][0], c4[2 * ck + 1][1], pa_h[2], pa_l[2]);
                bf_split2(c4[2 * ck + 1][2], c4[2 * ck + 1][3], pa_h[3], pa_l[3]);
                int key0 = 32 * h + 16 * ck;
#pragma unroll
                for (int cc = 0; cc < 4; cc++) {
                    unsigned vh[4], vl[4];
                    {
                        int r = key0 + (lane & 7) + ((lane & 8) ? 8 : 0);
                        int cb = cc * 32 + ((lane & 16) ? 16 : 0);
                        ldsm4t(vh, smu32(sVh + SW(r, cb)));
                        ldsm4t(vl, smu32(sVl + SW(r, cb)));
                    }
                    mma_bf(&oc[(2 * cc) * 4], pa_h, &vh[0]);
                    mma_bf(&oc[(2 * cc) * 4], pa_h, &vl[0]);
                    mma_bf(&oc[(2 * cc) * 4], pa_l, &vh[0]);
                    mma_bf(&oc[(2 * cc + 1) * 4], pa_h, &vh[2]);
                    mma_bf(&oc[(2 * cc + 1) * 4], pa_h, &vl[2]);
                    mma_bf(&oc[(2 * cc + 1) * 4], pa_l, &vh[2]);
                }
            }
        }
    }

    if (qi == 0) {
        red[h * 64 + r0] = rmax0;       red[h * 64 + r1] = rmax1;
        red[128 + h * 64 + r0] = rsum0; red[128 + h * 64 + r1] = rsum1;
    }
    __syncthreads();

    float m0a = red[r0], m1a = red[64 + r0];
    float mma_ = fmaxf(m0a, m1a);
    float fh_a = __expf(((h == 0) ? m0a : m1a) - mma_);
    float stot_a = red[128 + r0] * __expf(m0a - mma_) + red[192 + r0] * __expf(m1a - mma_);
    float m0b = red[r1], m1b = red[64 + r1];
    float mmb_ = fmaxf(m0b, m1b);
    float fh_b = __expf(((h == 0) ? m0b : m1b) - mmb_);
    float stot_b = red[128 + r1] * __expf(m0b - mmb_) + red[192 + r1] * __expf(m1b - mmb_);

    float* sO = (float*)sQ;
    if (h == 1) {
#pragma unroll
        for (int nt = 0; nt < 8; nt++) {
            int colb = 8 * nt + 2 * qi;
            sO[r0 * 64 + colb]     = oc[nt * 4 + 0] * fh_a;
            sO[r0 * 64 + colb + 1] = oc[nt * 4 + 1] * fh_a;
            sO[r1 * 64 + colb]     = oc[nt * 4 + 2] * fh_b;
            sO[r1 * 64 + colb + 1] = oc[nt * 4 + 3] * fh_b;
        }
    }
    __syncthreads();
    if (h == 0) {
        if (ksplit == 1) {
            float inva = fh_a / stot_a, invb = fh_b / stot_b;
            float ja = 1.f / stot_a, jb = 1.f / stot_b;
#pragma unroll
            for (int nt = 0; nt < 8; nt++) {
                int colb = 8 * nt + 2 * qi;
                if (r0 < nqv) {
                    O[(size_t)(qbase + r0) * 64 + colb]     = oc[nt * 4 + 0] * inva + sO[r0 * 64 + colb] * ja;
                    O[(size_t)(qbase + r0) * 64 + colb + 1] = oc[nt * 4 + 1] * inva + sO[r0 * 64 + colb + 1] * ja;
                }
                if (r1 < nqv) {
                    O[(size_t)(qbase + r1) * 64 + colb]     = oc[nt * 4 + 2] * invb + sO[r1 * 64 + colb] * jb;
                    O[(size_t)(qbase + r1) * 64 + colb + 1] = oc[nt * 4 + 3] * invb + sO[r1 * 64 + colb + 1] * jb;
                }
            }
        } else {
            float* pOo = pO + (size_t)si * CELLS;
            float* pM  = pMS + (size_t)si * 2 * NDMAX;
#pragma unroll
            for (int nt = 0; nt < 8; nt++) {
                int colb = 8 * nt + 2 * qi;
                if (r0 < nqv) {
                    pOo[(size_t)(qbase + r0) * 64 + colb]     = oc[nt * 4 + 0] * fh_a + sO[r0 * 64 + colb];
                    pOo[(size_t)(qbase + r0) * 64 + colb + 1] = oc[nt * 4 + 1] * fh_a + sO[r0 * 64 + colb + 1];
                }
                if (r1 < nqv) {
                    pOo[(size_t)(qbase + r1) * 64 + colb]     = oc[nt * 4 + 2] * fh_b + sO[r1 * 64 + colb];
                    pOo[(size_t)(qbase + r1) * 64 + colb + 1] = oc[nt * 4 + 3] * fh_b + sO[r1 * 64 + colb + 1];
                }
            }
            if (qi == 0) {
                if (r0 < nqv) { pM[(qbase + r0) * 2] = mma_; pM[(qbase + r0) * 2 + 1] = stot_a; }
                if (r1 < nqv) { pM[(qbase + r1) * 2] = mmb_; pM[(qbase + r1) * 2 + 1] = stot_b; }
            }
        }
    }
}

// ---------------------------------------------------------------------------
// BatchNorm pieces (unchanged from R9)
// ---------------------------------------------------------------------------
__global__ void k_bnstats_add(const float* __restrict__ X, const float* __restrict__ Y,
                              float* __restrict__ S, int N, float* __restrict__ part)
{
    __shared__ float sh[2][4][64];
    int c = threadIdx.x & 63, rg = threadIdx.x >> 6;
    float s = 0.f, s2 = 0.f;
    for (int r = blockIdx.x * 4 + rg; r < N; r += 256) {
        float v = X[r * 64 + c] + Y[r * 64 + c];
        S[r * 64 + c] = v;
        s += v; s2 += v * v;
    }
    sh[0][rg][c] = s; sh[1][rg][c] = s2;
    __syncthreads();
    if (threadIdx.x < 64) {
        float ts = sh[0][0][c] + sh[0][1][c] + sh[0][2][c] + sh[0][3][c];
        float t2 = sh[1][0][c] + sh[1][1][c] + sh[1][2][c] + sh[1][3][c];
        part[blockIdx.x * 128 + c] = ts;
        part[blockIdx.x * 128 + 64 + c] = t2;
    }
}

__global__ void __launch_bounds__(256) k_bnapply_stats(
    const float* __restrict__ X, const float* __restrict__ Res,
    const float* __restrict__ gamma, const float* __restrict__ beta,
    const float* __restrict__ sp, int snb,
    float* __restrict__ Out, int N, float* __restrict__ outpart)
{
    __shared__ float sh[2][4][64];
    __shared__ float sa[64], sb[64];
    int c = threadIdx.x & 63, rg = threadIdx.x >> 6;
    int row0 = blockIdx.x * 64;
    if (threadIdx.x < 64) bn_coeff(sp, snb, N, c, gamma[c], beta[c], sa[c], sb[c]);
    __syncthreads();
    float A = sa[c], Bc = sb[c];
    float s = 0.f, s2 = 0.f;
#pragma unroll
    for (int i = 0; i < 16; i++) {
        int r = row0 + rg + 4 * i;
        if (r < N) {
            float y = X[r * 64 + c] * A + Bc + Res[r * 64 + c];
            Out[r * 64 + c] = y;
            s += y; s2 += y * y;
        }
    }
    sh[0][rg][c] = s; sh[1][rg][c] = s2;
    __syncthreads();
    if (threadIdx.x < 64) {
        float ts = sh[0][0][c] + sh[0][1][c] + sh[0][2][c] + sh[0][3][c];
        float t2 = sh[1][0][c] + sh[1][1][c] + sh[1][2][c] + sh[1][3][c];
        outpart[blockIdx.x * 128 + c] = ts;
        outpart[blockIdx.x * 128 + 64 + c] = t2;
    }
}

__global__ void __launch_bounds__(256) k_bnapply_fin(
    const float* __restrict__ X,
    const float* __restrict__ gamma, const float* __restrict__ beta,
    const float* __restrict__ sp, int snb,
    float* __restrict__ Out, int N)
{
    __shared__ float sa[64], sb[64];
    int c = threadIdx.x & 63, rg = threadIdx.x >> 6;
    int row0 = blockIdx.x * 64;
    if (threadIdx.x < 64) bn_coeff(sp, snb, N, c, gamma[c], beta[c], sa[c], sb[c]);
    __syncthreads();
    float A = sa[c], Bc = sb[c];
#pragma unroll
    for (int i = 0; i < 16; i++) {
        int r = row0 + rg + 4 * i;
        if (r < N) Out[r * 64 + c] = fmaxf(X[r * 64 + c] * A + Bc, 0.f);
    }
}

// ---------------------------------------------------------------------------
extern "C" void kernel_launch(void* const* d_in, const int* in_sizes, int n_in,
                              void* d_out, int out_size)
{
    const float* xdec  = (const float*)d_in[0];
    const float* xenc  = (const float*)d_in[1];
    const float* Wp1   = (const float*)d_in[2];
    const float* Wq    = (const float*)d_in[3];
    const float* Wk    = (const float*)d_in[4];
    const float* Wv    = (const float*)d_in[5];
    const float* Wt    = (const float*)d_in[6];
    const float* Wq1   = (const float*)d_in[7];
    const float* Wk1   = (const float*)d_in[8];
    const float* Wv1   = (const float*)d_in[9];
    const float* Wdown = (const float*)d_in[10];
    const float* W3t   = (const float*)d_in[11];
    const float* W3a   = (const float*)d_in[12];
    const float* W3b   = (const float*)d_in[13];
    const float* gam   = (const float*)d_in[14];
    const float* bet   = (const float*)d_in[15];
    const int* nbr     = (const int*)d_in[16];
    const int* kv_nbr  = (const int*)d_in[17];
    const int* pad_idx = (const int*)d_in[18];

    int nd = in_sizes[0] / 64;
    int ne = in_sizes[1] / 64;
    int lq = in_sizes[18] / NBATCH;
    float* out = (float*)d_out;

    float* base = nullptr;   cudaGetSymbolAddress((void**)&base, g_buf);
    float* pob = nullptr;    cudaGetSymbolAddress((void**)&pob, g_po);
    float* pmsb = nullptr;   cudaGetSymbolAddress((void**)&pmsb, g_pms);
    float* partb = nullptr;  cudaGetSymbolAddress((void**)&partb, g_part);
    __nv_bfloat16* bfb = nullptr; cudaGetSymbolAddress((void**)&bfb, g_bf);
    __nv_bfloat16* wtb = nullptr; cudaGetSymbolAddress((void**)&wtb, g_wtb);

    float* B[15];
    for (int i = 0; i < 15; i++) B[i] = base + (size_t)i * CELLS;
    __nv_bfloat16* BF[6];
    for (int i = 0; i < 6; i++) BF[i] = bfb + (size_t)i * PADCELLS;
    __nv_bfloat16* WT[8];
    for (int i = 0; i < 8; i++) WT[i] = wtb + (size_t)i * 8192;
    float* partA = partb;
    float* partB = partb + 256 * 128;

    cudaFuncSetAttribute(k_flash_bf, cudaFuncAttributeMaxDynamicSharedMemorySize, FLASH_SMEM_BF);
    cudaFuncSetAttribute(k_gconv, cudaFuncAttributeMaxDynamicSharedMemorySize, GC_SMEM);

    dim3 thr(256);
    int gbd = (nd + 63) / 64;
    int gbe = (ne + 63) / 64;
    int gx = gbd > gbe ? gbd : gbe;

    // ---- init: weight conversion + segment prep (one launch) ----
    k_init<<<9, thr>>>(Wp1, Wq, Wk, Wv, Wt, Wq1, Wk1, Wv1, pad_idx, nd, ne, lq);

    // ---- Stage 1: xd0, q, ke, ve in one tensor-GEMM batch ----
    {
        TJobs JJ = {};
        JJ.j[0].A = xdec; JJ.j[0].Wbf = WT[0]; JJ.j[0].C = B[0]; JJ.j[0].N = nd; JJ.j[0].mode = 0;
        JJ.j[1].A = xdec; JJ.j[1].Wbf = WT[1]; JJ.j[1].hi = BF[0]; JJ.j[1].lo = BF[1]; JJ.j[1].N = nd; JJ.j[1].mode = 0;
        JJ.j[2].A = xenc; JJ.j[2].Wbf = WT[2]; JJ.j[2].hi = BF[2]; JJ.j[2].lo = BF[3]; JJ.j[2].N = ne; JJ.j[2].mode = 0;
        JJ.j[3].A = xenc; JJ.j[3].Wbf = WT[3]; JJ.j[3].hi = BF[4]; JJ.j[3].lo = BF[5]; JJ.j[3].N = ne; JJ.j[3].mode = 0;
        k_tgemm<<<dim3(gx, 4), thr>>>(JJ);
    }
    k_flash_bf<<<gbd * KS, thr, FLASH_SMEM_BF>>>(BF[0], BF[1], BF[2], BF[3], BF[4], BF[5],
                                                 B[4], 0, gbd * KS, KS, pob, pmsb);
    {   // xr = merge(splitK) @ Wt (+stats A)
        TJobs JJ = {};
        JJ.j[0].pO = pob; JJ.j[0].pMS = pmsb; JJ.j[0].Wbf = WT[4];
        JJ.j[0].C = B[5]; JJ.j[0].part = partA; JJ.j[0].N = nd; JJ.j[0].mode = 3;
        k_tgemm<<<dim3(gbd, 1), thr>>>(JJ);
    }
    {   // xd = bn(xr)+xd0 -> B6 ; q1 = xd@Wq1 -> B7 + BF0/1
        TJobs JJ = {};
        JJ.j[0].A = B[5]; JJ.j[0].Res = B[0]; JJ.j[0].bg = gam + 0; JJ.j[0].bb = bet + 0;
        JJ.j[0].sp = partA; JJ.j[0].snb = gbd; JJ.j[0].Aout = B[6];
        JJ.j[0].Wbf = WT[5]; JJ.j[0].C = B[7]; JJ.j[0].hi = BF[0]; JJ.j[0].lo = BF[1];
        JJ.j[0].N = nd; JJ.j[0].mode = 2;
        k_tgemm<<<dim3(gbd, 1), thr>>>(JJ);
    }

    // ---- Stage 2 ----
    k_gconv<<<gbd, thr, GC_SMEM>>>(B[7], kv_nbr, 8, Wdown, B[8], nd,
                                   partA, nullptr, 0, nullptr, nullptr);   // kv-pre (+stats A)
    {   // k1, v1 = bn(kv) @ {Wk1, Wv1}
        TJobs JJ = {};
        JJ.j[0].A = B[8]; JJ.j[0].Wbf = WT[6]; JJ.j[0].hi = BF[2]; JJ.j[0].lo = BF[3];
        JJ.j[0].bg = gam + 64; JJ.j[0].bb = bet + 64; JJ.j[0].sp = partA; JJ.j[0].snb = gbd;
        JJ.j[0].N = nd; JJ.j[0].mode = 1;
        JJ.j[1] = JJ.j[0];
        JJ.j[1].Wbf = WT[7]; JJ.j[1].hi = BF[4]; JJ.j[1].lo = BF[5];
        k_tgemm<<<dim3(gbd, 2), thr>>>(JJ);
    }
    int tps = (lq + 63) / 64;
    k_flash_bf<<<NBATCH * tps, thr, FLASH_SMEM_BF>>>(BF[0], BF[1], BF[2], BF[3], BF[4], BF[5],
                                                     B[12], 1, tps, 1, nullptr, nullptr);
    k_gconv<<<gbd, thr, GC_SMEM>>>(B[12], nbr, 27, W3t, B[13], nd,
                                   partA, nullptr, 0, nullptr, nullptr);   // xr2 (+stats A)
    k_bnapply_stats<<<gbd, thr>>>(B[13], B[6], gam + 128, bet + 128, partA, gbd,
                                  B[14], nd, partB);                       // xd2 (+stats B)

    // ---- Res block ----
    k_gconv<<<gbd, thr, GC_SMEM>>>(B[14], nbr, 27, W3a, B[1], nd,
                                   partA, partB, gbd, gam + 192, bet + 192);   // z1 (+stats A)
    k_gconv<<<gbd, thr, GC_SMEM>>>(B[1], nbr, 27, W3b, B[3], nd,
                                   nullptr, partA, gbd, gam + 256, bet + 256); // z2
    k_bnstats_add<<<64, thr>>>(B[14], B[3], B[4], nd, partA);
    k_bnapply_fin<<<gbd, thr>>>(B[4], gam + 320, bet + 320, partA, 64, out, nd);
}